// round 11
// baseline (speedup 1.0000x reference)
#include <cuda_runtime.h>
#include <cuda_fp16.h>
#include <math.h>
#include <stdint.h>

#define BB 8
#define LMAX 1024
#define DIM 512
#define HEADS 8
#define DH 64
#define NDEPTH 6
#define MLPD 2048
#define NC 1000
#define PDIM 768
#define NTOK (BB*LMAX)   // 8192

__constant__ int c_L[8]  = {1024, 768, 896, 576, 560, 512, 384, 640};
__constant__ int c_Wp[8] = {  32,  24,  32,  24,  28,  32,  16,  20};

// weight buffer offsets (elements)
#define OFF_QKV 0L
#define OFF_WO  4718592L
#define OFF_FF1 6291456L
#define OFF_FF2 12582912L
#define OFF_PE  18874368L
#define OFF_PK  19267584L
#define OFF_PV  19529728L
#define WTOT    19791872L

// ---------------- scratch ----------------
__device__ __align__(128) float g_tok[(size_t)NTOK*PDIM];
__device__ __align__(128) float g_t  [(size_t)NTOK*DIM];
__device__ __align__(128) float g_qkv[(size_t)3*NTOK*DIM];
__device__ __align__(128) float g_u  [DIM];
__device__ __align__(128) float g_qp [DIM];
__device__ __align__(128) float g_po [BB*DIM];
__device__ __align__(128) float g_pooled[BB*DIM];
__device__ __align__(128) float g_hn [BB*DIM];
__device__ __align__(128) __half g_wh[WTOT];
__device__ __align__(128) __half g_lt [(size_t)NTOK*PDIM];
__device__ __align__(128) __half g_xn [(size_t)NTOK*DIM];
__device__ __align__(128) __half g_mlp[(size_t)NTOK*MLPD];
__device__ __align__(128) __half g_o  [(size_t)NTOK*DIM];
__device__ __align__(128) __half g_qkv16[(size_t)3*NTOK*DIM];
__device__ __align__(128) __half g_qh2[(size_t)NTOK*DIM];
__device__ __align__(128) __half g_kh2[(size_t)NTOK*DIM];
__device__ __align__(128) __half g_vh2[(size_t)NTOK*DIM];

// ================= helpers =================
__device__ __forceinline__ uint32_t smem_u32(const void* p){
    uint32_t a; asm("{ .reg .u64 t; cvta.to.shared.u64 t, %1; cvt.u32.u64 %0, t; }" : "=r"(a) : "l"(p));
    return a;
}
__device__ __forceinline__ void ldsm_x4(uint32_t* r, uint32_t addr){
    asm volatile("ldmatrix.sync.aligned.m8n8.x4.shared.b16 {%0,%1,%2,%3}, [%4];"
        : "=r"(r[0]),"=r"(r[1]),"=r"(r[2]),"=r"(r[3]) : "r"(addr));
}
__device__ __forceinline__ void ldsm_x2(uint32_t* r, uint32_t addr){
    asm volatile("ldmatrix.sync.aligned.m8n8.x2.shared.b16 {%0,%1}, [%2];"
        : "=r"(r[0]),"=r"(r[1]) : "r"(addr));
}
__device__ __forceinline__ void ldsm_x2t(uint32_t* r, uint32_t addr){
    asm volatile("ldmatrix.sync.aligned.m8n8.x2.trans.shared.b16 {%0,%1}, [%2];"
        : "=r"(r[0]),"=r"(r[1]) : "r"(addr));
}
__device__ __forceinline__ void mma16816(float* c, const uint32_t* a, const uint32_t* b){
    asm volatile("mma.sync.aligned.m16n8k16.row.col.f32.f16.f16.f32 "
        "{%0,%1,%2,%3}, {%4,%5,%6,%7}, {%8,%9}, {%0,%1,%2,%3};"
        : "+f"(c[0]),"+f"(c[1]),"+f"(c[2]),"+f"(c[3])
        : "r"(a[0]),"r"(a[1]),"r"(a[2]),"r"(a[3]), "r"(b[0]),"r"(b[1]));
}
__device__ __forceinline__ void cp_async16(uint32_t dst, const void* src){
    asm volatile("cp.async.cg.shared.global [%0], [%1], 16;" :: "r"(dst), "l"(src) : "memory");
}
__device__ __forceinline__ void cp_commit(){ asm volatile("cp.async.commit_group;" ::: "memory"); }
template<int N> __device__ __forceinline__ void cp_wait(){
    asm volatile("cp.async.wait_group %0;" :: "n"(N) : "memory");
}
__device__ __forceinline__ uint32_t h2u(__half2 v){ return *reinterpret_cast<uint32_t*>(&v); }
__device__ __forceinline__ uint32_t packh(float a, float b){
    return h2u(__float22half2_rn(make_float2(a, b)));
}
__device__ __forceinline__ uint4 cvt8s(float4 a, float4 b){
    return make_uint4(packh(a.x, a.y), packh(a.z, a.w), packh(b.x, b.y), packh(b.z, b.w));
}

// ---------------- weight f32 -> fp16 convert (vectorized, n % 4 == 0) ----------------
__global__ void wcvt_kernel(const float* __restrict__ src, __half* __restrict__ h, int n4){
    int i = blockIdx.x*blockDim.x + threadIdx.x;
    if (i >= n4) return;
    float4 v = ((const float4*)src)[i];
    ((uint2*)h)[i] = make_uint2(packh(v.x, v.y), packh(v.z, v.w));
}

// ============== cp.async HMMA GEMM NT (128M x 256N tile, warp tile 64x64) ==============
#define PITCHB 144
#define A_TB (128*PITCHB)        // 18432
#define W_TB (256*PITCHB)        // 36864
#define B_BUF (A_TB + W_TB)      // 55296
#define B_SMEM (2*B_BUF)         // 110592

__global__ __launch_bounds__(256, 1) void bgemm_nt(
    const __half* __restrict__ A, int lda,
    const __half* __restrict__ W, int ldw, long wz,
    const float* __restrict__ bias,
    const float* __restrict__ R, int ldr,
    float* __restrict__ C, __half* __restrict__ Ch,
    int ldc, long cz,
    int K, int act, int tokrows)
{
    extern __shared__ char smem[];
    uint32_t sb = smem_u32(smem);
    int tid = threadIdx.x, lane = tid & 31, wid = tid >> 5;
    int z = blockIdx.z;
    W += (size_t)z*wz;
    if (C)  C  += (size_t)z*cz;
    if (Ch) Ch += (size_t)z*cz;
    int bm = blockIdx.y*128, bn = blockIdx.x*256;
    if (tokrows && (bm & 1023) >= c_L[bm >> 10]) return;
    int wr = (wid & 1)*64;        // warp M base
    int wn = (wid >> 1)*64;       // warp N base

    float acc[4][8][4];
    #pragma unroll
    for (int i = 0; i < 4; i++)
        #pragma unroll
        for (int j = 0; j < 8; j++)
            #pragma unroll
            for (int p = 0; p < 4; p++) acc[i][j][p] = 0.f;

#define BSTAGE(KC, BUFB) do { \
    int arow = tid >> 3, aseg = tid & 7; \
    _Pragma("unroll") \
    for (int it = 0; it < 4; it++){ \
        int row = it*32 + arow; \
        cp_async16(sb + (uint32_t)(BUFB) + (uint32_t)(row*PITCHB + aseg*16), \
                   A + (size_t)(bm + row)*lda + (KC)*64 + aseg*8); \
    } \
    _Pragma("unroll") \
    for (int it = 0; it < 8; it++){ \
        int row = it*32 + arow; \
        cp_async16(sb + (uint32_t)(BUFB) + A_TB + (uint32_t)(row*PITCHB + aseg*16), \
                   W + (size_t)(bn + row)*ldw + (KC)*64 + aseg*8); \
    } } while(0)

    int nk = K >> 6;
    BSTAGE(0, 0);
    cp_commit();

    int grp = lane >> 3, wi = lane & 7;
    int brow_lo = (lane & 7) + ((lane >> 4) & 1)*8;   // row-within-16 for W ldsm_x4
    int bkoff = ((lane >> 3) & 1)*8;                  // k-offset for W ldsm_x4
    for (int kc = 0; kc < nk; kc++){
        if (kc + 1 < nk){
            BSTAGE(kc + 1, ((kc + 1) & 1)*B_BUF);
            cp_commit();
            cp_wait<1>();
        } else {
            cp_wait<0>();
        }
        __syncthreads();
        uint32_t cur = (uint32_t)((kc & 1)*B_BUF);
        #pragma unroll
        for (int ks = 0; ks < 4; ks++){
            uint32_t a_f[4][4];
            #pragma unroll
            for (int mi = 0; mi < 4; mi++){
                uint32_t off = (uint32_t)((wr + mi*16 + wi + (grp & 1)*8)*PITCHB
                                          + (ks*16 + (grp >> 1)*8)*2);
                ldsm_x4(a_f[mi], sb + cur + off);
            }
            uint32_t b_f[4][4];
            #pragma unroll
            for (int ni = 0; ni < 4; ni++){
                uint32_t off = (uint32_t)((wn + ni*16 + brow_lo)*PITCHB
                                          + (ks*16 + bkoff)*2);
                ldsm_x4(b_f[ni], sb + cur + A_TB + off);
            }
            #pragma unroll
            for (int mi = 0; mi < 4; mi++)
                #pragma unroll
                for (int ni = 0; ni < 4; ni++){
                    mma16816(acc[mi][2*ni    ], a_f[mi], &b_f[ni][0]);
                    mma16816(acc[mi][2*ni + 1], a_f[mi], &b_f[ni][2]);
                }
        }
        __syncthreads();
    }
#undef BSTAGE

    // ---- epilogue ----
    #pragma unroll
    for (int mi = 0; mi < 4; mi++){
        #pragma unroll
        for (int nj = 0; nj < 8; nj++){
            int gn = bn + wn + nj*8 + (lane & 3)*2;
            #pragma unroll
            for (int hh = 0; hh < 2; hh++){
                int m = bm + wr + mi*16 + (lane >> 2) + hh*8;
                float v0 = acc[mi][nj][hh*2 + 0];
                float v1 = acc[mi][nj][hh*2 + 1];
                if (bias){ v0 += bias[gn]; v1 += bias[gn + 1]; }
                if (act){
                    v0 = 0.5f*v0*(1.f + erff(v0*0.70710678118654752f));
                    v1 = 0.5f*v1*(1.f + erff(v1*0.70710678118654752f));
                }
                if (Ch){
                    *(uint32_t*)(Ch + (size_t)m*ldc + gn) = packh(v0, v1);
                } else {
                    if (R){
                        const float* rp = R + (size_t)m*ldr + gn;
                        v0 += rp[0]; v1 += rp[1];
                    }
                    *(float2*)(C + (size_t)m*ldc + gn) = make_float2(v0, v1);
                }
            }
        }
    }
}

// ============== kvprep: reads fp16 qkv; head-LN(Q x 1/8, K); writes fp16 ==============
__global__ void kvprep_kernel(const __half* __restrict__ qkv,
    const float* __restrict__ qn, const float* __restrict__ kn,
    __half* __restrict__ qh, __half* __restrict__ kh, __half* __restrict__ vh)
{
    int g = blockIdx.x*blockDim.x + threadIdx.x;   // NTOK*HEADS*8
    int seg = g & 7;
    int r = g >> 3;
    int tokn = r >> 3, h = r & 7;
    int b = tokn >> 10, l = tokn & 1023;
    if (l >= c_L[b]) return;
    size_t base = (size_t)tokn*DIM + h*64 + seg*8;

#define LD8H(P, X, Y) do { \
    uint4 raw = *(const uint4*)(P); \
    float2 f0 = __half22float2(*reinterpret_cast<__half2*>(&raw.x)); \
    float2 f1 = __half22float2(*reinterpret_cast<__half2*>(&raw.y)); \
    float2 f2 = __half22float2(*reinterpret_cast<__half2*>(&raw.z)); \
    float2 f3 = __half22float2(*reinterpret_cast<__half2*>(&raw.w)); \
    X = make_float4(f0.x, f0.y, f1.x, f1.y); \
    Y = make_float4(f2.x, f2.y, f3.x, f3.y); \
} while(0)

#define LN8(x, y, wvec, scale) do { \
    float sum = x.x + x.y + x.z + x.w + y.x + y.y + y.z + y.w; \
    sum += __shfl_xor_sync(0xffffffffu, sum, 1); \
    sum += __shfl_xor_sync(0xffffffffu, sum, 2); \
    sum += __shfl_xor_sync(0xffffffffu, sum, 4); \
    float mu = sum * (1.f/64.f); \
    x.x -= mu; x.y -= mu; x.z -= mu; x.w -= mu; \
    y.x -= mu; y.y -= mu; y.z -= mu; y.w -= mu; \
    float ss = x.x*x.x + x.y*x.y + x.z*x.z + x.w*x.w \
             + y.x*y.x + y.y*y.y + y.z*y.z + y.w*y.w; \
    ss += __shfl_xor_sync(0xffffffffu, ss, 1); \
    ss += __shfl_xor_sync(0xffffffffu, ss, 2); \
    ss += __shfl_xor_sync(0xffffffffu, ss, 4); \
    float rs = rsqrtf(ss * (1.f/64.f) + 1e-5f) * (scale); \
    float4 w0 = *(const float4*)((wvec) + seg*8); \
    float4 w1 = *(const float4*)((wvec) + seg*8 + 4); \
    x.x *= rs*w0.x; x.y *= rs*w0.y; x.z *= rs*w0.z; x.w *= rs*w0.w; \
    y.x *= rs*w1.x; y.y *= rs*w1.y; y.z *= rs*w1.z; y.w *= rs*w1.w; \
} while(0)

    {   // Q
        float4 x, y; LD8H(qkv + base, x, y);
        LN8(x, y, qn, 0.125f);
        *(uint4*)(qh + base) = cvt8s(x, y);
    }
    {   // K
        float4 x, y; LD8H(qkv + (size_t)NTOK*DIM + base, x, y);
        LN8(x, y, kn, 1.f);
        *(uint4*)(kh + base) = cvt8s(x, y);
    }
    {   // V (straight copy, already fp16)
        *(uint4*)(vh + base) = *(const uint4*)(qkv + (size_t)2*NTOK*DIM + base);
    }
#undef LN8
#undef LD8H
}

// ============== flash attention: pure fp16, cp.async double-buffered K/V ==============
#define FQ 0
#define FKV0 18432
#define FKVS 36864
#define FSMEM (18432 + 2*36864)          // 92160

__global__ __launch_bounds__(256, 2) void flash_kernel(
    const __half* __restrict__ Qh,
    const __half* __restrict__ Kh,
    const __half* __restrict__ Vh,
    __half* __restrict__ O)
{
    extern __shared__ char smem[];
    uint32_t sb = smem_u32(smem);
    int tid = threadIdx.x, lane = tid & 31, wid = tid >> 5;
    int qt = blockIdx.x;
    int bh = blockIdx.y;
    int b = bh >> 3, h = bh & 7;
    int L = c_L[b];
    if (qt*128 >= L) return;
    int ktiles = (L + 127) >> 7;

    // ---- stage Q ----
    #pragma unroll
    for (int it = 0; it < 4; it++){
        int slot = it*256 + tid; int row = slot >> 3, seg = slot & 7;
        size_t go = (size_t)(b*1024 + qt*128 + row)*DIM + h*64 + seg*8;
        cp_async16(sb + FQ + (uint32_t)(row*144 + seg*16), Qh + go);
    }
    cp_commit();

#define KVSTAGE(KT, SBASE) do { \
    _Pragma("unroll") \
    for (int it = 0; it < 4; it++){ \
        int slot = it*256 + tid; int row = slot >> 3, seg = slot & 7; \
        size_t go = (size_t)(b*1024 + (KT)*128 + row)*DIM + h*64 + seg*8; \
        uint32_t so = (uint32_t)(SBASE) + (uint32_t)(row*144 + seg*16); \
        cp_async16(sb + so,         Kh + go); \
        cp_async16(sb + so + 18432, Vh + go); \
    } } while(0)

    KVSTAGE(0, FKV0);
    cp_commit();

    cp_wait<1>();
    __syncthreads();

    int wr = wid*16;
    int grp = lane >> 3, wi = lane & 7;
    uint32_t aq[4][4];
    #pragma unroll
    for (int ks = 0; ks < 4; ks++){
        uint32_t off = (uint32_t)((wr + wi + (grp & 1)*8)*144 + (ks*16 + (grp >> 1)*8)*2);
        ldsm_x4(aq[ks], sb + FQ + off);
    }

    float m0 = -1e30f, m1 = -1e30f, l0 = 0.f, l1 = 0.f;
    float ao[8][4];
    #pragma unroll
    for (int i = 0; i < 8; i++)
        #pragma unroll
        for (int p = 0; p < 4; p++) ao[i][p] = 0.f;

    for (int kt = 0; kt < ktiles; kt++){
        if (kt + 1 < ktiles){
            KVSTAGE(kt + 1, FKV0 + ((kt + 1) & 1)*FKVS);
            cp_commit();
            cp_wait<1>();
        } else {
            cp_wait<0>();
        }
        __syncthreads();
        uint32_t kb = (uint32_t)(FKV0 + (kt & 1)*FKVS);

        // ---- S = Q K^T ----
        float s[16][4];
        #pragma unroll
        for (int i = 0; i < 16; i++)
            #pragma unroll
            for (int p = 0; p < 4; p++) s[i][p] = 0.f;
        #pragma unroll
        for (int ks = 0; ks < 4; ks++){
            #pragma unroll
            for (int ni = 0; ni < 16; ni++){
                uint32_t off = (uint32_t)((ni*8 + wi)*144 + (ks*16 + (grp & 1)*8)*2);
                uint32_t b_[2];
                ldsm_x2(b_, sb + kb + off);
                mma16816(s[ni], aq[ks], b_);
            }
        }

        // ---- mask (partial tile only) ----
        if (kt == ktiles - 1 && (L & 127)){
            int kbase = kt*128 + 2*(lane & 3);
            #pragma unroll
            for (int ni = 0; ni < 16; ni++){
                int kg = kbase + ni*8;
                if (kg     >= L){ s[ni][0] = -1e9f; s[ni][2] = -1e9f; }
                if (kg + 1 >= L){ s[ni][1] = -1e9f; s[ni][3] = -1e9f; }
            }
        }

        // ---- online softmax ----
        float tm0 = -1e30f, tm1 = -1e30f;
        #pragma unroll
        for (int ni = 0; ni < 16; ni++){
            tm0 = fmaxf(tm0, fmaxf(s[ni][0], s[ni][1]));
            tm1 = fmaxf(tm1, fmaxf(s[ni][2], s[ni][3]));
        }
        tm0 = fmaxf(tm0, __shfl_xor_sync(0xffffffffu, tm0, 1));
        tm0 = fmaxf(tm0, __shfl_xor_sync(0xffffffffu, tm0, 2));
        tm1 = fmaxf(tm1, __shfl_xor_sync(0xffffffffu, tm1, 1));
        tm1 = fmaxf(tm1, __shfl_xor_sync(0xffffffffu, tm1, 2));
        float mn0 = fmaxf(m0, tm0), mn1 = fmaxf(m1, tm1);
        float sc0 = __expf(m0 - mn0), sc1 = __expf(m1 - mn1);
        m0 = mn0; m1 = mn1;
        float ts0 = 0.f, ts1 = 0.f;
        #pragma unroll
        for (int ni = 0; ni < 16; ni++){
            s[ni][0] = __expf(s[ni][0] - m0);
            s[ni][1] = __expf(s[ni][1] - m0);
            s[ni][2] = __expf(s[ni][2] - m1);
            s[ni][3] = __expf(s[ni][3] - m1);
            ts0 += s[ni][0] + s[ni][1];
            ts1 += s[ni][2] + s[ni][3];
        }
        ts0 += __shfl_xor_sync(0xffffffffu, ts0, 1);
        ts0 += __shfl_xor_sync(0xffffffffu, ts0, 2);
        ts1 += __shfl_xor_sync(0xffffffffu, ts1, 1);
        ts1 += __shfl_xor_sync(0xffffffffu, ts1, 2);
        l0 = l0*sc0 + ts0;
        l1 = l1*sc1 + ts1;
        #pragma unroll
        for (int i = 0; i < 8; i++){
            ao[i][0] *= sc0; ao[i][1] *= sc0;
            ao[i][2] *= sc1; ao[i][3] *= sc1;
        }

        // ---- O += P V ----
        #pragma unroll
        for (int kk = 0; kk < 8; kk++){
            uint32_t ap[4];
            ap[0] = packh(s[2*kk][0],   s[2*kk][1]);
            ap[1] = packh(s[2*kk][2],   s[2*kk][3]);
            ap[2] = packh(s[2*kk+1][0], s[2*kk+1][1]);
            ap[3] = packh(s[2*kk+1][2], s[2*kk+1][3]);
            #pragma unroll
            for (int ni = 0; ni < 8; ni++){
                uint32_t off = (uint32_t)((kk*16 + (lane & 15))*144 + ni*16);
                uint32_t v_[2];
                ldsm_x2t(v_, sb + kb + 18432 + off);
                mma16816(ao[ni], ap, v_);
            }
        }
        __syncthreads();
    }
#undef KVSTAGE

    // ---- epilogue: fp16 O ----
    float il0 = 1.f / l0, il1 = 1.f / l1;
    int mrow = qt*128 + wr + (lane >> 2);
    #pragma unroll
    for (int ni = 0; ni < 8; ni++){
        int col = h*64 + ni*8 + 2*(lane & 3);
        *(uint32_t*)(O + (size_t)(b*1024 + mrow)*DIM + col)     = packh(ao[ni][0]*il0, ao[ni][1]*il0);
        *(uint32_t*)(O + (size_t)(b*1024 + mrow + 8)*DIM + col) = packh(ao[ni][2]*il1, ao[ni][3]*il1);
    }
}

// ---------------- patch packing ----------------
__global__ void pack_kernel(const float* __restrict__ img, float* __restrict__ tok){
    size_t i = (size_t)blockIdx.x*blockDim.x + threadIdx.x;
    if (i >= (size_t)NTOK*PDIM) return;
    int pd = (int)(i % PDIM);
    size_t bl = i / PDIM;
    int l = (int)(bl % LMAX);
    int b = (int)(bl / LMAX);
    int L = c_L[b], w = c_Wp[b];
    float v = 0.f;
    if (l < L){
        int c  = pd >> 8;
        int r  = pd & 255;
        int py = r >> 4, px = r & 15;
        int ph = l / w, pw = l % w;
        v = img[((size_t)(b*3 + c)*512 + (size_t)(ph*16 + py))*512 + (size_t)(pw*16 + px)];
    }
    tok[i] = v;
}

// ---------------- row LayerNorm, vectorized; writes f32 (y) or fp16 (yh) ----------------
__global__ void ln_kernel(const float* __restrict__ x, const float* __restrict__ w,
                          const float* __restrict__ bb, float* __restrict__ y,
                          __half* __restrict__ yh, int D, int tokskip){
    __shared__ float red[8];
    int row = blockIdx.x, tid = threadIdx.x, lane = tid & 31, wp = tid >> 5;
    int nw = blockDim.x >> 5;
    if (tokskip && (row & 1023) >= c_L[row >> 10]) return;
    int idx = tid*4;
    float4 v = make_float4(0,0,0,0);
    if (idx < D) v = *(const float4*)(x + (size_t)row*D + idx);
    float s = v.x + v.y + v.z + v.w;
    #pragma unroll
    for (int off = 16; off; off >>= 1) s += __shfl_xor_sync(0xffffffffu, s, off);
    if (lane == 0) red[wp] = s;
    __syncthreads();
    float tot = 0.f;
    for (int i = 0; i < nw; i++) tot += red[i];
    float mu = tot / (float)D;
    __syncthreads();
    float vs = 0.f;
    if (idx < D){
        float a = v.x - mu, b2 = v.y - mu, c = v.z - mu, d = v.w - mu;
        vs = a*a + b2*b2 + c*c + d*d;
    }
    #pragma unroll
    for (int off = 16; off; off >>= 1) vs += __shfl_xor_sync(0xffffffffu, vs, off);
    if (lane == 0) red[wp] = vs;
    __syncthreads();
    float tv = 0.f;
    for (int i = 0; i < nw; i++) tv += red[i];
    float rs = rsqrtf(tv / (float)D + 1e-5f);
    if (idx < D){
        float4 w4 = *(const float4*)(w + idx);
        float4 o;
        o.x = (v.x - mu)*rs*w4.x;
        o.y = (v.y - mu)*rs*w4.y;
        o.z = (v.z - mu)*rs*w4.z;
        o.w = (v.w - mu)*rs*w4.w;
        if (bb){
            float4 b4 = *(const float4*)(bb + idx);
            o.x += b4.x; o.y += b4.y; o.z += b4.z; o.w += b4.w;
        }
        if (y) *(float4*)(y + (size_t)row*D + idx) = o;
        else   *(uint2*)(yh + (size_t)row*D + idx) = make_uint2(packh(o.x, o.y), packh(o.z, o.w));
    }
}

// ---------------- fused LN + pos-embed + mask (D=512, in-place on t) ----------------
__global__ void ln_pos_kernel(float* __restrict__ t, const float* __restrict__ w,
                              const float* __restrict__ bb,
                              const float* __restrict__ ph, const float* __restrict__ pw){
    __shared__ float red[8];
    int row = blockIdx.x, tid = threadIdx.x, lane = tid & 31, wpi = tid >> 5;
    int nw = blockDim.x >> 5;
    int b = row >> 10, l = row & 1023;
    int L = c_L[b], wgrid = c_Wp[b];
    int idx = tid*4;
    if (l >= L){
        if (idx < DIM) *(float4*)(t + (size_t)row*DIM + idx) = make_float4(0,0,0,0);
        return;
    }
    float4 v = make_float4(0,0,0,0);
    if (idx < DIM) v = *(const float4*)(t + (size_t)row*DIM + idx);
    float s = v.x + v.y + v.z + v.w;
    #pragma unroll
    for (int off = 16; off; off >>= 1) s += __shfl_xor_sync(0xffffffffu, s, off);
    if (lane == 0) red[wpi] = s;
    __syncthreads();
    float tot = 0.f;
    for (int i = 0; i < nw; i++) tot += red[i];
    float mu = tot / (float)DIM;
    __syncthreads();
    float vs = 0.f;
    if (idx < DIM){
        float a = v.x - mu, b2 = v.y - mu, c = v.z - mu, d = v.w - mu;
        vs = a*a + b2*b2 + c*c + d*d;
    }
    #pragma unroll
    for (int off = 16; off; off >>= 1) vs += __shfl_xor_sync(0xffffffffu, vs, off);
    if (lane == 0) red[wpi] = vs;
    __syncthreads();
    float tv = 0.f;
    for (int i = 0; i < nw; i++) tv += red[i];
    float rs = rsqrtf(tv / (float)DIM + 1e-5f);
    if (idx < DIM){
        float4 w4 = *(const float4*)(w + idx);
        float4 b4 = *(const float4*)(bb + idx);
        float4 p0 = *(const float4*)(ph + (size_t)(l / wgrid)*DIM + idx);
        float4 p1 = *(const float4*)(pw + (size_t)(l % wgrid)*DIM + idx);
        float4 o;
        o.x = (v.x - mu)*rs*w4.x + b4.x + p0.x + p1.x;
        o.y = (v.y - mu)*rs*w4.y + b4.y + p0.y + p1.y;
        o.z = (v.z - mu)*rs*w4.z + b4.z + p0.z + p1.z;
        o.w = (v.w - mu)*rs*w4.w + b4.w + p0.w + p1.w;
        *(float4*)(t + (size_t)row*DIM + idx) = o;
    }
}

// ---------------- per-head LayerNorm over 64 dims (pool path) ----------------
__global__ void head_ln_kernel(float* __restrict__ x, const float* __restrict__ w, int rows){
    int gw = (int)(((size_t)blockIdx.x*blockDim.x + threadIdx.x) >> 5);
    int lane = threadIdx.x & 31;
    if (gw >= rows) return;
    float* p = x + (size_t)gw*64;
    float a = p[lane], b = p[lane + 32];
    float s = a + b;
    #pragma unroll
    for (int off = 16; off; off >>= 1) s += __shfl_xor_sync(0xffffffffu, s, off);
    float mu = s * (1.f/64.f);
    float da = a - mu, db = b - mu;
    float vs = da*da + db*db;
    #pragma unroll
    for (int off = 16; off; off >>= 1) vs += __shfl_xor_sync(0xffffffffu, vs, off);
    float rs = rsqrtf(vs * (1.f/64.f) + 1e-5f);
    p[lane]      = da * rs * w[lane];
    p[lane + 32] = db * rs * w[lane + 32];
}

// ---------------- tiny GEMM NT: warp per output element (small M) ----------------
__global__ void tiny_nt_kernel(const float* __restrict__ A, int lda,
                               const float* __restrict__ W, int ldw,
                               const float* __restrict__ bias,
                               float* __restrict__ C, int ldc,
                               int M, int N, int K){
    int gw = (int)(((size_t)blockIdx.x*blockDim.x + threadIdx.x) >> 5);
    int lane = threadIdx.x & 31;
    if (gw >= M*N) return;
    int m = gw / N, n = gw % N;
    const float* a = A + (size_t)m*lda;
    const float* wv = W + (size_t)n*ldw;
    float s = 0.f;
    for (int k = lane*4; k < K; k += 128){
        float4 av = *(const float4*)(a + k);
        float4 bv = *(const float4*)(wv + k);
        s += av.x*bv.x + av.y*bv.y + av.z*bv.z + av.w*bv.w;
    }
    #pragma unroll
    for (int off = 16; off; off >>= 1) s += __shfl_xor_sync(0xffffffffu, s, off);
    if (lane == 0){
        if (bias) s += bias[n];
        C[(size_t)m*ldc + n] = s;
    }
}

// ---------------- pooling attention (Lq=1) ----------------
__global__ void pool_attn_kernel(const float* __restrict__ qhat, const float* __restrict__ K,
                                 const float* __restrict__ V, float* __restrict__ O){
    int h = blockIdx.x, b = blockIdx.y;
    __shared__ float sq[64];
    __shared__ float sa[1024];
    __shared__ float red[8], red2[8];
    __shared__ float racc[4][64];
    int tid = threadIdx.x, lane = tid & 31, wp = tid >> 5;
    if (tid < 64) sq[tid] = qhat[h*64 + tid];
    __syncthreads();
    int L = c_L[b];
    for (int kk = tid; kk < 1024; kk += 256){
        float dot = -1e9f;
        if (kk < L){
            const float* kr = K + ((size_t)(b*1024 + kk))*DIM + h*64;
            float ss = 0.f;
            #pragma unroll
            for (int d = 0; d < 64; d++) ss += sq[d]*kr[d];
            dot = ss*0.125f;
        }
        sa[kk] = dot;
    }
    __syncthreads();
    float m = -1e30f;
    for (int kk = tid; kk < 1024; kk += 256) m = fmaxf(m, sa[kk]);
    #pragma unroll
    for (int off = 16; off; off >>= 1) m = fmaxf(m, __shfl_xor_sync(0xffffffffu, m, off));
    if (lane == 0) red[wp] = m;
    __syncthreads();
    float bm = -1e30f;
    #pragma unroll
    for (int i = 0; i < 8; i++) bm = fmaxf(bm, red[i]);
    float sum = 0.f;
    for (int kk = tid; kk < 1024; kk += 256){
        float e = __expf(sa[kk] - bm);
        sa[kk] = e; sum += e;
    }
    #pragma unroll
    for (int off = 16; off; off >>= 1) sum += __shfl_xor_sync(0xffffffffu, sum, off);
    if (lane == 0) red2[wp] = sum;
    __syncthreads();
    float bs = 0.f;
    #pragma unroll
    for (int i = 0; i < 8; i++) bs += red2[i];
    float inv = 1.f / bs;
    int dd = tid & 63, part = tid >> 6;
    float acc = 0.f;
    for (int kk = part; kk < 1024; kk += 4)
        acc += sa[kk] * V[((size_t)(b*1024 + kk))*DIM + h*64 + dd];
    racc[part][dd] = acc;
    __syncthreads();
    if (part == 0)
        O[b*DIM + h*64 + dd] = (racc[0][dd] + racc[1][dd] + racc[2][dd] + racc[3][dd]) * inv;
}

// ---------------- host helpers ----------------
static void launch_wcvt(const float* src, __half* h, long n){
    long n4 = n >> 2;
    wcvt_kernel<<<(int)((n4 + 255)/256), 256>>>(src, h, (int)n4);
}
static void launch_bg(const __half* A, int lda,
                      const __half* W, int ldw, long wz,
                      const float* bias, const float* R, int ldr,
                      float* C, __half* Ch, int ldc, long cz,
                      int N, int K, int act, int nz, int tokrows){
    dim3 g(N/256, NTOK/128, nz);
    bgemm_nt<<<g, 256, B_SMEM>>>(A, lda, W, ldw, wz, bias, R, ldr,
                                 C, Ch, ldc, cz, K, act, tokrows);
}
static void launch_tiny(const float* A, int lda, const float* W, int ldw,
                        const float* bias, float* C, int ldc, int M, int N, int K){
    int warps = M*N;
    tiny_nt_kernel<<<(warps*32 + 255)/256, 256>>>(A, lda, W, ldw, bias, C, ldc, M, N, K);
}

extern "C" void kernel_launch(void* const* d_in, const int* in_sizes, int n_in,
                              void* d_out, int out_size){
    const float* images   = (const float*)d_in[0];
    const float* pe_ln1_w = (const float*)d_in[1];
    const float* pe_ln1_b = (const float*)d_in[2];
    const float* pe_w     = (const float*)d_in[3];
    const float* pe_b     = (const float*)d_in[4];
    const float* pe_ln2_w = (const float*)d_in[5];
    const float* pe_ln2_b = (const float*)d_in[6];
    const float* pos_h    = (const float*)d_in[7];
    const float* pos_w    = (const float*)d_in[8];
    const float* attn_ln  = (const float*)d_in[9];
    const float* wq       = (const float*)d_in[10];
    const float* wk       = (const float*)d_in[11];
    const float* wv       = (const float*)d_in[12];
    const float* qn       = (const float*)d_in[13];
    const float* kn       = (const float*)d_in[14];
    const float* wo       = (const float*)d_in[15];
    const float* ff_ln    = (const float*)d_in[16];
    const float* ff_w1    = (const float*)d_in[17];
    const float* ff_b1    = (const float*)d_in[18];
    const float* ff_w2    = (const float*)d_in[19];
    const float* ff_b2    = (const float*)d_in[20];
    const float* final_ln = (const float*)d_in[21];
    const float* pool_q   = (const float*)d_in[22];
    const float* pool_ln  = (const float*)d_in[23];
    const float* pool_wq  = (const float*)d_in[24];
    const float* pool_wk  = (const float*)d_in[25];
    const float* pool_wv  = (const float*)d_in[26];
    const float* pool_qn  = (const float*)d_in[27];
    const float* pool_kn  = (const float*)d_in[28];
    const float* pool_wo  = (const float*)d_in[29];
    const float* head_ln  = (const float*)d_in[30];
    const float* head_w   = (const float*)d_in[31];
    float* out = (float*)d_out;

    cudaFuncSetAttribute(bgemm_nt, cudaFuncAttributeMaxDynamicSharedMemorySize, B_SMEM);
    cudaFuncSetAttribute(flash_kernel, cudaFuncAttributeMaxDynamicSharedMemorySize, FSMEM);

    float *tok,*t,*qkv,*u,*qp,*po,*pooled,*hn;
    __half *wh,*lt,*xn,*mlp,*o,*qkv16,*qh,*kh,*vh;
    cudaGetSymbolAddress((void**)&tok, g_tok);
    cudaGetSymbolAddress((void**)&t,   g_t);
    cudaGetSymbolAddress((void**)&qkv, g_qkv);
    cudaGetSymbolAddress((void**)&u,   g_u);
    cudaGetSymbolAddress((void**)&qp,  g_qp);
    cudaGetSymbolAddress((void**)&po,  g_po);
    cudaGetSymbolAddress((void**)&pooled, g_pooled);
    cudaGetSymbolAddress((void**)&hn,  g_hn);
    cudaGetSymbolAddress((void**)&wh,  g_wh);
    cudaGetSymbolAddress((void**)&lt,  g_lt);
    cudaGetSymbolAddress((void**)&xn,  g_xn);
    cudaGetSymbolAddress((void**)&mlp, g_mlp);
    cudaGetSymbolAddress((void**)&o,   g_o);
    cudaGetSymbolAddress((void**)&qkv16, g_qkv16);
    cudaGetSymbolAddress((void**)&qh,  g_qh2);
    cudaGetSymbolAddress((void**)&kh,  g_kh2);
    cudaGetSymbolAddress((void**)&vh,  g_vh2);

    float* kf = qkv + (size_t)NTOK*DIM;
    float* vf = qkv + (size_t)2*NTOK*DIM;

    // ---- weight convert (once per launch) ----
    launch_wcvt(wq, wh + OFF_QKV,            6L*DIM*DIM);
    launch_wcvt(wk, wh + OFF_QKV + 1572864L, 6L*DIM*DIM);
    launch_wcvt(wv, wh + OFF_QKV + 3145728L, 6L*DIM*DIM);
    launch_wcvt(wo, wh + OFF_WO,  6L*DIM*DIM);
    launch_wcvt(ff_w1, wh + OFF_FF1, 6L*MLPD*DIM);
    launch_wcvt(ff_w2, wh + OFF_FF2, 6L*DIM*MLPD);
    launch_wcvt(pe_w, wh + OFF_PE, (long)DIM*PDIM);
    launch_wcvt(pool_wk, wh + OFF_PK, (long)DIM*DIM);
    launch_wcvt(pool_wv, wh + OFF_PV, (long)DIM*DIM);

    // ---- patch embed ----
    pack_kernel<<<((size_t)NTOK*PDIM + 255)/256, 256>>>(images, tok);
    ln_kernel<<<NTOK, 256>>>(tok, pe_ln1_w, pe_ln1_b, nullptr, lt, PDIM, 1);
    launch_bg(lt, PDIM, wh + OFF_PE, PDIM, 0, pe_b,
              nullptr, 0, t, nullptr, DIM, 0, DIM, PDIM, 0, 1, 1);
    ln_pos_kernel<<<NTOK, 128>>>(t, pe_ln2_w, pe_ln2_b, pos_h, pos_w);

    // ---- transformer layers ----
    for (int l = 0; l < NDEPTH; l++){
        ln_kernel<<<NTOK, 128>>>(t, attn_ln + l*DIM, nullptr, nullptr, xn, DIM, 1);
        launch_bg(xn, DIM, wh + OFF_QKV + (size_t)l*DIM*DIM, DIM, 1572864L,
                  nullptr, nullptr, 0,
                  nullptr, qkv16, DIM, (long)NTOK*DIM, DIM, DIM, 0, 3, 1);
        kvprep_kernel<<<NTOK*HEADS*8/256, 256>>>(qkv16, qn + l*DH, kn + l*DH, qh, kh, vh);
        flash_kernel<<<dim3(8, BB*HEADS), 256, FSMEM>>>(qh, kh, vh, o);
        launch_bg(o, DIM, wh + OFF_WO + (size_t)l*DIM*DIM, DIM, 0,
                  nullptr, t, DIM, t, nullptr, DIM, 0, DIM, DIM, 0, 1, 1);
        ln_kernel<<<NTOK, 128>>>(t, ff_ln + l*DIM, nullptr, nullptr, xn, DIM, 1);
        launch_bg(xn, DIM, wh + OFF_FF1 + (size_t)l*MLPD*DIM, DIM, 0,
                  ff_b1 + l*MLPD, nullptr, 0,
                  nullptr, mlp, MLPD, 0, MLPD, DIM, 1, 1, 1);
        launch_bg(mlp, MLPD, wh + OFF_FF2 + (size_t)l*DIM*MLPD, MLPD, 0,
                  ff_b2 + l*DIM, t, DIM, t, nullptr, DIM, 0, DIM, MLPD, 0, 1, 1);
    }

    // ---- final LN + pooling ----
    ln_kernel<<<NTOK, 128>>>(t, final_ln, nullptr, nullptr, xn, DIM, 1);
    ln_kernel<<<1, 128>>>(pool_q, pool_ln, nullptr, u, nullptr, DIM, 0);
    launch_tiny(u, DIM, pool_wq, DIM, nullptr, qp, DIM, 1, DIM, DIM);
    head_ln_kernel<<<1, 256>>>(qp, pool_qn, HEADS);
    launch_bg(xn, DIM, wh + OFF_PK, DIM, 0, nullptr, nullptr, 0,
              kf, nullptr, DIM, 0, DIM, DIM, 0, 1, 1);
    head_ln_kernel<<<(NTOK*HEADS*32 + 255)/256, 256>>>(kf, pool_kn, NTOK*HEADS);
    launch_bg(xn, DIM, wh + OFF_PV, DIM, 0, nullptr, nullptr, 0,
              vf, nullptr, DIM, 0, DIM, DIM, 0, 1, 1);
    pool_attn_kernel<<<dim3(HEADS, BB), 256>>>(qp, kf, vf, po);
    launch_tiny(po, DIM, pool_wo, DIM, nullptr, pooled, DIM, BB, DIM, DIM);
    ln_kernel<<<BB, 128>>>(pooled, head_ln, nullptr, hn, nullptr, DIM, 0);
    launch_tiny(hn, DIM, head_w, DIM, nullptr, out, NC, BB, NC, DIM);
}

// round 12
// speedup vs baseline: 1.0769x; 1.0769x over previous
#include <cuda_runtime.h>
#include <cuda_fp16.h>
#include <math.h>
#include <stdint.h>

#define BB 8
#define LMAX 1024
#define DIM 512
#define HEADS 8
#define DH 64
#define NDEPTH 6
#define MLPD 2048
#define NC 1000
#define PDIM 768
#define NTOK (BB*LMAX)   // 8192

__constant__ int c_L[8]  = {1024, 768, 896, 576, 560, 512, 384, 640};
__constant__ int c_Wp[8] = {  32,  24,  32,  24,  28,  32,  16,  20};

// weight buffer offsets (elements)
#define OFF_QKV 0L
#define OFF_WO  4718592L
#define OFF_FF1 6291456L
#define OFF_FF2 12582912L
#define OFF_PE  18874368L
#define OFF_PK  19267584L
#define OFF_PV  19529728L
#define WTOT    19791872L

// ---------------- scratch ----------------
__device__ __align__(128) float g_tok[(size_t)NTOK*PDIM];
__device__ __align__(128) float g_t  [(size_t)NTOK*DIM];
__device__ __align__(128) float g_qkv[(size_t)3*NTOK*DIM];
__device__ __align__(128) float g_u  [DIM];
__device__ __align__(128) float g_qp [DIM];
__device__ __align__(128) float g_po [BB*DIM];
__device__ __align__(128) float g_pooled[BB*DIM];
__device__ __align__(128) float g_hn [BB*DIM];
__device__ __align__(128) __half g_wh[WTOT];
__device__ __align__(128) __half g_lt [(size_t)NTOK*PDIM];
__device__ __align__(128) __half g_xn [(size_t)NTOK*DIM];
__device__ __align__(128) __half g_mlp[(size_t)NTOK*MLPD];
__device__ __align__(128) __half g_o  [(size_t)NTOK*DIM];
__device__ __align__(128) __half g_qkv16[(size_t)3*NTOK*DIM];
__device__ __align__(128) __half g_qh2[(size_t)NTOK*DIM];
__device__ __align__(128) __half g_kh2[(size_t)NTOK*DIM];
__device__ __align__(128) __half g_vh2[(size_t)NTOK*DIM];

// ================= helpers =================
__device__ __forceinline__ uint32_t smem_u32(const void* p){
    uint32_t a; asm("{ .reg .u64 t; cvta.to.shared.u64 t, %1; cvt.u32.u64 %0, t; }" : "=r"(a) : "l"(p));
    return a;
}
__device__ __forceinline__ void ldsm_x4(uint32_t* r, uint32_t addr){
    asm volatile("ldmatrix.sync.aligned.m8n8.x4.shared.b16 {%0,%1,%2,%3}, [%4];"
        : "=r"(r[0]),"=r"(r[1]),"=r"(r[2]),"=r"(r[3]) : "r"(addr));
}
__device__ __forceinline__ void ldsm_x2(uint32_t* r, uint32_t addr){
    asm volatile("ldmatrix.sync.aligned.m8n8.x2.shared.b16 {%0,%1}, [%2];"
        : "=r"(r[0]),"=r"(r[1]) : "r"(addr));
}
__device__ __forceinline__ void ldsm_x2t(uint32_t* r, uint32_t addr){
    asm volatile("ldmatrix.sync.aligned.m8n8.x2.trans.shared.b16 {%0,%1}, [%2];"
        : "=r"(r[0]),"=r"(r[1]) : "r"(addr));
}
__device__ __forceinline__ void mma16816(float* c, const uint32_t* a, const uint32_t* b){
    asm volatile("mma.sync.aligned.m16n8k16.row.col.f32.f16.f16.f32 "
        "{%0,%1,%2,%3}, {%4,%5,%6,%7}, {%8,%9}, {%0,%1,%2,%3};"
        : "+f"(c[0]),"+f"(c[1]),"+f"(c[2]),"+f"(c[3])
        : "r"(a[0]),"r"(a[1]),"r"(a[2]),"r"(a[3]), "r"(b[0]),"r"(b[1]));
}
__device__ __forceinline__ void cp_async16(uint32_t dst, const void* src){
    asm volatile("cp.async.cg.shared.global [%0], [%1], 16;" :: "r"(dst), "l"(src) : "memory");
}
__device__ __forceinline__ void cp_commit(){ asm volatile("cp.async.commit_group;" ::: "memory"); }
template<int N> __device__ __forceinline__ void cp_wait(){
    asm volatile("cp.async.wait_group %0;" :: "n"(N) : "memory");
}
__device__ __forceinline__ uint32_t h2u(__half2 v){ return *reinterpret_cast<uint32_t*>(&v); }
__device__ __forceinline__ uint32_t packh(float a, float b){
    return h2u(__float22half2_rn(make_float2(a, b)));
}
__device__ __forceinline__ uint4 cvt8s(float4 a, float4 b){
    return make_uint4(packh(a.x, a.y), packh(a.z, a.w), packh(b.x, b.y), packh(b.z, b.w));
}

// ---------------- weight f32 -> fp16 convert (vectorized, n % 4 == 0) ----------------
__global__ void wcvt_kernel(const float* __restrict__ src, __half* __restrict__ h, int n4){
    int i = blockIdx.x*blockDim.x + threadIdx.x;
    if (i >= n4) return;
    float4 v = ((const float4*)src)[i];
    ((uint2*)h)[i] = make_uint2(packh(v.x, v.y), packh(v.z, v.w));
}

// ============== cp.async HMMA GEMM NT (128x128 tile, 3-stage pipeline) ==============
#define BTILE (128*144)          // 18432
#define B_A  0
#define B_W  BTILE
#define B_BUF (2*BTILE)          // 36864
#define B_SMEM (3*B_BUF)         // 110592

__global__ __launch_bounds__(256, 2) void bgemm_nt(
    const __half* __restrict__ A, int lda,
    const __half* __restrict__ W, int ldw, long wz,
    const float* __restrict__ bias,
    const float* __restrict__ R, int ldr,
    float* __restrict__ C, __half* __restrict__ Ch,
    int ldc, long cz,
    int K, int act, int tokrows)
{
    extern __shared__ char smem[];
    uint32_t sb = smem_u32(smem);
    int tid = threadIdx.x, lane = tid & 31, wid = tid >> 5;
    int z = blockIdx.z;
    W += (size_t)z*wz;
    if (C)  C  += (size_t)z*cz;
    if (Ch) Ch += (size_t)z*cz;
    int bm = blockIdx.y*128, bn = blockIdx.x*128;
    if (tokrows && (bm & 1023) >= c_L[bm >> 10]) return;
    int wr = (wid & 1)*64;
    int wn = (wid >> 1)*32;

    float acc[4][4][4];
    #pragma unroll
    for (int i = 0; i < 4; i++)
        #pragma unroll
        for (int j = 0; j < 4; j++)
            #pragma unroll
            for (int p = 0; p < 4; p++) acc[i][j][p] = 0.f;

#define BSTAGE(KC, BUFB) do { \
    _Pragma("unroll") \
    for (int it = 0; it < 4; it++){ \
        int slot = it*256 + tid; int row = slot >> 3, seg = slot & 7; \
        uint32_t so = (uint32_t)(BUFB) + (uint32_t)(row*144 + seg*16); \
        cp_async16(sb + B_A + so, A + (size_t)(bm + row)*lda + (KC)*64 + seg*8); \
        cp_async16(sb + B_W + so, W + (size_t)(bn + row)*ldw + (KC)*64 + seg*8); \
    } } while(0)

    int nk = K >> 6;
    BSTAGE(0, 0);
    cp_commit();
    if (nk > 1){ BSTAGE(1, B_BUF); cp_commit(); }

    int grp = lane >> 3, wi = lane & 7;
    int buf = 0;
    for (int kc = 0; kc < nk; kc++){
        if (kc + 2 < nk){
            int nb = buf + 2; if (nb >= 3) nb -= 3;
            BSTAGE(kc + 2, nb*B_BUF);
            cp_commit();
            cp_wait<2>();
        } else if (kc + 1 < nk){
            cp_wait<1>();
        } else {
            cp_wait<0>();
        }
        __syncthreads();
        uint32_t cur = (uint32_t)(buf*B_BUF);
        #pragma unroll
        for (int ks = 0; ks < 4; ks++){
            uint32_t a_f[4][4];
            #pragma unroll
            for (int mi = 0; mi < 4; mi++){
                uint32_t off = (uint32_t)((wr + mi*16 + wi + (grp & 1)*8)*144
                                          + (ks*16 + (grp >> 1)*8)*2);
                ldsm_x4(a_f[mi], sb + B_A + cur + off);
            }
            uint32_t b_f[4][2];
            #pragma unroll
            for (int ni = 0; ni < 4; ni++){
                uint32_t off = (uint32_t)((wn + ni*8 + (lane & 7))*144
                                          + (ks*16 + ((lane >> 3) & 1)*8)*2);
                ldsm_x2(b_f[ni], sb + B_W + cur + off);
            }
            #pragma unroll
            for (int mi = 0; mi < 4; mi++)
                #pragma unroll
                for (int ni = 0; ni < 4; ni++)
                    mma16816(acc[mi][ni], a_f[mi], b_f[ni]);
        }
        __syncthreads();
        buf++; if (buf == 3) buf = 0;
    }
#undef BSTAGE

    // ---- epilogue ----
    #pragma unroll
    for (int mi = 0; mi < 4; mi++){
        #pragma unroll
        for (int ni = 0; ni < 4; ni++){
            int gn = bn + wn + ni*8 + (lane & 3)*2;
            #pragma unroll
            for (int hh = 0; hh < 2; hh++){
                int m = bm + wr + mi*16 + (lane >> 2) + hh*8;
                float v0 = acc[mi][ni][hh*2 + 0];
                float v1 = acc[mi][ni][hh*2 + 1];
                if (bias){ v0 += bias[gn]; v1 += bias[gn + 1]; }
                if (act){
                    v0 = 0.5f*v0*(1.f + erff(v0*0.70710678118654752f));
                    v1 = 0.5f*v1*(1.f + erff(v1*0.70710678118654752f));
                }
                if (Ch){
                    *(uint32_t*)(Ch + (size_t)m*ldc + gn) = packh(v0, v1);
                } else {
                    if (R){
                        const float* rp = R + (size_t)m*ldr + gn;
                        v0 += rp[0]; v1 += rp[1];
                    }
                    *(float2*)(C + (size_t)m*ldc + gn) = make_float2(v0, v1);
                }
            }
        }
    }
}

// ============== kvprep: reads fp16 qkv; head-LN(Q x 1/8, K); writes fp16 ==============
__global__ void kvprep_kernel(const __half* __restrict__ qkv,
    const float* __restrict__ qn, const float* __restrict__ kn,
    __half* __restrict__ qh, __half* __restrict__ kh, __half* __restrict__ vh)
{
    int g = blockIdx.x*blockDim.x + threadIdx.x;   // NTOK*HEADS*8
    int seg = g & 7;
    int r = g >> 3;
    int tokn = r >> 3, h = r & 7;
    int b = tokn >> 10, l = tokn & 1023;
    if (l >= c_L[b]) return;
    size_t base = (size_t)tokn*DIM + h*64 + seg*8;

#define LD8H(P, X, Y) do { \
    uint4 raw = *(const uint4*)(P); \
    float2 f0 = __half22float2(*reinterpret_cast<__half2*>(&raw.x)); \
    float2 f1 = __half22float2(*reinterpret_cast<__half2*>(&raw.y)); \
    float2 f2 = __half22float2(*reinterpret_cast<__half2*>(&raw.z)); \
    float2 f3 = __half22float2(*reinterpret_cast<__half2*>(&raw.w)); \
    X = make_float4(f0.x, f0.y, f1.x, f1.y); \
    Y = make_float4(f2.x, f2.y, f3.x, f3.y); \
} while(0)

#define LN8(x, y, wvec, scale) do { \
    float sum = x.x + x.y + x.z + x.w + y.x + y.y + y.z + y.w; \
    sum += __shfl_xor_sync(0xffffffffu, sum, 1); \
    sum += __shfl_xor_sync(0xffffffffu, sum, 2); \
    sum += __shfl_xor_sync(0xffffffffu, sum, 4); \
    float mu = sum * (1.f/64.f); \
    x.x -= mu; x.y -= mu; x.z -= mu; x.w -= mu; \
    y.x -= mu; y.y -= mu; y.z -= mu; y.w -= mu; \
    float ss = x.x*x.x + x.y*x.y + x.z*x.z + x.w*x.w \
             + y.x*y.x + y.y*y.y + y.z*y.z + y.w*y.w; \
    ss += __shfl_xor_sync(0xffffffffu, ss, 1); \
    ss += __shfl_xor_sync(0xffffffffu, ss, 2); \
    ss += __shfl_xor_sync(0xffffffffu, ss, 4); \
    float rs = rsqrtf(ss * (1.f/64.f) + 1e-5f) * (scale); \
    float4 w0 = *(const float4*)((wvec) + seg*8); \
    float4 w1 = *(const float4*)((wvec) + seg*8 + 4); \
    x.x *= rs*w0.x; x.y *= rs*w0.y; x.z *= rs*w0.z; x.w *= rs*w0.w; \
    y.x *= rs*w1.x; y.y *= rs*w1.y; y.z *= rs*w1.z; y.w *= rs*w1.w; \
} while(0)

    {   // Q
        float4 x, y; LD8H(qkv + base, x, y);
        LN8(x, y, qn, 0.125f);
        *(uint4*)(qh + base) = cvt8s(x, y);
    }
    {   // K
        float4 x, y; LD8H(qkv + (size_t)NTOK*DIM + base, x, y);
        LN8(x, y, kn, 1.f);
        *(uint4*)(kh + base) = cvt8s(x, y);
    }
    {   // V (straight copy, already fp16)
        *(uint4*)(vh + base) = *(const uint4*)(qkv + (size_t)2*NTOK*DIM + base);
    }
#undef LN8
#undef LD8H
}

// ============== flash attention: pure fp16, cp.async double-buffered K/V ==============
#define FQ 0
#define FKV0 18432
#define FKVS 36864
#define FSMEM (18432 + 2*36864)          // 92160

__global__ __launch_bounds__(256, 2) void flash_kernel(
    const __half* __restrict__ Qh,
    const __half* __restrict__ Kh,
    const __half* __restrict__ Vh,
    __half* __restrict__ O)
{
    extern __shared__ char smem[];
    uint32_t sb = smem_u32(smem);
    int tid = threadIdx.x, lane = tid & 31, wid = tid >> 5;
    int qt = blockIdx.x;
    int bh = blockIdx.y;
    int b = bh >> 3, h = bh & 7;
    int L = c_L[b];
    if (qt*128 >= L) return;
    int ktiles = (L + 127) >> 7;

    // ---- stage Q ----
    #pragma unroll
    for (int it = 0; it < 4; it++){
        int slot = it*256 + tid; int row = slot >> 3, seg = slot & 7;
        size_t go = (size_t)(b*1024 + qt*128 + row)*DIM + h*64 + seg*8;
        cp_async16(sb + FQ + (uint32_t)(row*144 + seg*16), Qh + go);
    }
    cp_commit();

#define KVSTAGE(KT, SBASE) do { \
    _Pragma("unroll") \
    for (int it = 0; it < 4; it++){ \
        int slot = it*256 + tid; int row = slot >> 3, seg = slot & 7; \
        size_t go = (size_t)(b*1024 + (KT)*128 + row)*DIM + h*64 + seg*8; \
        uint32_t so = (uint32_t)(SBASE) + (uint32_t)(row*144 + seg*16); \
        cp_async16(sb + so,         Kh + go); \
        cp_async16(sb + so + 18432, Vh + go); \
    } } while(0)

    KVSTAGE(0, FKV0);
    cp_commit();

    cp_wait<1>();
    __syncthreads();

    int wr = wid*16;
    int grp = lane >> 3, wi = lane & 7;
    uint32_t aq[4][4];
    #pragma unroll
    for (int ks = 0; ks < 4; ks++){
        uint32_t off = (uint32_t)((wr + wi + (grp & 1)*8)*144 + (ks*16 + (grp >> 1)*8)*2);
        ldsm_x4(aq[ks], sb + FQ + off);
    }

    float m0 = -1e30f, m1 = -1e30f, l0 = 0.f, l1 = 0.f;
    float ao[8][4];
    #pragma unroll
    for (int i = 0; i < 8; i++)
        #pragma unroll
        for (int p = 0; p < 4; p++) ao[i][p] = 0.f;

    for (int kt = 0; kt < ktiles; kt++){
        if (kt + 1 < ktiles){
            KVSTAGE(kt + 1, FKV0 + ((kt + 1) & 1)*FKVS);
            cp_commit();
            cp_wait<1>();
        } else {
            cp_wait<0>();
        }
        __syncthreads();
        uint32_t kb = (uint32_t)(FKV0 + (kt & 1)*FKVS);

        // ---- S = Q K^T ----
        float s[16][4];
        #pragma unroll
        for (int i = 0; i < 16; i++)
            #pragma unroll
            for (int p = 0; p < 4; p++) s[i][p] = 0.f;
        #pragma unroll
        for (int ks = 0; ks < 4; ks++){
            #pragma unroll
            for (int ni = 0; ni < 16; ni++){
                uint32_t off = (uint32_t)((ni*8 + wi)*144 + (ks*16 + (grp & 1)*8)*2);
                uint32_t b_[2];
                ldsm_x2(b_, sb + kb + off);
                mma16816(s[ni], aq[ks], b_);
            }
        }

        // ---- mask (partial tile only) ----
        if (kt == ktiles - 1 && (L & 127)){
            int kbase = kt*128 + 2*(lane & 3);
            #pragma unroll
            for (int ni = 0; ni < 16; ni++){
                int kg = kbase + ni*8;
                if (kg     >= L){ s[ni][0] = -1e9f; s[ni][2] = -1e9f; }
                if (kg + 1 >= L){ s[ni][1] = -1e9f; s[ni][3] = -1e9f; }
            }
        }

        // ---- online softmax ----
        float tm0 = -1e30f, tm1 = -1e30f;
        #pragma unroll
        for (int ni = 0; ni < 16; ni++){
            tm0 = fmaxf(tm0, fmaxf(s[ni][0], s[ni][1]));
            tm1 = fmaxf(tm1, fmaxf(s[ni][2], s[ni][3]));
        }
        tm0 = fmaxf(tm0, __shfl_xor_sync(0xffffffffu, tm0, 1));
        tm0 = fmaxf(tm0, __shfl_xor_sync(0xffffffffu, tm0, 2));
        tm1 = fmaxf(tm1, __shfl_xor_sync(0xffffffffu, tm1, 1));
        tm1 = fmaxf(tm1, __shfl_xor_sync(0xffffffffu, tm1, 2));
        float mn0 = fmaxf(m0, tm0), mn1 = fmaxf(m1, tm1);
        float sc0 = __expf(m0 - mn0), sc1 = __expf(m1 - mn1);
        m0 = mn0; m1 = mn1;
        float ts0 = 0.f, ts1 = 0.f;
        #pragma unroll
        for (int ni = 0; ni < 16; ni++){
            s[ni][0] = __expf(s[ni][0] - m0);
            s[ni][1] = __expf(s[ni][1] - m0);
            s[ni][2] = __expf(s[ni][2] - m1);
            s[ni][3] = __expf(s[ni][3] - m1);
            ts0 += s[ni][0] + s[ni][1];
            ts1 += s[ni][2] + s[ni][3];
        }
        ts0 += __shfl_xor_sync(0xffffffffu, ts0, 1);
        ts0 += __shfl_xor_sync(0xffffffffu, ts0, 2);
        ts1 += __shfl_xor_sync(0xffffffffu, ts1, 1);
        ts1 += __shfl_xor_sync(0xffffffffu, ts1, 2);
        l0 = l0*sc0 + ts0;
        l1 = l1*sc1 + ts1;
        #pragma unroll
        for (int i = 0; i < 8; i++){
            ao[i][0] *= sc0; ao[i][1] *= sc0;
            ao[i][2] *= sc1; ao[i][3] *= sc1;
        }

        // ---- O += P V ----
        #pragma unroll
        for (int kk = 0; kk < 8; kk++){
            uint32_t ap[4];
            ap[0] = packh(s[2*kk][0],   s[2*kk][1]);
            ap[1] = packh(s[2*kk][2],   s[2*kk][3]);
            ap[2] = packh(s[2*kk+1][0], s[2*kk+1][1]);
            ap[3] = packh(s[2*kk+1][2], s[2*kk+1][3]);
            #pragma unroll
            for (int ni = 0; ni < 8; ni++){
                uint32_t off = (uint32_t)((kk*16 + (lane & 15))*144 + ni*16);
                uint32_t v_[2];
                ldsm_x2t(v_, sb + kb + 18432 + off);
                mma16816(ao[ni], ap, v_);
            }
        }
        __syncthreads();
    }
#undef KVSTAGE

    // ---- epilogue: fp16 O ----
    float il0 = 1.f / l0, il1 = 1.f / l1;
    int mrow = qt*128 + wr + (lane >> 2);
    #pragma unroll
    for (int ni = 0; ni < 8; ni++){
        int col = h*64 + ni*8 + 2*(lane & 3);
        *(uint32_t*)(O + (size_t)(b*1024 + mrow)*DIM + col)     = packh(ao[ni][0]*il0, ao[ni][1]*il0);
        *(uint32_t*)(O + (size_t)(b*1024 + mrow + 8)*DIM + col) = packh(ao[ni][2]*il1, ao[ni][3]*il1);
    }
}

// ---------------- patch packing ----------------
__global__ void pack_kernel(const float* __restrict__ img, float* __restrict__ tok){
    size_t i = (size_t)blockIdx.x*blockDim.x + threadIdx.x;
    if (i >= (size_t)NTOK*PDIM) return;
    int pd = (int)(i % PDIM);
    size_t bl = i / PDIM;
    int l = (int)(bl % LMAX);
    int b = (int)(bl / LMAX);
    int L = c_L[b], w = c_Wp[b];
    float v = 0.f;
    if (l < L){
        int c  = pd >> 8;
        int r  = pd & 255;
        int py = r >> 4, px = r & 15;
        int ph = l / w, pw = l % w;
        v = img[((size_t)(b*3 + c)*512 + (size_t)(ph*16 + py))*512 + (size_t)(pw*16 + px)];
    }
    tok[i] = v;
}

// ---------------- row LayerNorm, vectorized; writes f32 (y) or fp16 (yh) ----------------
__global__ void ln_kernel(const float* __restrict__ x, const float* __restrict__ w,
                          const float* __restrict__ bb, float* __restrict__ y,
                          __half* __restrict__ yh, int D, int tokskip){
    __shared__ float red[8];
    int row = blockIdx.x, tid = threadIdx.x, lane = tid & 31, wp = tid >> 5;
    int nw = blockDim.x >> 5;
    if (tokskip && (row & 1023) >= c_L[row >> 10]) return;
    int idx = tid*4;
    float4 v = make_float4(0,0,0,0);
    if (idx < D) v = *(const float4*)(x + (size_t)row*D + idx);
    float s = v.x + v.y + v.z + v.w;
    #pragma unroll
    for (int off = 16; off; off >>= 1) s += __shfl_xor_sync(0xffffffffu, s, off);
    if (lane == 0) red[wp] = s;
    __syncthreads();
    float tot = 0.f;
    for (int i = 0; i < nw; i++) tot += red[i];
    float mu = tot / (float)D;
    __syncthreads();
    float vs = 0.f;
    if (idx < D){
        float a = v.x - mu, b2 = v.y - mu, c = v.z - mu, d = v.w - mu;
        vs = a*a + b2*b2 + c*c + d*d;
    }
    #pragma unroll
    for (int off = 16; off; off >>= 1) vs += __shfl_xor_sync(0xffffffffu, vs, off);
    if (lane == 0) red[wp] = vs;
    __syncthreads();
    float tv = 0.f;
    for (int i = 0; i < nw; i++) tv += red[i];
    float rs = rsqrtf(tv / (float)D + 1e-5f);
    if (idx < D){
        float4 w4 = *(const float4*)(w + idx);
        float4 o;
        o.x = (v.x - mu)*rs*w4.x;
        o.y = (v.y - mu)*rs*w4.y;
        o.z = (v.z - mu)*rs*w4.z;
        o.w = (v.w - mu)*rs*w4.w;
        if (bb){
            float4 b4 = *(const float4*)(bb + idx);
            o.x += b4.x; o.y += b4.y; o.z += b4.z; o.w += b4.w;
        }
        if (y) *(float4*)(y + (size_t)row*D + idx) = o;
        else   *(uint2*)(yh + (size_t)row*D + idx) = make_uint2(packh(o.x, o.y), packh(o.z, o.w));
    }
}

// ---------------- fused LN + pos-embed + mask (D=512, in-place on t) ----------------
__global__ void ln_pos_kernel(float* __restrict__ t, const float* __restrict__ w,
                              const float* __restrict__ bb,
                              const float* __restrict__ ph, const float* __restrict__ pw){
    __shared__ float red[8];
    int row = blockIdx.x, tid = threadIdx.x, lane = tid & 31, wpi = tid >> 5;
    int nw = blockDim.x >> 5;
    int b = row >> 10, l = row & 1023;
    int L = c_L[b], wgrid = c_Wp[b];
    int idx = tid*4;
    if (l >= L){
        if (idx < DIM) *(float4*)(t + (size_t)row*DIM + idx) = make_float4(0,0,0,0);
        return;
    }
    float4 v = make_float4(0,0,0,0);
    if (idx < DIM) v = *(const float4*)(t + (size_t)row*DIM + idx);
    float s = v.x + v.y + v.z + v.w;
    #pragma unroll
    for (int off = 16; off; off >>= 1) s += __shfl_xor_sync(0xffffffffu, s, off);
    if (lane == 0) red[wpi] = s;
    __syncthreads();
    float tot = 0.f;
    for (int i = 0; i < nw; i++) tot += red[i];
    float mu = tot / (float)DIM;
    __syncthreads();
    float vs = 0.f;
    if (idx < DIM){
        float a = v.x - mu, b2 = v.y - mu, c = v.z - mu, d = v.w - mu;
        vs = a*a + b2*b2 + c*c + d*d;
    }
    #pragma unroll
    for (int off = 16; off; off >>= 1) vs += __shfl_xor_sync(0xffffffffu, vs, off);
    if (lane == 0) red[wpi] = vs;
    __syncthreads();
    float tv = 0.f;
    for (int i = 0; i < nw; i++) tv += red[i];
    float rs = rsqrtf(tv / (float)DIM + 1e-5f);
    if (idx < DIM){
        float4 w4 = *(const float4*)(w + idx);
        float4 b4 = *(const float4*)(bb + idx);
        float4 p0 = *(const float4*)(ph + (size_t)(l / wgrid)*DIM + idx);
        float4 p1 = *(const float4*)(pw + (size_t)(l % wgrid)*DIM + idx);
        float4 o;
        o.x = (v.x - mu)*rs*w4.x + b4.x + p0.x + p1.x;
        o.y = (v.y - mu)*rs*w4.y + b4.y + p0.y + p1.y;
        o.z = (v.z - mu)*rs*w4.z + b4.z + p0.z + p1.z;
        o.w = (v.w - mu)*rs*w4.w + b4.w + p0.w + p1.w;
        *(float4*)(t + (size_t)row*DIM + idx) = o;
    }
}

// ---------------- per-head LayerNorm over 64 dims (pool path) ----------------
__global__ void head_ln_kernel(float* __restrict__ x, const float* __restrict__ w, int rows){
    int gw = (int)(((size_t)blockIdx.x*blockDim.x + threadIdx.x) >> 5);
    int lane = threadIdx.x & 31;
    if (gw >= rows) return;
    float* p = x + (size_t)gw*64;
    float a = p[lane], b = p[lane + 32];
    float s = a + b;
    #pragma unroll
    for (int off = 16; off; off >>= 1) s += __shfl_xor_sync(0xffffffffu, s, off);
    float mu = s * (1.f/64.f);
    float da = a - mu, db = b - mu;
    float vs = da*da + db*db;
    #pragma unroll
    for (int off = 16; off; off >>= 1) vs += __shfl_xor_sync(0xffffffffu, vs, off);
    float rs = rsqrtf(vs * (1.f/64.f) + 1e-5f);
    p[lane]      = da * rs * w[lane];
    p[lane + 32] = db * rs * w[lane + 32];
}

// ---------------- tiny GEMM NT: warp per output element (small M) ----------------
__global__ void tiny_nt_kernel(const float* __restrict__ A, int lda,
                               const float* __restrict__ W, int ldw,
                               const float* __restrict__ bias,
                               float* __restrict__ C, int ldc,
                               int M, int N, int K){
    int gw = (int)(((size_t)blockIdx.x*blockDim.x + threadIdx.x) >> 5);
    int lane = threadIdx.x & 31;
    if (gw >= M*N) return;
    int m = gw / N, n = gw % N;
    const float* a = A + (size_t)m*lda;
    const float* wv = W + (size_t)n*ldw;
    float s = 0.f;
    for (int k = lane*4; k < K; k += 128){
        float4 av = *(const float4*)(a + k);
        float4 bv = *(const float4*)(wv + k);
        s += av.x*bv.x + av.y*bv.y + av.z*bv.z + av.w*bv.w;
    }
    #pragma unroll
    for (int off = 16; off; off >>= 1) s += __shfl_xor_sync(0xffffffffu, s, off);
    if (lane == 0){
        if (bias) s += bias[n];
        C[(size_t)m*ldc + n] = s;
    }
}

// ---------------- pooling attention (Lq=1) ----------------
__global__ void pool_attn_kernel(const float* __restrict__ qhat, const float* __restrict__ K,
                                 const float* __restrict__ V, float* __restrict__ O){
    int h = blockIdx.x, b = blockIdx.y;
    __shared__ float sq[64];
    __shared__ float sa[1024];
    __shared__ float red[8], red2[8];
    __shared__ float racc[4][64];
    int tid = threadIdx.x, lane = tid & 31, wp = tid >> 5;
    if (tid < 64) sq[tid] = qhat[h*64 + tid];
    __syncthreads();
    int L = c_L[b];
    for (int kk = tid; kk < 1024; kk += 256){
        float dot = -1e9f;
        if (kk < L){
            const float* kr = K + ((size_t)(b*1024 + kk))*DIM + h*64;
            float ss = 0.f;
            #pragma unroll
            for (int d = 0; d < 64; d++) ss += sq[d]*kr[d];
            dot = ss*0.125f;
        }
        sa[kk] = dot;
    }
    __syncthreads();
    float m = -1e30f;
    for (int kk = tid; kk < 1024; kk += 256) m = fmaxf(m, sa[kk]);
    #pragma unroll
    for (int off = 16; off; off >>= 1) m = fmaxf(m, __shfl_xor_sync(0xffffffffu, m, off));
    if (lane == 0) red[wp] = m;
    __syncthreads();
    float bm = -1e30f;
    #pragma unroll
    for (int i = 0; i < 8; i++) bm = fmaxf(bm, red[i]);
    float sum = 0.f;
    for (int kk = tid; kk < 1024; kk += 256){
        float e = __expf(sa[kk] - bm);
        sa[kk] = e; sum += e;
    }
    #pragma unroll
    for (int off = 16; off; off >>= 1) sum += __shfl_xor_sync(0xffffffffu, sum, off);
    if (lane == 0) red2[wp] = sum;
    __syncthreads();
    float bs = 0.f;
    #pragma unroll
    for (int i = 0; i < 8; i++) bs += red2[i];
    float inv = 1.f / bs;
    int dd = tid & 63, part = tid >> 6;
    float acc = 0.f;
    for (int kk = part; kk < 1024; kk += 4)
        acc += sa[kk] * V[((size_t)(b*1024 + kk))*DIM + h*64 + dd];
    racc[part][dd] = acc;
    __syncthreads();
    if (part == 0)
        O[b*DIM + h*64 + dd] = (racc[0][dd] + racc[1][dd] + racc[2][dd] + racc[3][dd]) * inv;
}

// ---------------- host helpers ----------------
static void launch_wcvt(const float* src, __half* h, long n){
    long n4 = n >> 2;
    wcvt_kernel<<<(int)((n4 + 255)/256), 256>>>(src, h, (int)n4);
}
static void launch_bg(const __half* A, int lda,
                      const __half* W, int ldw, long wz,
                      const float* bias, const float* R, int ldr,
                      float* C, __half* Ch, int ldc, long cz,
                      int N, int K, int act, int nz, int tokrows){
    dim3 g(N/128, NTOK/128, nz);
    bgemm_nt<<<g, 256, B_SMEM>>>(A, lda, W, ldw, wz, bias, R, ldr,
                                 C, Ch, ldc, cz, K, act, tokrows);
}
static void launch_tiny(const float* A, int lda, const float* W, int ldw,
                        const float* bias, float* C, int ldc, int M, int N, int K){
    int warps = M*N;
    tiny_nt_kernel<<<(warps*32 + 255)/256, 256>>>(A, lda, W, ldw, bias, C, ldc, M, N, K);
}

extern "C" void kernel_launch(void* const* d_in, const int* in_sizes, int n_in,
                              void* d_out, int out_size){
    const float* images   = (const float*)d_in[0];
    const float* pe_ln1_w = (const float*)d_in[1];
    const float* pe_ln1_b = (const float*)d_in[2];
    const float* pe_w     = (const float*)d_in[3];
    const float* pe_b     = (const float*)d_in[4];
    const float* pe_ln2_w = (const float*)d_in[5];
    const float* pe_ln2_b = (const float*)d_in[6];
    const float* pos_h    = (const float*)d_in[7];
    const float* pos_w    = (const float*)d_in[8];
    const float* attn_ln  = (const float*)d_in[9];
    const float* wq       = (const float*)d_in[10];
    const float* wk       = (const float*)d_in[11];
    const float* wv       = (const float*)d_in[12];
    const float* qn       = (const float*)d_in[13];
    const float* kn       = (const float*)d_in[14];
    const float* wo       = (const float*)d_in[15];
    const float* ff_ln    = (const float*)d_in[16];
    const float* ff_w1    = (const float*)d_in[17];
    const float* ff_b1    = (const float*)d_in[18];
    const float* ff_w2    = (const float*)d_in[19];
    const float* ff_b2    = (const float*)d_in[20];
    const float* final_ln = (const float*)d_in[21];
    const float* pool_q   = (const float*)d_in[22];
    const float* pool_ln  = (const float*)d_in[23];
    const float* pool_wq  = (const float*)d_in[24];
    const float* pool_wk  = (const float*)d_in[25];
    const float* pool_wv  = (const float*)d_in[26];
    const float* pool_qn  = (const float*)d_in[27];
    const float* pool_kn  = (const float*)d_in[28];
    const float* pool_wo  = (const float*)d_in[29];
    const float* head_ln  = (const float*)d_in[30];
    const float* head_w   = (const float*)d_in[31];
    float* out = (float*)d_out;

    cudaFuncSetAttribute(bgemm_nt, cudaFuncAttributeMaxDynamicSharedMemorySize, B_SMEM);
    cudaFuncSetAttribute(flash_kernel, cudaFuncAttributeMaxDynamicSharedMemorySize, FSMEM);

    float *tok,*t,*qkv,*u,*qp,*po,*pooled,*hn;
    __half *wh,*lt,*xn,*mlp,*o,*qkv16,*qh,*kh,*vh;
    cudaGetSymbolAddress((void**)&tok, g_tok);
    cudaGetSymbolAddress((void**)&t,   g_t);
    cudaGetSymbolAddress((void**)&qkv, g_qkv);
    cudaGetSymbolAddress((void**)&u,   g_u);
    cudaGetSymbolAddress((void**)&qp,  g_qp);
    cudaGetSymbolAddress((void**)&po,  g_po);
    cudaGetSymbolAddress((void**)&pooled, g_pooled);
    cudaGetSymbolAddress((void**)&hn,  g_hn);
    cudaGetSymbolAddress((void**)&wh,  g_wh);
    cudaGetSymbolAddress((void**)&lt,  g_lt);
    cudaGetSymbolAddress((void**)&xn,  g_xn);
    cudaGetSymbolAddress((void**)&mlp, g_mlp);
    cudaGetSymbolAddress((void**)&o,   g_o);
    cudaGetSymbolAddress((void**)&qkv16, g_qkv16);
    cudaGetSymbolAddress((void**)&qh,  g_qh2);
    cudaGetSymbolAddress((void**)&kh,  g_kh2);
    cudaGetSymbolAddress((void**)&vh,  g_vh2);

    float* kf = qkv + (size_t)NTOK*DIM;
    float* vf = qkv + (size_t)2*NTOK*DIM;

    // ---- weight convert (once per launch) ----
    launch_wcvt(wq, wh + OFF_QKV,            6L*DIM*DIM);
    launch_wcvt(wk, wh + OFF_QKV + 1572864L, 6L*DIM*DIM);
    launch_wcvt(wv, wh + OFF_QKV + 3145728L, 6L*DIM*DIM);
    launch_wcvt(wo, wh + OFF_WO,  6L*DIM*DIM);
    launch_wcvt(ff_w1, wh + OFF_FF1, 6L*MLPD*DIM);
    launch_wcvt(ff_w2, wh + OFF_FF2, 6L*DIM*MLPD);
    launch_wcvt(pe_w, wh + OFF_PE, (long)DIM*PDIM);
    launch_wcvt(pool_wk, wh + OFF_PK, (long)DIM*DIM);
    launch_wcvt(pool_wv, wh + OFF_PV, (long)DIM*DIM);

    // ---- patch embed ----
    pack_kernel<<<((size_t)NTOK*PDIM + 255)/256, 256>>>(images, tok);
    ln_kernel<<<NTOK, 256>>>(tok, pe_ln1_w, pe_ln1_b, nullptr, lt, PDIM, 1);
    launch_bg(lt, PDIM, wh + OFF_PE, PDIM, 0, pe_b,
              nullptr, 0, t, nullptr, DIM, 0, DIM, PDIM, 0, 1, 1);
    ln_pos_kernel<<<NTOK, 128>>>(t, pe_ln2_w, pe_ln2_b, pos_h, pos_w);

    // ---- transformer layers ----
    for (int l = 0; l < NDEPTH; l++){
        ln_kernel<<<NTOK, 128>>>(t, attn_ln + l*DIM, nullptr, nullptr, xn, DIM, 1);
        launch_bg(xn, DIM, wh + OFF_QKV + (size_t)l*DIM*DIM, DIM, 1572864L,
                  nullptr, nullptr, 0,
                  nullptr, qkv16, DIM, (long)NTOK*DIM, DIM, DIM, 0, 3, 1);
        kvprep_kernel<<<NTOK*HEADS*8/256, 256>>>(qkv16, qn + l*DH, kn + l*DH, qh, kh, vh);
        flash_kernel<<<dim3(8, BB*HEADS), 256, FSMEM>>>(qh, kh, vh, o);
        launch_bg(o, DIM, wh + OFF_WO + (size_t)l*DIM*DIM, DIM, 0,
                  nullptr, t, DIM, t, nullptr, DIM, 0, DIM, DIM, 0, 1, 1);
        ln_kernel<<<NTOK, 128>>>(t, ff_ln + l*DIM, nullptr, nullptr, xn, DIM, 1);
        launch_bg(xn, DIM, wh + OFF_FF1 + (size_t)l*MLPD*DIM, DIM, 0,
                  ff_b1 + l*MLPD, nullptr, 0,
                  nullptr, mlp, MLPD, 0, MLPD, DIM, 1, 1, 1);
        launch_bg(mlp, MLPD, wh + OFF_FF2 + (size_t)l*DIM*MLPD, MLPD, 0,
                  ff_b2 + l*DIM, t, DIM, t, nullptr, DIM, 0, DIM, MLPD, 0, 1, 1);
    }

    // ---- final LN + pooling ----
    ln_kernel<<<NTOK, 128>>>(t, final_ln, nullptr, nullptr, xn, DIM, 1);
    ln_kernel<<<1, 128>>>(pool_q, pool_ln, nullptr, u, nullptr, DIM, 0);
    launch_tiny(u, DIM, pool_wq, DIM, nullptr, qp, DIM, 1, DIM, DIM);
    head_ln_kernel<<<1, 256>>>(qp, pool_qn, HEADS);
    launch_bg(xn, DIM, wh + OFF_PK, DIM, 0, nullptr, nullptr, 0,
              kf, nullptr, DIM, 0, DIM, DIM, 0, 1, 1);
    head_ln_kernel<<<(NTOK*HEADS*32 + 255)/256, 256>>>(kf, pool_kn, NTOK*HEADS);
    launch_bg(xn, DIM, wh + OFF_PV, DIM, 0, nullptr, nullptr, 0,
              vf, nullptr, DIM, 0, DIM, DIM, 0, 1, 1);
    pool_attn_kernel<<<dim3(HEADS, BB), 256>>>(qp, kf, vf, po);
    launch_tiny(po, DIM, pool_wo, DIM, nullptr, pooled, DIM, BB, DIM, DIM);
    ln_kernel<<<BB, 128>>>(pooled, head_ln, nullptr, hn, nullptr, DIM, 0);
    launch_tiny(hn, DIM, head_w, DIM, nullptr, out, NC, BB, NC, DIM);
}

// round 14
// speedup vs baseline: 1.1097x; 1.0305x over previous
#include <cuda_runtime.h>
#include <cuda_fp16.h>
#include <math.h>
#include <stdint.h>

#define BB 8
#define LMAX 1024
#define DIM 512
#define HEADS 8
#define DH 64
#define NDEPTH 6
#define MLPD 2048
#define NC 1000
#define PDIM 768
#define NTOK (BB*LMAX)   // 8192

__constant__ int c_L[8]  = {1024, 768, 896, 576, 560, 512, 384, 640};
__constant__ int c_Wp[8] = {  32,  24,  32,  24,  28,  32,  16,  20};

// weight buffer offsets (elements)
#define OFF_QKV 0L
#define OFF_WO  4718592L
#define OFF_FF1 6291456L
#define OFF_FF2 12582912L
#define OFF_PE  18874368L
#define OFF_PK  19267584L
#define OFF_PV  19529728L
#define WTOT    19791872L

// ---------------- scratch ----------------
__device__ __align__(128) float g_tok[(size_t)NTOK*PDIM];
__device__ __align__(128) float g_t  [(size_t)NTOK*DIM];
__device__ __align__(128) float g_qkv[(size_t)3*NTOK*DIM];
__device__ __align__(128) float g_u  [DIM];
__device__ __align__(128) float g_qp [DIM];
__device__ __align__(128) float g_po [BB*DIM];
__device__ __align__(128) float g_pooled[BB*DIM];
__device__ __align__(128) float g_hn [BB*DIM];
__device__ __align__(128) __half g_wh[WTOT];
__device__ __align__(128) __half g_lt [(size_t)NTOK*PDIM];
__device__ __align__(128) __half g_xn [(size_t)NTOK*DIM];
__device__ __align__(128) __half g_mlp[(size_t)NTOK*MLPD];
__device__ __align__(128) __half g_o  [(size_t)NTOK*DIM];
__device__ __align__(128) __half g_qkv16[(size_t)3*NTOK*DIM];
__device__ __align__(128) __half g_qh2[(size_t)NTOK*DIM];
__device__ __align__(128) __half g_kh2[(size_t)NTOK*DIM];
__device__ __align__(128) __half g_vh2[(size_t)NTOK*DIM];

// ================= helpers =================
__device__ __forceinline__ uint32_t smem_u32(const void* p){
    uint32_t a; asm("{ .reg .u64 t; cvta.to.shared.u64 t, %1; cvt.u32.u64 %0, t; }" : "=r"(a) : "l"(p));
    return a;
}
__device__ __forceinline__ void ldsm_x4(uint32_t* r, uint32_t addr){
    asm volatile("ldmatrix.sync.aligned.m8n8.x4.shared.b16 {%0,%1,%2,%3}, [%4];"
        : "=r"(r[0]),"=r"(r[1]),"=r"(r[2]),"=r"(r[3]) : "r"(addr));
}
__device__ __forceinline__ void ldsm_x2(uint32_t* r, uint32_t addr){
    asm volatile("ldmatrix.sync.aligned.m8n8.x2.shared.b16 {%0,%1}, [%2];"
        : "=r"(r[0]),"=r"(r[1]) : "r"(addr));
}
__device__ __forceinline__ void ldsm_x2t(uint32_t* r, uint32_t addr){
    asm volatile("ldmatrix.sync.aligned.m8n8.x2.trans.shared.b16 {%0,%1}, [%2];"
        : "=r"(r[0]),"=r"(r[1]) : "r"(addr));
}
__device__ __forceinline__ void mma16816(float* c, const uint32_t* a, const uint32_t* b){
    asm volatile("mma.sync.aligned.m16n8k16.row.col.f32.f16.f16.f32 "
        "{%0,%1,%2,%3}, {%4,%5,%6,%7}, {%8,%9}, {%0,%1,%2,%3};"
        : "+f"(c[0]),"+f"(c[1]),"+f"(c[2]),"+f"(c[3])
        : "r"(a[0]),"r"(a[1]),"r"(a[2]),"r"(a[3]), "r"(b[0]),"r"(b[1]));
}
__device__ __forceinline__ void cp_async16(uint32_t dst, const void* src){
    asm volatile("cp.async.cg.shared.global [%0], [%1], 16;" :: "r"(dst), "l"(src) : "memory");
}
__device__ __forceinline__ void cp_commit(){ asm volatile("cp.async.commit_group;" ::: "memory"); }
template<int N> __device__ __forceinline__ void cp_wait(){
    asm volatile("cp.async.wait_group %0;" :: "n"(N) : "memory");
}
__device__ __forceinline__ uint32_t h2u(__half2 v){ return *reinterpret_cast<uint32_t*>(&v); }
__device__ __forceinline__ uint32_t packh(float a, float b){
    return h2u(__float22half2_rn(make_float2(a, b)));
}
__device__ __forceinline__ uint4 cvt8s(float4 a, float4 b){
    return make_uint4(packh(a.x, a.y), packh(a.z, a.w), packh(b.x, b.y), packh(b.z, b.w));
}

// ---------------- fused weight convert: all 9 regions in one kernel ----------------
struct WSrcs { const float* p[9]; };
__constant__ long c_wbase4[10] = {0L, 393216L, 786432L, 1179648L, 1572864L,
                                  3145728L, 4718592L, 4816896L, 4882432L, 4947968L};
__global__ void wcvt_all_kernel(WSrcs srcs, __half* __restrict__ h, int n4){
    int i = blockIdx.x*blockDim.x + threadIdx.x;
    if (i >= n4) return;
    int r = 0;
    #pragma unroll
    for (int j = 1; j < 9; j++) if (i >= (int)c_wbase4[j]) r = j;
    float4 v = ((const float4*)srcs.p[r])[i - (int)c_wbase4[r]];
    ((uint2*)h)[i] = make_uint2(packh(v.x, v.y), packh(v.z, v.w));
}

// ============== cp.async HMMA GEMM NT (128x128 tile, 2-stage pipeline) ==============
#define BTILE (128*144)          // 18432
#define B_A  0
#define B_W  BTILE
#define B_BUF (2*BTILE)          // 36864
#define B_SMEM (2*B_BUF)         // 73728

__global__ __launch_bounds__(256, 2) void bgemm_nt(
    const __half* __restrict__ A, int lda,
    const __half* __restrict__ W, int ldw, long wz,
    const float* __restrict__ bias,
    const float* __restrict__ R, int ldr,
    float* __restrict__ C, __half* __restrict__ Ch,
    int ldc, long cz,
    int K, int act, int tokrows)
{
    extern __shared__ char smem[];
    uint32_t sb = smem_u32(smem);
    int tid = threadIdx.x, lane = tid & 31, wid = tid >> 5;
    int z = blockIdx.z;
    W += (size_t)z*wz;
    if (C)  C  += (size_t)z*cz;
    if (Ch) Ch += (size_t)z*cz;
    int bm = blockIdx.y*128, bn = blockIdx.x*128;
    if (tokrows && (bm & 1023) >= c_L[bm >> 10]) return;
    int wr = (wid & 1)*64;
    int wn = (wid >> 1)*32;

    float acc[4][4][4];
    #pragma unroll
    for (int i = 0; i < 4; i++)
        #pragma unroll
        for (int j = 0; j < 4; j++)
            #pragma unroll
            for (int p = 0; p < 4; p++) acc[i][j][p] = 0.f;

#define BSTAGE(KC, BUFB) do { \
    _Pragma("unroll") \
    for (int it = 0; it < 4; it++){ \
        int slot = it*256 + tid; int row = slot >> 3, seg = slot & 7; \
        uint32_t so = (uint32_t)(BUFB) + (uint32_t)(row*144 + seg*16); \
        cp_async16(sb + B_A + so, A + (size_t)(bm + row)*lda + (KC)*64 + seg*8); \
        cp_async16(sb + B_W + so, W + (size_t)(bn + row)*ldw + (KC)*64 + seg*8); \
    } } while(0)

    int nk = K >> 6;
    BSTAGE(0, 0);
    cp_commit();

    int grp = lane >> 3, wi = lane & 7;
    for (int kc = 0; kc < nk; kc++){
        if (kc + 1 < nk){
            BSTAGE(kc + 1, ((kc + 1) & 1)*B_BUF);
            cp_commit();
            cp_wait<1>();
        } else {
            cp_wait<0>();
        }
        __syncthreads();
        uint32_t cur = (uint32_t)((kc & 1)*B_BUF);
        #pragma unroll
        for (int ks = 0; ks < 4; ks++){
            uint32_t a_f[4][4];
            #pragma unroll
            for (int mi = 0; mi < 4; mi++){
                uint32_t off = (uint32_t)((wr + mi*16 + wi + (grp & 1)*8)*144
                                          + (ks*16 + (grp >> 1)*8)*2);
                ldsm_x4(a_f[mi], sb + B_A + cur + off);
            }
            uint32_t b_f[4][2];
            #pragma unroll
            for (int ni = 0; ni < 4; ni++){
                uint32_t off = (uint32_t)((wn + ni*8 + (lane & 7))*144
                                          + (ks*16 + ((lane >> 3) & 1)*8)*2);
                ldsm_x2(b_f[ni], sb + B_W + cur + off);
            }
            #pragma unroll
            for (int mi = 0; mi < 4; mi++)
                #pragma unroll
                for (int ni = 0; ni < 4; ni++)
                    mma16816(acc[mi][ni], a_f[mi], b_f[ni]);
        }
        __syncthreads();
    }
#undef BSTAGE

    // ---- epilogue ----
    #pragma unroll
    for (int mi = 0; mi < 4; mi++){
        #pragma unroll
        for (int ni = 0; ni < 4; ni++){
            int gn = bn + wn + ni*8 + (lane & 3)*2;
            #pragma unroll
            for (int hh = 0; hh < 2; hh++){
                int m = bm + wr + mi*16 + (lane >> 2) + hh*8;
                float v0 = acc[mi][ni][hh*2 + 0];
                float v1 = acc[mi][ni][hh*2 + 1];
                if (bias){ v0 += bias[gn]; v1 += bias[gn + 1]; }
                if (act){
                    v0 = 0.5f*v0*(1.f + erff(v0*0.70710678118654752f));
                    v1 = 0.5f*v1*(1.f + erff(v1*0.70710678118654752f));
                }
                if (Ch){
                    *(uint32_t*)(Ch + (size_t)m*ldc + gn) = packh(v0, v1);
                } else {
                    if (R){
                        const float* rp = R + (size_t)m*ldr + gn;
                        v0 += rp[0]; v1 += rp[1];
                    }
                    *(float2*)(C + (size_t)m*ldc + gn) = make_float2(v0, v1);
                }
            }
        }
    }
}

// ============== kvprep: reads fp16 qkv; head-LN(Q x 1/8, K); writes fp16 ==============
__global__ void kvprep_kernel(const __half* __restrict__ qkv,
    const float* __restrict__ qn, const float* __restrict__ kn,
    __half* __restrict__ qh, __half* __restrict__ kh, __half* __restrict__ vh)
{
    int g = blockIdx.x*blockDim.x + threadIdx.x;   // NTOK*HEADS*8
    int seg = g & 7;
    int r = g >> 3;
    int tokn = r >> 3, h = r & 7;
    int b = tokn >> 10, l = tokn & 1023;
    if (l >= c_L[b]) return;
    size_t base = (size_t)tokn*DIM + h*64 + seg*8;

#define LD8H(P, X, Y) do { \
    uint4 raw = *(const uint4*)(P); \
    float2 f0 = __half22float2(*reinterpret_cast<__half2*>(&raw.x)); \
    float2 f1 = __half22float2(*reinterpret_cast<__half2*>(&raw.y)); \
    float2 f2 = __half22float2(*reinterpret_cast<__half2*>(&raw.z)); \
    float2 f3 = __half22float2(*reinterpret_cast<__half2*>(&raw.w)); \
    X = make_float4(f0.x, f0.y, f1.x, f1.y); \
    Y = make_float4(f2.x, f2.y, f3.x, f3.y); \
} while(0)

#define LN8(x, y, wvec, scale) do { \
    float sum = x.x + x.y + x.z + x.w + y.x + y.y + y.z + y.w; \
    sum += __shfl_xor_sync(0xffffffffu, sum, 1); \
    sum += __shfl_xor_sync(0xffffffffu, sum, 2); \
    sum += __shfl_xor_sync(0xffffffffu, sum, 4); \
    float mu = sum * (1.f/64.f); \
    x.x -= mu; x.y -= mu; x.z -= mu; x.w -= mu; \
    y.x -= mu; y.y -= mu; y.z -= mu; y.w -= mu; \
    float ss = x.x*x.x + x.y*x.y + x.z*x.z + x.w*x.w \
             + y.x*y.x + y.y*y.y + y.z*y.z + y.w*y.w; \
    ss += __shfl_xor_sync(0xffffffffu, ss, 1); \
    ss += __shfl_xor_sync(0xffffffffu, ss, 2); \
    ss += __shfl_xor_sync(0xffffffffu, ss, 4); \
    float rs = rsqrtf(ss * (1.f/64.f) + 1e-5f) * (scale); \
    float4 w0 = *(const float4*)((wvec) + seg*8); \
    float4 w1 = *(const float4*)((wvec) + seg*8 + 4); \
    x.x *= rs*w0.x; x.y *= rs*w0.y; x.z *= rs*w0.z; x.w *= rs*w0.w; \
    y.x *= rs*w1.x; y.y *= rs*w1.y; y.z *= rs*w1.z; y.w *= rs*w1.w; \
} while(0)

    {   // Q
        float4 x, y; LD8H(qkv + base, x, y);
        LN8(x, y, qn, 0.125f);
        *(uint4*)(qh + base) = cvt8s(x, y);
    }
    {   // K
        float4 x, y; LD8H(qkv + (size_t)NTOK*DIM + base, x, y);
        LN8(x, y, kn, 1.f);
        *(uint4*)(kh + base) = cvt8s(x, y);
    }
    {   // V (straight copy, already fp16)
        *(uint4*)(vh + base) = *(const uint4*)(qkv + (size_t)2*NTOK*DIM + base);
    }
#undef LN8
#undef LD8H
}

// ============== flash attention: pure fp16, cp.async double-buffered K/V ==============
#define FQ 0
#define FKV0 18432
#define FKVS 36864
#define FSMEM (18432 + 2*36864)          // 92160

__global__ __launch_bounds__(256, 2) void flash_kernel(
    const __half* __restrict__ Qh,
    const __half* __restrict__ Kh,
    const __half* __restrict__ Vh,
    __half* __restrict__ O)
{
    extern __shared__ char smem[];
    uint32_t sb = smem_u32(smem);
    int tid = threadIdx.x, lane = tid & 31, wid = tid >> 5;
    int qt = blockIdx.x;
    int bh = blockIdx.y;
    int b = bh >> 3, h = bh & 7;
    int L = c_L[b];
    if (qt*128 >= L) return;
    int ktiles = (L + 127) >> 7;

    // ---- stage Q ----
    #pragma unroll
    for (int it = 0; it < 4; it++){
        int slot = it*256 + tid; int row = slot >> 3, seg = slot & 7;
        size_t go = (size_t)(b*1024 + qt*128 + row)*DIM + h*64 + seg*8;
        cp_async16(sb + FQ + (uint32_t)(row*144 + seg*16), Qh + go);
    }
    cp_commit();

#define KVSTAGE(KT, SBASE) do { \
    _Pragma("unroll") \
    for (int it = 0; it < 4; it++){ \
        int slot = it*256 + tid; int row = slot >> 3, seg = slot & 7; \
        size_t go = (size_t)(b*1024 + (KT)*128 + row)*DIM + h*64 + seg*8; \
        uint32_t so = (uint32_t)(SBASE) + (uint32_t)(row*144 + seg*16); \
        cp_async16(sb + so,         Kh + go); \
        cp_async16(sb + so + 18432, Vh + go); \
    } } while(0)

    KVSTAGE(0, FKV0);
    cp_commit();

    cp_wait<1>();
    __syncthreads();

    int wr = wid*16;
    int grp = lane >> 3, wi = lane & 7;
    uint32_t aq[4][4];
    #pragma unroll
    for (int ks = 0; ks < 4; ks++){
        uint32_t off = (uint32_t)((wr + wi + (grp & 1)*8)*144 + (ks*16 + (grp >> 1)*8)*2);
        ldsm_x4(aq[ks], sb + FQ + off);
    }

    float m0 = -1e30f, m1 = -1e30f, l0 = 0.f, l1 = 0.f;
    float ao[8][4];
    #pragma unroll
    for (int i = 0; i < 8; i++)
        #pragma unroll
        for (int p = 0; p < 4; p++) ao[i][p] = 0.f;

    for (int kt = 0; kt < ktiles; kt++){
        if (kt + 1 < ktiles){
            KVSTAGE(kt + 1, FKV0 + ((kt + 1) & 1)*FKVS);
            cp_commit();
            cp_wait<1>();
        } else {
            cp_wait<0>();
        }
        __syncthreads();
        uint32_t kb = (uint32_t)(FKV0 + (kt & 1)*FKVS);

        // ---- S = Q K^T ----
        float s[16][4];
        #pragma unroll
        for (int i = 0; i < 16; i++)
            #pragma unroll
            for (int p = 0; p < 4; p++) s[i][p] = 0.f;
        #pragma unroll
        for (int ks = 0; ks < 4; ks++){
            #pragma unroll
            for (int ni = 0; ni < 16; ni++){
                uint32_t off = (uint32_t)((ni*8 + wi)*144 + (ks*16 + (grp & 1)*8)*2);
                uint32_t b_[2];
                ldsm_x2(b_, sb + kb + off);
                mma16816(s[ni], aq[ks], b_);
            }
        }

        // ---- mask (partial tile only) ----
        if (kt == ktiles - 1 && (L & 127)){
            int kbase = kt*128 + 2*(lane & 3);
            #pragma unroll
            for (int ni = 0; ni < 16; ni++){
                int kg = kbase + ni*8;
                if (kg     >= L){ s[ni][0] = -1e9f; s[ni][2] = -1e9f; }
                if (kg + 1 >= L){ s[ni][1] = -1e9f; s[ni][3] = -1e9f; }
            }
        }

        // ---- online softmax ----
        float tm0 = -1e30f, tm1 = -1e30f;
        #pragma unroll
        for (int ni = 0; ni < 16; ni++){
            tm0 = fmaxf(tm0, fmaxf(s[ni][0], s[ni][1]));
            tm1 = fmaxf(tm1, fmaxf(s[ni][2], s[ni][3]));
        }
        tm0 = fmaxf(tm0, __shfl_xor_sync(0xffffffffu, tm0, 1));
        tm0 = fmaxf(tm0, __shfl_xor_sync(0xffffffffu, tm0, 2));
        tm1 = fmaxf(tm1, __shfl_xor_sync(0xffffffffu, tm1, 1));
        tm1 = fmaxf(tm1, __shfl_xor_sync(0xffffffffu, tm1, 2));
        float mn0 = fmaxf(m0, tm0), mn1 = fmaxf(m1, tm1);
        float sc0 = __expf(m0 - mn0), sc1 = __expf(m1 - mn1);
        m0 = mn0; m1 = mn1;
        float ts0 = 0.f, ts1 = 0.f;
        #pragma unroll
        for (int ni = 0; ni < 16; ni++){
            s[ni][0] = __expf(s[ni][0] - m0);
            s[ni][1] = __expf(s[ni][1] - m0);
            s[ni][2] = __expf(s[ni][2] - m1);
            s[ni][3] = __expf(s[ni][3] - m1);
            ts0 += s[ni][0] + s[ni][1];
            ts1 += s[ni][2] + s[ni][3];
        }
        ts0 += __shfl_xor_sync(0xffffffffu, ts0, 1);
        ts0 += __shfl_xor_sync(0xffffffffu, ts0, 2);
        ts1 += __shfl_xor_sync(0xffffffffu, ts1, 1);
        ts1 += __shfl_xor_sync(0xffffffffu, ts1, 2);
        l0 = l0*sc0 + ts0;
        l1 = l1*sc1 + ts1;
        #pragma unroll
        for (int i = 0; i < 8; i++){
            ao[i][0] *= sc0; ao[i][1] *= sc0;
            ao[i][2] *= sc1; ao[i][3] *= sc1;
        }

        // ---- O += P V ----
        #pragma unroll
        for (int kk = 0; kk < 8; kk++){
            uint32_t ap[4];
            ap[0] = packh(s[2*kk][0],   s[2*kk][1]);
            ap[1] = packh(s[2*kk][2],   s[2*kk][3]);
            ap[2] = packh(s[2*kk+1][0], s[2*kk+1][1]);
            ap[3] = packh(s[2*kk+1][2], s[2*kk+1][3]);
            #pragma unroll
            for (int ni = 0; ni < 8; ni++){
                uint32_t off = (uint32_t)((kk*16 + (lane & 15))*144 + ni*16);
                uint32_t v_[2];
                ldsm_x2t(v_, sb + kb + 18432 + off);
                mma16816(ao[ni], ap, v_);
            }
        }
        __syncthreads();
    }
#undef KVSTAGE

    // ---- epilogue: fp16 O ----
    float il0 = 1.f / l0, il1 = 1.f / l1;
    int mrow = qt*128 + wr + (lane >> 2);
    #pragma unroll
    for (int ni = 0; ni < 8; ni++){
        int col = h*64 + ni*8 + 2*(lane & 3);
        *(uint32_t*)(O + (size_t)(b*1024 + mrow)*DIM + col)     = packh(ao[ni][0]*il0, ao[ni][1]*il0);
        *(uint32_t*)(O + (size_t)(b*1024 + mrow + 8)*DIM + col) = packh(ao[ni][2]*il1, ao[ni][3]*il1);
    }
}

// ---------------- patch packing ----------------
__global__ void pack_kernel(const float* __restrict__ img, float* __restrict__ tok){
    size_t i = (size_t)blockIdx.x*blockDim.x + threadIdx.x;
    if (i >= (size_t)NTOK*PDIM) return;
    int pd = (int)(i % PDIM);
    size_t bl = i / PDIM;
    int l = (int)(bl % LMAX);
    int b = (int)(bl / LMAX);
    int L = c_L[b], w = c_Wp[b];
    float v = 0.f;
    if (l < L){
        int c  = pd >> 8;
        int r  = pd & 255;
        int py = r >> 4, px = r & 15;
        int ph = l / w, pw = l % w;
        v = img[((size_t)(b*3 + c)*512 + (size_t)(ph*16 + py))*512 + (size_t)(pw*16 + px)];
    }
    tok[i] = v;
}

// ---------------- warp-per-row LayerNorm (D = NV*128); writes f32 (y) or fp16 (yh) ----------------
template<int NV>
__global__ void lnw_kernel(const float* __restrict__ x, const float* __restrict__ w,
                           const float* __restrict__ bb, float* __restrict__ y,
                           __half* __restrict__ yh, int rows, int tokskip){
    int gw = (int)(((size_t)blockIdx.x*blockDim.x + threadIdx.x) >> 5);
    int lane = threadIdx.x & 31;
    if (gw >= rows) return;
    if (tokskip && (gw & 1023) >= c_L[gw >> 10]) return;
    const int D = NV*128;
    const float* xr = x + (size_t)gw*D;
    float4 v[NV];
    float s = 0.f;
    #pragma unroll
    for (int i = 0; i < NV; i++){
        v[i] = *(const float4*)(xr + i*128 + lane*4);
        s += v[i].x + v[i].y + v[i].z + v[i].w;
    }
    #pragma unroll
    for (int off = 16; off; off >>= 1) s += __shfl_xor_sync(0xffffffffu, s, off);
    float mu = s / (float)D;
    float vs = 0.f;
    #pragma unroll
    for (int i = 0; i < NV; i++){
        float a = v[i].x - mu, b = v[i].y - mu, c = v[i].z - mu, d = v[i].w - mu;
        vs += a*a + b*b + c*c + d*d;
    }
    #pragma unroll
    for (int off = 16; off; off >>= 1) vs += __shfl_xor_sync(0xffffffffu, vs, off);
    float rs = rsqrtf(vs / (float)D + 1e-5f);
    #pragma unroll
    for (int i = 0; i < NV; i++){
        int idx = i*128 + lane*4;
        float4 w4 = *(const float4*)(w + idx);
        float4 o;
        o.x = (v[i].x - mu)*rs*w4.x;
        o.y = (v[i].y - mu)*rs*w4.y;
        o.z = (v[i].z - mu)*rs*w4.z;
        o.w = (v[i].w - mu)*rs*w4.w;
        if (bb){
            float4 b4 = *(const float4*)(bb + idx);
            o.x += b4.x; o.y += b4.y; o.z += b4.z; o.w += b4.w;
        }
        if (y) *(float4*)(y + (size_t)gw*D + idx) = o;
        else   *(uint2*)(yh + (size_t)gw*D + idx) = make_uint2(packh(o.x, o.y), packh(o.z, o.w));
    }
}

// ---------------- fused LN + pos-embed + mask (D=512, in-place on t), warp per row ----------------
__global__ void ln_pos_kernel(float* __restrict__ t, const float* __restrict__ w,
                              const float* __restrict__ bb,
                              const float* __restrict__ ph, const float* __restrict__ pw){
    int gw = (int)(((size_t)blockIdx.x*blockDim.x + threadIdx.x) >> 5);
    int lane = threadIdx.x & 31;
    if (gw >= NTOK) return;
    int b = gw >> 10, l = gw & 1023;
    int L = c_L[b], wgrid = c_Wp[b];
    float* tr = t + (size_t)gw*DIM;
    if (l >= L){
        #pragma unroll
        for (int i = 0; i < 4; i++)
            *(float4*)(tr + i*128 + lane*4) = make_float4(0,0,0,0);
        return;
    }
    float4 v[4];
    float s = 0.f;
    #pragma unroll
    for (int i = 0; i < 4; i++){
        v[i] = *(const float4*)(tr + i*128 + lane*4);
        s += v[i].x + v[i].y + v[i].z + v[i].w;
    }
    #pragma unroll
    for (int off = 16; off; off >>= 1) s += __shfl_xor_sync(0xffffffffu, s, off);
    float mu = s / (float)DIM;
    float vs = 0.f;
    #pragma unroll
    for (int i = 0; i < 4; i++){
        float a = v[i].x - mu, b2 = v[i].y - mu, c = v[i].z - mu, d = v[i].w - mu;
        vs += a*a + b2*b2 + c*c + d*d;
    }
    #pragma unroll
    for (int off = 16; off; off >>= 1) vs += __shfl_xor_sync(0xffffffffu, vs, off);
    float rs = rsqrtf(vs / (float)DIM + 1e-5f);
    const float* p0r = ph + (size_t)(l / wgrid)*DIM;
    const float* p1r = pw + (size_t)(l % wgrid)*DIM;
    #pragma unroll
    for (int i = 0; i < 4; i++){
        int idx = i*128 + lane*4;
        float4 w4 = *(const float4*)(w + idx);
        float4 b4 = *(const float4*)(bb + idx);
        float4 p0 = *(const float4*)(p0r + idx);
        float4 p1 = *(const float4*)(p1r + idx);
        float4 o;
        o.x = (v[i].x - mu)*rs*w4.x + b4.x + p0.x + p1.x;
        o.y = (v[i].y - mu)*rs*w4.y + b4.y + p0.y + p1.y;
        o.z = (v[i].z - mu)*rs*w4.z + b4.z + p0.z + p1.z;
        o.w = (v[i].w - mu)*rs*w4.w + b4.w + p0.w + p1.w;
        *(float4*)(tr + idx) = o;
    }
}

// ---------------- per-head LayerNorm over 64 dims (pool path) ----------------
__global__ void head_ln_kernel(float* __restrict__ x, const float* __restrict__ w, int rows){
    int gw = (int)(((size_t)blockIdx.x*blockDim.x + threadIdx.x) >> 5);
    int lane = threadIdx.x & 31;
    if (gw >= rows) return;
    float* p = x + (size_t)gw*64;
    float a = p[lane], b = p[lane + 32];
    float s = a + b;
    #pragma unroll
    for (int off = 16; off; off >>= 1) s += __shfl_xor_sync(0xffffffffu, s, off);
    float mu = s * (1.f/64.f);
    float da = a - mu, db = b - mu;
    float vs = da*da + db*db;
    #pragma unroll
    for (int off = 16; off; off >>= 1) vs += __shfl_xor_sync(0xffffffffu, vs, off);
    float rs = rsqrtf(vs * (1.f/64.f) + 1e-5f);
    p[lane]      = da * rs * w[lane];
    p[lane + 32] = db * rs * w[lane + 32];
}

// ---------------- tiny GEMM NT: warp per output element (small M) ----------------
__global__ void tiny_nt_kernel(const float* __restrict__ A, int lda,
                               const float* __restrict__ W, int ldw,
                               const float* __restrict__ bias,
                               float* __restrict__ C, int ldc,
                               int M, int N, int K){
    int gw = (int)(((size_t)blockIdx.x*blockDim.x + threadIdx.x) >> 5);
    int lane = threadIdx.x & 31;
    if (gw >= M*N) return;
    int m = gw / N, n = gw % N;
    const float* a = A + (size_t)m*lda;
    const float* wv = W + (size_t)n*ldw;
    float s = 0.f;
    for (int k = lane*4; k < K; k += 128){
        float4 av = *(const float4*)(a + k);
        float4 bv = *(const float4*)(wv + k);
        s += av.x*bv.x + av.y*bv.y + av.z*bv.z + av.w*bv.w;
    }
    #pragma unroll
    for (int off = 16; off; off >>= 1) s += __shfl_xor_sync(0xffffffffu, s, off);
    if (lane == 0){
        if (bias) s += bias[n];
        C[(size_t)m*ldc + n] = s;
    }
}

// ---------------- pooling attention (Lq=1) ----------------
__global__ void pool_attn_kernel(const float* __restrict__ qhat, const float* __restrict__ K,
                                 const float* __restrict__ V, float* __restrict__ O){
    int h = blockIdx.x, b = blockIdx.y;
    __shared__ float sq[64];
    __shared__ float sa[1024];
    __shared__ float red[8], red2[8];
    __shared__ float racc[4][64];
    int tid = threadIdx.x, lane = tid & 31, wp = tid >> 5;
    if (tid < 64) sq[tid] = qhat[h*64 + tid];
    __syncthreads();
    int L = c_L[b];
    for (int kk = tid; kk < 1024; kk += 256){
        float dot = -1e9f;
        if (kk < L){
            const float* kr = K + ((size_t)(b*1024 + kk))*DIM + h*64;
            float ss = 0.f;
            #pragma unroll
            for (int d = 0; d < 64; d++) ss += sq[d]*kr[d];
            dot = ss*0.125f;
        }
        sa[kk] = dot;
    }
    __syncthreads();
    float m = -1e30f;
    for (int kk = tid; kk < 1024; kk += 256) m = fmaxf(m, sa[kk]);
    #pragma unroll
    for (int off = 16; off; off >>= 1) m = fmaxf(m, __shfl_xor_sync(0xffffffffu, m, off));
    if (lane == 0) red[wp] = m;
    __syncthreads();
    float bm = -1e30f;
    #pragma unroll
    for (int i = 0; i < 8; i++) bm = fmaxf(bm, red[i]);
    float sum = 0.f;
    for (int kk = tid; kk < 1024; kk += 256){
        float e = __expf(sa[kk] - bm);
        sa[kk] = e; sum += e;
    }
    #pragma unroll
    for (int off = 16; off; off >>= 1) sum += __shfl_xor_sync(0xffffffffu, sum, off);
    if (lane == 0) red2[wp] = sum;
    __syncthreads();
    float bs = 0.f;
    #pragma unroll
    for (int i = 0; i < 8; i++) bs += red2[i];
    float inv = 1.f / bs;
    int dd = tid & 63, part = tid >> 6;
    float acc = 0.f;
    for (int kk = part; kk < 1024; kk += 4)
        acc += sa[kk] * V[((size_t)(b*1024 + kk))*DIM + h*64 + dd];
    racc[part][dd] = acc;
    __syncthreads();
    if (part == 0)
        O[b*DIM + h*64 + dd] = (racc[0][dd] + racc[1][dd] + racc[2][dd] + racc[3][dd]) * inv;
}

// ---------------- host helpers ----------------
static void launch_bg(const __half* A, int lda,
                      const __half* W, int ldw, long wz,
                      const float* bias, const float* R, int ldr,
                      float* C, __half* Ch, int ldc, long cz,
                      int N, int K, int act, int nz, int tokrows){
    dim3 g(N/128, NTOK/128, nz);
    bgemm_nt<<<g, 256, B_SMEM>>>(A, lda, W, ldw, wz, bias, R, ldr,
                                 C, Ch, ldc, cz, K, act, tokrows);
}
static void launch_tiny(const float* A, int lda, const float* W, int ldw,
                        const float* bias, float* C, int ldc, int M, int N, int K){
    int warps = M*N;
    tiny_nt_kernel<<<(warps*32 + 255)/256, 256>>>(A, lda, W, ldw, bias, C, ldc, M, N, K);
}
static void launch_ln4(const float* x, const float* w, const float* bb,
                       float* y, __half* yh, int rows, int tokskip){
    lnw_kernel<4><<<(rows*32 + 255)/256, 256>>>(x, w, bb, y, yh, rows, tokskip);
}

extern "C" void kernel_launch(void* const* d_in, const int* in_sizes, int n_in,
                              void* d_out, int out_size){
    const float* images   = (const float*)d_in[0];
    const float* pe_ln1_w = (const float*)d_in[1];
    const float* pe_ln1_b = (const float*)d_in[2];
    const float* pe_w     = (const float*)d_in[3];
    const float* pe_b     = (const float*)d_in[4];
    const float* pe_ln2_w = (const float*)d_in[5];
    const float* pe_ln2_b = (const float*)d_in[6];
    const float* pos_h    = (const float*)d_in[7];
    const float* pos_w    = (const float*)d_in[8];
    const float* attn_ln  = (const float*)d_in[9];
    const float* wq       = (const float*)d_in[10];
    const float* wk       = (const float*)d_in[11];
    const float* wv       = (const float*)d_in[12];
    const float* qn       = (const float*)d_in[13];
    const float* kn       = (const float*)d_in[14];
    const float* wo       = (const float*)d_in[15];
    const float* ff_ln    = (const float*)d_in[16];
    const float* ff_w1    = (const float*)d_in[17];
    const float* ff_b1    = (const float*)d_in[18];
    const float* ff_w2    = (const float*)d_in[19];
    const float* ff_b2    = (const float*)d_in[20];
    const float* final_ln = (const float*)d_in[21];
    const float* pool_q   = (const float*)d_in[22];
    const float* pool_ln  = (const float*)d_in[23];
    const float* pool_wq  = (const float*)d_in[24];
    const float* pool_wk  = (const float*)d_in[25];
    const float* pool_wv  = (const float*)d_in[26];
    const float* pool_qn  = (const float*)d_in[27];
    const float* pool_kn  = (const float*)d_in[28];
    const float* pool_wo  = (const float*)d_in[29];
    const float* head_ln  = (const float*)d_in[30];
    const float* head_w   = (const float*)d_in[31];
    float* out = (float*)d_out;

    cudaFuncSetAttribute(bgemm_nt, cudaFuncAttributeMaxDynamicSharedMemorySize, B_SMEM);
    cudaFuncSetAttribute(flash_kernel, cudaFuncAttributeMaxDynamicSharedMemorySize, FSMEM);

    float *tok,*t,*qkv,*u,*qp,*po,*pooled,*hn;
    __half *wh,*lt,*xn,*mlp,*o,*qkv16,*qh,*kh,*vh;
    cudaGetSymbolAddress((void**)&tok, g_tok);
    cudaGetSymbolAddress((void**)&t,   g_t);
    cudaGetSymbolAddress((void**)&qkv, g_qkv);
    cudaGetSymbolAddress((void**)&u,   g_u);
    cudaGetSymbolAddress((void**)&qp,  g_qp);
    cudaGetSymbolAddress((void**)&po,  g_po);
    cudaGetSymbolAddress((void**)&pooled, g_pooled);
    cudaGetSymbolAddress((void**)&hn,  g_hn);
    cudaGetSymbolAddress((void**)&wh,  g_wh);
    cudaGetSymbolAddress((void**)&lt,  g_lt);
    cudaGetSymbolAddress((void**)&xn,  g_xn);
    cudaGetSymbolAddress((void**)&mlp, g_mlp);
    cudaGetSymbolAddress((void**)&o,   g_o);
    cudaGetSymbolAddress((void**)&qkv16, g_qkv16);
    cudaGetSymbolAddress((void**)&qh,  g_qh2);
    cudaGetSymbolAddress((void**)&kh,  g_kh2);
    cudaGetSymbolAddress((void**)&vh,  g_vh2);

    float* kf = qkv + (size_t)NTOK*DIM;
    float* vf = qkv + (size_t)2*NTOK*DIM;

    // ---- weight convert: single fused launch ----
    {
        WSrcs ws;
        ws.p[0] = wq;  ws.p[1] = wk;  ws.p[2] = wv;  ws.p[3] = wo;
        ws.p[4] = ff_w1; ws.p[5] = ff_w2; ws.p[6] = pe_w;
        ws.p[7] = pool_wk; ws.p[8] = pool_wv;
        int n4 = (int)(WTOT >> 2);
        wcvt_all_kernel<<<(n4 + 255)/256, 256>>>(ws, wh, n4);
    }

    // ---- patch embed ----
    pack_kernel<<<((size_t)NTOK*PDIM + 255)/256, 256>>>(images, tok);
    lnw_kernel<6><<<(NTOK*32 + 255)/256, 256>>>(tok, pe_ln1_w, pe_ln1_b, nullptr, lt, NTOK, 1);
    launch_bg(lt, PDIM, wh + OFF_PE, PDIM, 0, pe_b,
              nullptr, 0, t, nullptr, DIM, 0, DIM, PDIM, 0, 1, 1);
    ln_pos_kernel<<<(NTOK*32 + 255)/256, 256>>>(t, pe_ln2_w, pe_ln2_b, pos_h, pos_w);

    // ---- transformer layers ----
    for (int l = 0; l < NDEPTH; l++){
        launch_ln4(t, attn_ln + l*DIM, nullptr, nullptr, xn, NTOK, 1);
        launch_bg(xn, DIM, wh + OFF_QKV + (size_t)l*DIM*DIM, DIM, 1572864L,
                  nullptr, nullptr, 0,
                  nullptr, qkv16, DIM, (long)NTOK*DIM, DIM, DIM, 0, 3, 1);
        kvprep_kernel<<<NTOK*HEADS*8/256, 256>>>(qkv16, qn + l*DH, kn + l*DH, qh, kh, vh);
        flash_kernel<<<dim3(8, BB*HEADS), 256, FSMEM>>>(qh, kh, vh, o);
        launch_bg(o, DIM, wh + OFF_WO + (size_t)l*DIM*DIM, DIM, 0,
                  nullptr, t, DIM, t, nullptr, DIM, 0, DIM, DIM, 0, 1, 1);
        launch_ln4(t, ff_ln + l*DIM, nullptr, nullptr, xn, NTOK, 1);
        launch_bg(xn, DIM, wh + OFF_FF1 + (size_t)l*MLPD*DIM, DIM, 0,
                  ff_b1 + l*MLPD, nullptr, 0,
                  nullptr, mlp, MLPD, 0, MLPD, DIM, 1, 1, 1);
        launch_bg(mlp, MLPD, wh + OFF_FF2 + (size_t)l*DIM*MLPD, MLPD, 0,
                  ff_b2 + l*DIM, t, DIM, t, nullptr, DIM, 0, DIM, MLPD, 0, 1, 1);
    }

    // ---- final LN + pooling ----
    launch_ln4(t, final_ln, nullptr, nullptr, xn, NTOK, 1);
    launch_ln4(pool_q, pool_ln, nullptr, u, nullptr, 1, 0);
    launch_tiny(u, DIM, pool_wq, DIM, nullptr, qp, DIM, 1, DIM, DIM);
    head_ln_kernel<<<1, 256>>>(qp, pool_qn, HEADS);
    // pool K and V in one batched GEMM (weights adjacent: OFF_PK then OFF_PV)
    launch_bg(xn, DIM, wh + OFF_PK, DIM, (long)(OFF_PV - OFF_PK), nullptr, nullptr, 0,
              kf, nullptr, DIM, (long)NTOK*DIM, DIM, DIM, 0, 2, 1);
    head_ln_kernel<<<(NTOK*HEADS*32 + 255)/256, 256>>>(kf, pool_kn, NTOK*HEADS);
    pool_attn_kernel<<<dim3(HEADS, BB), 256>>>(qp, kf, vf, po);
    launch_tiny(po, DIM, pool_wo, DIM, nullptr, pooled, DIM, BB, DIM, DIM);
    launch_ln4(pooled, head_ln, nullptr, hn, nullptr, BB, 0);
    launch_tiny(hn, DIM, head_w, DIM, nullptr, out, NC, BB, NC, DIM);
}

// round 15
// speedup vs baseline: 1.1185x; 1.0079x over previous
#include <cuda_runtime.h>
#include <cuda_fp16.h>
#include <math.h>
#include <stdint.h>

#define BB 8
#define LMAX 1024
#define DIM 512
#define HEADS 8
#define DH 64
#define NDEPTH 6
#define MLPD 2048
#define NC 1000
#define PDIM 768
#define NTOK (BB*LMAX)   // 8192

__constant__ int c_L[8]  = {1024, 768, 896, 576, 560, 512, 384, 640};
__constant__ int c_Wp[8] = {  32,  24,  32,  24,  28,  32,  16,  20};

// weight buffer offsets (elements)
#define OFF_QKV 0L
#define OFF_WO  4718592L
#define OFF_FF1 6291456L
#define OFF_FF2 12582912L
#define OFF_PE  18874368L
#define OFF_PK  19267584L
#define OFF_PV  19529728L
#define WTOT    19791872L

// ---------------- scratch ----------------
__device__ __align__(128) float g_tok[(size_t)NTOK*PDIM];
__device__ __align__(128) float g_t  [(size_t)NTOK*DIM];
__device__ __align__(128) float g_qkv[(size_t)3*NTOK*DIM];
__device__ __align__(128) float g_u  [DIM];
__device__ __align__(128) float g_qp [DIM];
__device__ __align__(128) float g_po [BB*DIM];
__device__ __align__(128) float g_pooled[BB*DIM];
__device__ __align__(128) float g_hn [BB*DIM];
__device__ __align__(128) __half g_wh[WTOT];
__device__ __align__(128) __half g_lt [(size_t)NTOK*PDIM];
__device__ __align__(128) __half g_xn [(size_t)NTOK*DIM];
__device__ __align__(128) __half g_mlp[(size_t)NTOK*MLPD];
__device__ __align__(128) __half g_o  [(size_t)NTOK*DIM];
__device__ __align__(128) __half g_qkv16[(size_t)3*NTOK*DIM];
__device__ __align__(128) __half g_qh2[(size_t)NTOK*DIM];
__device__ __align__(128) __half g_kh2[(size_t)NTOK*DIM];
__device__ __align__(128) __half g_vh2[(size_t)NTOK*DIM];

// ================= helpers =================
__device__ __forceinline__ uint32_t smem_u32(const void* p){
    uint32_t a; asm("{ .reg .u64 t; cvta.to.shared.u64 t, %1; cvt.u32.u64 %0, t; }" : "=r"(a) : "l"(p));
    return a;
}
__device__ __forceinline__ void ldsm_x4(uint32_t* r, uint32_t addr){
    asm volatile("ldmatrix.sync.aligned.m8n8.x4.shared.b16 {%0,%1,%2,%3}, [%4];"
        : "=r"(r[0]),"=r"(r[1]),"=r"(r[2]),"=r"(r[3]) : "r"(addr));
}
__device__ __forceinline__ void ldsm_x2(uint32_t* r, uint32_t addr){
    asm volatile("ldmatrix.sync.aligned.m8n8.x2.shared.b16 {%0,%1}, [%2];"
        : "=r"(r[0]),"=r"(r[1]) : "r"(addr));
}
__device__ __forceinline__ void ldsm_x2t(uint32_t* r, uint32_t addr){
    asm volatile("ldmatrix.sync.aligned.m8n8.x2.trans.shared.b16 {%0,%1}, [%2];"
        : "=r"(r[0]),"=r"(r[1]) : "r"(addr));
}
__device__ __forceinline__ void mma16816(float* c, const uint32_t* a, const uint32_t* b){
    asm volatile("mma.sync.aligned.m16n8k16.row.col.f32.f16.f16.f32 "
        "{%0,%1,%2,%3}, {%4,%5,%6,%7}, {%8,%9}, {%0,%1,%2,%3};"
        : "+f"(c[0]),"+f"(c[1]),"+f"(c[2]),"+f"(c[3])
        : "r"(a[0]),"r"(a[1]),"r"(a[2]),"r"(a[3]), "r"(b[0]),"r"(b[1]));
}
__device__ __forceinline__ void cp_async16(uint32_t dst, const void* src){
    asm volatile("cp.async.cg.shared.global [%0], [%1], 16;" :: "r"(dst), "l"(src) : "memory");
}
__device__ __forceinline__ void cp_commit(){ asm volatile("cp.async.commit_group;" ::: "memory"); }
template<int N> __device__ __forceinline__ void cp_wait(){
    asm volatile("cp.async.wait_group %0;" :: "n"(N) : "memory");
}
__device__ __forceinline__ uint32_t h2u(__half2 v){ return *reinterpret_cast<uint32_t*>(&v); }
__device__ __forceinline__ uint32_t packh(float a, float b){
    return h2u(__float22half2_rn(make_float2(a, b)));
}
__device__ __forceinline__ uint4 cvt8s(float4 a, float4 b){
    return make_uint4(packh(a.x, a.y), packh(a.z, a.w), packh(b.x, b.y), packh(b.z, b.w));
}

// ---------------- fused weight convert: all 9 regions in one kernel ----------------
struct WSrcs { const float* p[9]; };
__constant__ long c_wbase4[10] = {0L, 393216L, 786432L, 1179648L, 1572864L,
                                  3145728L, 4718592L, 4816896L, 4882432L, 4947968L};
__global__ void wcvt_all_kernel(WSrcs srcs, __half* __restrict__ h, int n4){
    int i = blockIdx.x*blockDim.x + threadIdx.x;
    if (i >= n4) return;
    int r = 0;
    #pragma unroll
    for (int j = 1; j < 9; j++) if (i >= (int)c_wbase4[j]) r = j;
    float4 v = ((const float4*)srcs.p[r])[i - (int)c_wbase4[r]];
    ((uint2*)h)[i] = make_uint2(packh(v.x, v.y), packh(v.z, v.w));
}

// ============== cp.async HMMA GEMM NT (128x128 tile, 2-stage, 1 sync/iter) ==============
#define BTILE (128*144)          // 18432
#define B_A  0
#define B_W  BTILE
#define B_BUF (2*BTILE)          // 36864
#define B_SMEM (2*B_BUF)         // 73728

__global__ __launch_bounds__(256, 2) void bgemm_nt(
    const __half* __restrict__ A, int lda,
    const __half* __restrict__ W, int ldw, long wz,
    const float* __restrict__ bias,
    const float* __restrict__ R, int ldr,
    float* __restrict__ C, __half* __restrict__ Ch,
    int ldc, long cz,
    int K, int act, int tokrows)
{
    extern __shared__ char smem[];
    uint32_t sb = smem_u32(smem);
    int tid = threadIdx.x, lane = tid & 31, wid = tid >> 5;
    int z = blockIdx.z;
    W += (size_t)z*wz;
    if (C)  C  += (size_t)z*cz;
    if (Ch) Ch += (size_t)z*cz;
    int bm = blockIdx.y*128, bn = blockIdx.x*128;
    if (tokrows && (bm & 1023) >= c_L[bm >> 10]) return;
    int wr = (wid & 1)*64;
    int wn = (wid >> 1)*32;

    float acc[4][4][4];
    #pragma unroll
    for (int i = 0; i < 4; i++)
        #pragma unroll
        for (int j = 0; j < 4; j++)
            #pragma unroll
            for (int p = 0; p < 4; p++) acc[i][j][p] = 0.f;

#define BSTAGE(KC, BUFB) do { \
    _Pragma("unroll") \
    for (int it = 0; it < 4; it++){ \
        int slot = it*256 + tid; int row = slot >> 3, seg = slot & 7; \
        uint32_t so = (uint32_t)(BUFB) + (uint32_t)(row*144 + seg*16); \
        cp_async16(sb + B_A + so, A + (size_t)(bm + row)*lda + (KC)*64 + seg*8); \
        cp_async16(sb + B_W + so, W + (size_t)(bn + row)*ldw + (KC)*64 + seg*8); \
    } } while(0)

    int nk = K >> 6;
    BSTAGE(0, 0);
    cp_commit();

    int grp = lane >> 3, wi = lane & 7;
    for (int kc = 0; kc < nk; kc++){
        cp_wait<0>();          // chunk kc resident
        __syncthreads();       // also: all warps done reading buffer (kc+1)&1 from iter kc-1
        if (kc + 1 < nk){
            BSTAGE(kc + 1, ((kc + 1) & 1)*B_BUF);
            cp_commit();
        }
        uint32_t cur = (uint32_t)((kc & 1)*B_BUF);
        #pragma unroll
        for (int ks = 0; ks < 4; ks++){
            uint32_t a_f[4][4];
            #pragma unroll
            for (int mi = 0; mi < 4; mi++){
                uint32_t off = (uint32_t)((wr + mi*16 + wi + (grp & 1)*8)*144
                                          + (ks*16 + (grp >> 1)*8)*2);
                ldsm_x4(a_f[mi], sb + B_A + cur + off);
            }
            uint32_t b_f[4][2];
            #pragma unroll
            for (int ni = 0; ni < 4; ni++){
                uint32_t off = (uint32_t)((wn + ni*8 + (lane & 7))*144
                                          + (ks*16 + ((lane >> 3) & 1)*8)*2);
                ldsm_x2(b_f[ni], sb + B_W + cur + off);
            }
            #pragma unroll
            for (int mi = 0; mi < 4; mi++)
                #pragma unroll
                for (int ni = 0; ni < 4; ni++)
                    mma16816(acc[mi][ni], a_f[mi], b_f[ni]);
        }
    }
#undef BSTAGE

    // ---- epilogue ----
    #pragma unroll
    for (int mi = 0; mi < 4; mi++){
        #pragma unroll
        for (int ni = 0; ni < 4; ni++){
            int gn = bn + wn + ni*8 + (lane & 3)*2;
            #pragma unroll
            for (int hh = 0; hh < 2; hh++){
                int m = bm + wr + mi*16 + (lane >> 2) + hh*8;
                float v0 = acc[mi][ni][hh*2 + 0];
                float v1 = acc[mi][ni][hh*2 + 1];
                if (bias){ v0 += bias[gn]; v1 += bias[gn + 1]; }
                if (act){
                    v0 = 0.5f*v0*(1.f + erff(v0*0.70710678118654752f));
                    v1 = 0.5f*v1*(1.f + erff(v1*0.70710678118654752f));
                }
                if (Ch){
                    *(uint32_t*)(Ch + (size_t)m*ldc + gn) = packh(v0, v1);
                } else {
                    if (R){
                        const float* rp = R + (size_t)m*ldr + gn;
                        v0 += rp[0]; v1 += rp[1];
                    }
                    *(float2*)(C + (size_t)m*ldc + gn) = make_float2(v0, v1);
                }
            }
        }
    }
}

// ============== kvprep: reads fp16 qkv; head-LN(Q x 1/8, K); writes fp16 ==============
__global__ void kvprep_kernel(const __half* __restrict__ qkv,
    const float* __restrict__ qn, const float* __restrict__ kn,
    __half* __restrict__ qh, __half* __restrict__ kh, __half* __restrict__ vh)
{
    int g = blockIdx.x*blockDim.x + threadIdx.x;   // NTOK*HEADS*8
    int seg = g & 7;
    int r = g >> 3;
    int tokn = r >> 3, h = r & 7;
    int b = tokn >> 10, l = tokn & 1023;
    if (l >= c_L[b]) return;
    size_t base = (size_t)tokn*DIM + h*64 + seg*8;

#define LD8H(P, X, Y) do { \
    uint4 raw = *(const uint4*)(P); \
    float2 f0 = __half22float2(*reinterpret_cast<__half2*>(&raw.x)); \
    float2 f1 = __half22float2(*reinterpret_cast<__half2*>(&raw.y)); \
    float2 f2 = __half22float2(*reinterpret_cast<__half2*>(&raw.z)); \
    float2 f3 = __half22float2(*reinterpret_cast<__half2*>(&raw.w)); \
    X = make_float4(f0.x, f0.y, f1.x, f1.y); \
    Y = make_float4(f2.x, f2.y, f3.x, f3.y); \
} while(0)

#define LN8(x, y, wvec, scale) do { \
    float sum = x.x + x.y + x.z + x.w + y.x + y.y + y.z + y.w; \
    sum += __shfl_xor_sync(0xffffffffu, sum, 1); \
    sum += __shfl_xor_sync(0xffffffffu, sum, 2); \
    sum += __shfl_xor_sync(0xffffffffu, sum, 4); \
    float mu = sum * (1.f/64.f); \
    x.x -= mu; x.y -= mu; x.z -= mu; x.w -= mu; \
    y.x -= mu; y.y -= mu; y.z -= mu; y.w -= mu; \
    float ss = x.x*x.x + x.y*x.y + x.z*x.z + x.w*x.w \
             + y.x*y.x + y.y*y.y + y.z*y.z + y.w*y.w; \
    ss += __shfl_xor_sync(0xffffffffu, ss, 1); \
    ss += __shfl_xor_sync(0xffffffffu, ss, 2); \
    ss += __shfl_xor_sync(0xffffffffu, ss, 4); \
    float rs = rsqrtf(ss * (1.f/64.f) + 1e-5f) * (scale); \
    float4 w0 = *(const float4*)((wvec) + seg*8); \
    float4 w1 = *(const float4*)((wvec) + seg*8 + 4); \
    x.x *= rs*w0.x; x.y *= rs*w0.y; x.z *= rs*w0.z; x.w *= rs*w0.w; \
    y.x *= rs*w1.x; y.y *= rs*w1.y; y.z *= rs*w1.z; y.w *= rs*w1.w; \
} while(0)

    {   // Q
        float4 x, y; LD8H(qkv + base, x, y);
        LN8(x, y, qn, 0.125f);
        *(uint4*)(qh + base) = cvt8s(x, y);
    }
    {   // K
        float4 x, y; LD8H(qkv + (size_t)NTOK*DIM + base, x, y);
        LN8(x, y, kn, 1.f);
        *(uint4*)(kh + base) = cvt8s(x, y);
    }
    {   // V (straight copy, already fp16)
        *(uint4*)(vh + base) = *(const uint4*)(qkv + (size_t)2*NTOK*DIM + base);
    }
#undef LN8
#undef LD8H
}

// ============== flash attention: pure fp16, cp.async double-buffered, 1 sync/iter ==============
#define FQ 0
#define FKV0 18432
#define FKVS 36864
#define FSMEM (18432 + 2*36864)          // 92160

__global__ __launch_bounds__(256, 2) void flash_kernel(
    const __half* __restrict__ Qh,
    const __half* __restrict__ Kh,
    const __half* __restrict__ Vh,
    __half* __restrict__ O)
{
    extern __shared__ char smem[];
    uint32_t sb = smem_u32(smem);
    int tid = threadIdx.x, lane = tid & 31, wid = tid >> 5;
    int qt = blockIdx.x;
    int bh = blockIdx.y;
    int b = bh >> 3, h = bh & 7;
    int L = c_L[b];
    if (qt*128 >= L) return;
    int ktiles = (L + 127) >> 7;

    // ---- stage Q + KV0 ----
    #pragma unroll
    for (int it = 0; it < 4; it++){
        int slot = it*256 + tid; int row = slot >> 3, seg = slot & 7;
        size_t go = (size_t)(b*1024 + qt*128 + row)*DIM + h*64 + seg*8;
        cp_async16(sb + FQ + (uint32_t)(row*144 + seg*16), Qh + go);
    }
    cp_commit();

#define KVSTAGE(KT, SBASE) do { \
    _Pragma("unroll") \
    for (int it = 0; it < 4; it++){ \
        int slot = it*256 + tid; int row = slot >> 3, seg = slot & 7; \
        size_t go = (size_t)(b*1024 + (KT)*128 + row)*DIM + h*64 + seg*8; \
        uint32_t so = (uint32_t)(SBASE) + (uint32_t)(row*144 + seg*16); \
        cp_async16(sb + so,         Kh + go); \
        cp_async16(sb + so + 18432, Vh + go); \
    } } while(0)

    KVSTAGE(0, FKV0);
    cp_commit();

    cp_wait<1>();          // Q resident
    __syncthreads();

    int wr = wid*16;
    int grp = lane >> 3, wi = lane & 7;
    uint32_t aq[4][4];
    #pragma unroll
    for (int ks = 0; ks < 4; ks++){
        uint32_t off = (uint32_t)((wr + wi + (grp & 1)*8)*144 + (ks*16 + (grp >> 1)*8)*2);
        ldsm_x4(aq[ks], sb + FQ + off);
    }

    float m0 = -1e30f, m1 = -1e30f, l0 = 0.f, l1 = 0.f;
    float ao[8][4];
    #pragma unroll
    for (int i = 0; i < 8; i++)
        #pragma unroll
        for (int p = 0; p < 4; p++) ao[i][p] = 0.f;

    for (int kt = 0; kt < ktiles; kt++){
        cp_wait<0>();          // KV chunk kt resident
        __syncthreads();       // all warps done reading buffer (kt+1)&1 from iter kt-1
        if (kt + 1 < ktiles){
            KVSTAGE(kt + 1, FKV0 + ((kt + 1) & 1)*FKVS);
            cp_commit();
        }
        uint32_t kb = (uint32_t)(FKV0 + (kt & 1)*FKVS);

        // ---- S = Q K^T ----
        float s[16][4];
        #pragma unroll
        for (int i = 0; i < 16; i++)
            #pragma unroll
            for (int p = 0; p < 4; p++) s[i][p] = 0.f;
        #pragma unroll
        for (int ks = 0; ks < 4; ks++){
            #pragma unroll
            for (int ni = 0; ni < 16; ni++){
                uint32_t off = (uint32_t)((ni*8 + wi)*144 + (ks*16 + (grp & 1)*8)*2);
                uint32_t b_[2];
                ldsm_x2(b_, sb + kb + off);
                mma16816(s[ni], aq[ks], b_);
            }
        }

        // ---- mask (partial tile only) ----
        if (kt == ktiles - 1 && (L & 127)){
            int kbase = kt*128 + 2*(lane & 3);
            #pragma unroll
            for (int ni = 0; ni < 16; ni++){
                int kg = kbase + ni*8;
                if (kg     >= L){ s[ni][0] = -1e9f; s[ni][2] = -1e9f; }
                if (kg + 1 >= L){ s[ni][1] = -1e9f; s[ni][3] = -1e9f; }
            }
        }

        // ---- online softmax ----
        float tm0 = -1e30f, tm1 = -1e30f;
        #pragma unroll
        for (int ni = 0; ni < 16; ni++){
            tm0 = fmaxf(tm0, fmaxf(s[ni][0], s[ni][1]));
            tm1 = fmaxf(tm1, fmaxf(s[ni][2], s[ni][3]));
        }
        tm0 = fmaxf(tm0, __shfl_xor_sync(0xffffffffu, tm0, 1));
        tm0 = fmaxf(tm0, __shfl_xor_sync(0xffffffffu, tm0, 2));
        tm1 = fmaxf(tm1, __shfl_xor_sync(0xffffffffu, tm1, 1));
        tm1 = fmaxf(tm1, __shfl_xor_sync(0xffffffffu, tm1, 2));
        float mn0 = fmaxf(m0, tm0), mn1 = fmaxf(m1, tm1);
        float sc0 = __expf(m0 - mn0), sc1 = __expf(m1 - mn1);
        m0 = mn0; m1 = mn1;
        float ts0 = 0.f, ts1 = 0.f;
        #pragma unroll
        for (int ni = 0; ni < 16; ni++){
            s[ni][0] = __expf(s[ni][0] - m0);
            s[ni][1] = __expf(s[ni][1] - m0);
            s[ni][2] = __expf(s[ni][2] - m1);
            s[ni][3] = __expf(s[ni][3] - m1);
            ts0 += s[ni][0] + s[ni][1];
            ts1 += s[ni][2] + s[ni][3];
        }
        ts0 += __shfl_xor_sync(0xffffffffu, ts0, 1);
        ts0 += __shfl_xor_sync(0xffffffffu, ts0, 2);
        ts1 += __shfl_xor_sync(0xffffffffu, ts1, 1);
        ts1 += __shfl_xor_sync(0xffffffffu, ts1, 2);
        l0 = l0*sc0 + ts0;
        l1 = l1*sc1 + ts1;
        #pragma unroll
        for (int i = 0; i < 8; i++){
            ao[i][0] *= sc0; ao[i][1] *= sc0;
            ao[i][2] *= sc1; ao[i][3] *= sc1;
        }

        // ---- O += P V ----
        #pragma unroll
        for (int kk = 0; kk < 8; kk++){
            uint32_t ap[4];
            ap[0] = packh(s[2*kk][0],   s[2*kk][1]);
            ap[1] = packh(s[2*kk][2],   s[2*kk][3]);
            ap[2] = packh(s[2*kk+1][0], s[2*kk+1][1]);
            ap[3] = packh(s[2*kk+1][2], s[2*kk+1][3]);
            #pragma unroll
            for (int ni = 0; ni < 8; ni++){
                uint32_t off = (uint32_t)((kk*16 + (lane & 15))*144 + ni*16);
                uint32_t v_[2];
                ldsm_x2t(v_, sb + kb + 18432 + off);
                mma16816(ao[ni], ap, v_);
            }
        }
    }
#undef KVSTAGE

    // ---- epilogue: fp16 O ----
    float il0 = 1.f / l0, il1 = 1.f / l1;
    int mrow = qt*128 + wr + (lane >> 2);
    #pragma unroll
    for (int ni = 0; ni < 8; ni++){
        int col = h*64 + ni*8 + 2*(lane & 3);
        *(uint32_t*)(O + (size_t)(b*1024 + mrow)*DIM + col)     = packh(ao[ni][0]*il0, ao[ni][1]*il0);
        *(uint32_t*)(O + (size_t)(b*1024 + mrow + 8)*DIM + col) = packh(ao[ni][2]*il1, ao[ni][3]*il1);
    }
}

// ---------------- patch packing ----------------
__global__ void pack_kernel(const float* __restrict__ img, float* __restrict__ tok){
    size_t i = (size_t)blockIdx.x*blockDim.x + threadIdx.x;
    if (i >= (size_t)NTOK*PDIM) return;
    int pd = (int)(i % PDIM);
    size_t bl = i / PDIM;
    int l = (int)(bl % LMAX);
    int b = (int)(bl / LMAX);
    int L = c_L[b], w = c_Wp[b];
    float v = 0.f;
    if (l < L){
        int c  = pd >> 8;
        int r  = pd & 255;
        int py = r >> 4, px = r & 15;
        int ph = l / w, pw = l % w;
        v = img[((size_t)(b*3 + c)*512 + (size_t)(ph*16 + py))*512 + (size_t)(pw*16 + px)];
    }
    tok[i] = v;
}

// ---------------- warp-per-row LayerNorm (D = NV*128); writes f32 (y) or fp16 (yh) ----------------
template<int NV>
__global__ void lnw_kernel(const float* __restrict__ x, const float* __restrict__ w,
                           const float* __restrict__ bb, float* __restrict__ y,
                           __half* __restrict__ yh, int rows, int tokskip){
    int gw = (int)(((size_t)blockIdx.x*blockDim.x + threadIdx.x) >> 5);
    int lane = threadIdx.x & 31;
    if (gw >= rows) return;
    if (tokskip && (gw & 1023) >= c_L[gw >> 10]) return;
    const int D = NV*128;
    const float* xr = x + (size_t)gw*D;
    float4 v[NV];
    float s = 0.f;
    #pragma unroll
    for (int i = 0; i < NV; i++){
        v[i] = *(const float4*)(xr + i*128 + lane*4);
        s += v[i].x + v[i].y + v[i].z + v[i].w;
    }
    #pragma unroll
    for (int off = 16; off; off >>= 1) s += __shfl_xor_sync(0xffffffffu, s, off);
    float mu = s / (float)D;
    float vs = 0.f;
    #pragma unroll
    for (int i = 0; i < NV; i++){
        float a = v[i].x - mu, b = v[i].y - mu, c = v[i].z - mu, d = v[i].w - mu;
        vs += a*a + b*b + c*c + d*d;
    }
    #pragma unroll
    for (int off = 16; off; off >>= 1) vs += __shfl_xor_sync(0xffffffffu, vs, off);
    float rs = rsqrtf(vs / (float)D + 1e-5f);
    #pragma unroll
    for (int i = 0; i < NV; i++){
        int idx = i*128 + lane*4;
        float4 w4 = *(const float4*)(w + idx);
        float4 o;
        o.x = (v[i].x - mu)*rs*w4.x;
        o.y = (v[i].y - mu)*rs*w4.y;
        o.z = (v[i].z - mu)*rs*w4.z;
        o.w = (v[i].w - mu)*rs*w4.w;
        if (bb){
            float4 b4 = *(const float4*)(bb + idx);
            o.x += b4.x; o.y += b4.y; o.z += b4.z; o.w += b4.w;
        }
        if (y) *(float4*)(y + (size_t)gw*D + idx) = o;
        else   *(uint2*)(yh + (size_t)gw*D + idx) = make_uint2(packh(o.x, o.y), packh(o.z, o.w));
    }
}

// ---------------- fused LN + pos-embed + mask (D=512, in-place on t), warp per row ----------------
__global__ void ln_pos_kernel(float* __restrict__ t, const float* __restrict__ w,
                              const float* __restrict__ bb,
                              const float* __restrict__ ph, const float* __restrict__ pw){
    int gw = (int)(((size_t)blockIdx.x*blockDim.x + threadIdx.x) >> 5);
    int lane = threadIdx.x & 31;
    if (gw >= NTOK) return;
    int b = gw >> 10, l = gw & 1023;
    int L = c_L[b], wgrid = c_Wp[b];
    float* tr = t + (size_t)gw*DIM;
    if (l >= L){
        #pragma unroll
        for (int i = 0; i < 4; i++)
            *(float4*)(tr + i*128 + lane*4) = make_float4(0,0,0,0);
        return;
    }
    float4 v[4];
    float s = 0.f;
    #pragma unroll
    for (int i = 0; i < 4; i++){
        v[i] = *(const float4*)(tr + i*128 + lane*4);
        s += v[i].x + v[i].y + v[i].z + v[i].w;
    }
    #pragma unroll
    for (int off = 16; off; off >>= 1) s += __shfl_xor_sync(0xffffffffu, s, off);
    float mu = s / (float)DIM;
    float vs = 0.f;
    #pragma unroll
    for (int i = 0; i < 4; i++){
        float a = v[i].x - mu, b2 = v[i].y - mu, c = v[i].z - mu, d = v[i].w - mu;
        vs += a*a + b2*b2 + c*c + d*d;
    }
    #pragma unroll
    for (int off = 16; off; off >>= 1) vs += __shfl_xor_sync(0xffffffffu, vs, off);
    float rs = rsqrtf(vs / (float)DIM + 1e-5f);
    const float* p0r = ph + (size_t)(l / wgrid)*DIM;
    const float* p1r = pw + (size_t)(l % wgrid)*DIM;
    #pragma unroll
    for (int i = 0; i < 4; i++){
        int idx = i*128 + lane*4;
        float4 w4 = *(const float4*)(w + idx);
        float4 b4 = *(const float4*)(bb + idx);
        float4 p0 = *(const float4*)(p0r + idx);
        float4 p1 = *(const float4*)(p1r + idx);
        float4 o;
        o.x = (v[i].x - mu)*rs*w4.x + b4.x + p0.x + p1.x;
        o.y = (v[i].y - mu)*rs*w4.y + b4.y + p0.y + p1.y;
        o.z = (v[i].z - mu)*rs*w4.z + b4.z + p0.z + p1.z;
        o.w = (v[i].w - mu)*rs*w4.w + b4.w + p0.w + p1.w;
        *(float4*)(tr + idx) = o;
    }
}

// ---------------- per-head LayerNorm over 64 dims (pool path) ----------------
__global__ void head_ln_kernel(float* __restrict__ x, const float* __restrict__ w, int rows){
    int gw = (int)(((size_t)blockIdx.x*blockDim.x + threadIdx.x) >> 5);
    int lane = threadIdx.x & 31;
    if (gw >= rows) return;
    float* p = x + (size_t)gw*64;
    float a = p[lane], b = p[lane + 32];
    float s = a + b;
    #pragma unroll
    for (int off = 16; off; off >>= 1) s += __shfl_xor_sync(0xffffffffu, s, off);
    float mu = s * (1.f/64.f);
    float da = a - mu, db = b - mu;
    float vs = da*da + db*db;
    #pragma unroll
    for (int off = 16; off; off >>= 1) vs += __shfl_xor_sync(0xffffffffu, vs, off);
    float rs = rsqrtf(vs * (1.f/64.f) + 1e-5f);
    p[lane]      = da * rs * w[lane];
    p[lane + 32] = db * rs * w[lane + 32];
}

// ---------------- tiny GEMM NT: warp per output element (small M) ----------------
__global__ void tiny_nt_kernel(const float* __restrict__ A, int lda,
                               const float* __restrict__ W, int ldw,
                               const float* __restrict__ bias,
                               float* __restrict__ C, int ldc,
                               int M, int N, int K){
    int gw = (int)(((size_t)blockIdx.x*blockDim.x + threadIdx.x) >> 5);
    int lane = threadIdx.x & 31;
    if (gw >= M*N) return;
    int m = gw / N, n = gw % N;
    const float* a = A + (size_t)m*lda;
    const float* wv = W + (size_t)n*ldw;
    float s = 0.f;
    for (int k = lane*4; k < K; k += 128){
        float4 av = *(const float4*)(a + k);
        float4 bv = *(const float4*)(wv + k);
        s += av.x*bv.x + av.y*bv.y + av.z*bv.z + av.w*bv.w;
    }
    #pragma unroll
    for (int off = 16; off; off >>= 1) s += __shfl_xor_sync(0xffffffffu, s, off);
    if (lane == 0){
        if (bias) s += bias[n];
        C[(size_t)m*ldc + n] = s;
    }
}

// ---------------- pooling attention (Lq=1) ----------------
__global__ void pool_attn_kernel(const float* __restrict__ qhat, const float* __restrict__ K,
                                 const float* __restrict__ V, float* __restrict__ O){
    int h = blockIdx.x, b = blockIdx.y;
    __shared__ float sq[64];
    __shared__ float sa[1024];
    __shared__ float red[8], red2[8];
    __shared__ float racc[4][64];
    int tid = threadIdx.x, lane = tid & 31, wp = tid >> 5;
    if (tid < 64) sq[tid] = qhat[h*64 + tid];
    __syncthreads();
    int L = c_L[b];
    for (int kk = tid; kk < 1024; kk += 256){
        float dot = -1e9f;
        if (kk < L){
            const float* kr = K + ((size_t)(b*1024 + kk))*DIM + h*64;
            float ss = 0.f;
            #pragma unroll
            for (int d = 0; d < 64; d++) ss += sq[d]*kr[d];
            dot = ss*0.125f;
        }
        sa[kk] = dot;
    }
    __syncthreads();
    float m = -1e30f;
    for (int kk = tid; kk < 1024; kk += 256) m = fmaxf(m, sa[kk]);
    #pragma unroll
    for (int off = 16; off; off >>= 1) m = fmaxf(m, __shfl_xor_sync(0xffffffffu, m, off));
    if (lane == 0) red[wp] = m;
    __syncthreads();
    float bm = -1e30f;
    #pragma unroll
    for (int i = 0; i < 8; i++) bm = fmaxf(bm, red[i]);
    float sum = 0.f;
    for (int kk = tid; kk < 1024; kk += 256){
        float e = __expf(sa[kk] - bm);
        sa[kk] = e; sum += e;
    }
    #pragma unroll
    for (int off = 16; off; off >>= 1) sum += __shfl_xor_sync(0xffffffffu, sum, off);
    if (lane == 0) red2[wp] = sum;
    __syncthreads();
    float bs = 0.f;
    #pragma unroll
    for (int i = 0; i < 8; i++) bs += red2[i];
    float inv = 1.f / bs;
    int dd = tid & 63, part = tid >> 6;
    float acc = 0.f;
    for (int kk = part; kk < 1024; kk += 4)
        acc += sa[kk] * V[((size_t)(b*1024 + kk))*DIM + h*64 + dd];
    racc[part][dd] = acc;
    __syncthreads();
    if (part == 0)
        O[b*DIM + h*64 + dd] = (racc[0][dd] + racc[1][dd] + racc[2][dd] + racc[3][dd]) * inv;
}

// ---------------- host helpers ----------------
static void launch_bg(const __half* A, int lda,
                      const __half* W, int ldw, long wz,
                      const float* bias, const float* R, int ldr,
                      float* C, __half* Ch, int ldc, long cz,
                      int N, int K, int act, int nz, int tokrows){
    dim3 g(N/128, NTOK/128, nz);
    bgemm_nt<<<g, 256, B_SMEM>>>(A, lda, W, ldw, wz, bias, R, ldr,
                                 C, Ch, ldc, cz, K, act, tokrows);
}
static void launch_tiny(const float* A, int lda, const float* W, int ldw,
                        const float* bias, float* C, int ldc, int M, int N, int K){
    int warps = M*N;
    tiny_nt_kernel<<<(warps*32 + 255)/256, 256>>>(A, lda, W, ldw, bias, C, ldc, M, N, K);
}
static void launch_ln4(const float* x, const float* w, const float* bb,
                       float* y, __half* yh, int rows, int tokskip){
    lnw_kernel<4><<<(rows*32 + 255)/256, 256>>>(x, w, bb, y, yh, rows, tokskip);
}

extern "C" void kernel_launch(void* const* d_in, const int* in_sizes, int n_in,
                              void* d_out, int out_size){
    const float* images   = (const float*)d_in[0];
    const float* pe_ln1_w = (const float*)d_in[1];
    const float* pe_ln1_b = (const float*)d_in[2];
    const float* pe_w     = (const float*)d_in[3];
    const float* pe_b     = (const float*)d_in[4];
    const float* pe_ln2_w = (const float*)d_in[5];
    const float* pe_ln2_b = (const float*)d_in[6];
    const float* pos_h    = (const float*)d_in[7];
    const float* pos_w    = (const float*)d_in[8];
    const float* attn_ln  = (const float*)d_in[9];
    const float* wq       = (const float*)d_in[10];
    const float* wk       = (const float*)d_in[11];
    const float* wv       = (const float*)d_in[12];
    const float* qn       = (const float*)d_in[13];
    const float* kn       = (const float*)d_in[14];
    const float* wo       = (const float*)d_in[15];
    const float* ff_ln    = (const float*)d_in[16];
    const float* ff_w1    = (const float*)d_in[17];
    const float* ff_b1    = (const float*)d_in[18];
    const float* ff_w2    = (const float*)d_in[19];
    const float* ff_b2    = (const float*)d_in[20];
    const float* final_ln = (const float*)d_in[21];
    const float* pool_q   = (const float*)d_in[22];
    const float* pool_ln  = (const float*)d_in[23];
    const float* pool_wq  = (const float*)d_in[24];
    const float* pool_wk  = (const float*)d_in[25];
    const float* pool_wv  = (const float*)d_in[26];
    const float* pool_qn  = (const float*)d_in[27];
    const float* pool_kn  = (const float*)d_in[28];
    const float* pool_wo  = (const float*)d_in[29];
    const float* head_ln  = (const float*)d_in[30];
    const float* head_w   = (const float*)d_in[31];
    float* out = (float*)d_out;

    cudaFuncSetAttribute(bgemm_nt, cudaFuncAttributeMaxDynamicSharedMemorySize, B_SMEM);
    cudaFuncSetAttribute(flash_kernel, cudaFuncAttributeMaxDynamicSharedMemorySize, FSMEM);

    float *tok,*t,*qkv,*u,*qp,*po,*pooled,*hn;
    __half *wh,*lt,*xn,*mlp,*o,*qkv16,*qh,*kh,*vh;
    cudaGetSymbolAddress((void**)&tok, g_tok);
    cudaGetSymbolAddress((void**)&t,   g_t);
    cudaGetSymbolAddress((void**)&qkv, g_qkv);
    cudaGetSymbolAddress((void**)&u,   g_u);
    cudaGetSymbolAddress((void**)&qp,  g_qp);
    cudaGetSymbolAddress((void**)&po,  g_po);
    cudaGetSymbolAddress((void**)&pooled, g_pooled);
    cudaGetSymbolAddress((void**)&hn,  g_hn);
    cudaGetSymbolAddress((void**)&wh,  g_wh);
    cudaGetSymbolAddress((void**)&lt,  g_lt);
    cudaGetSymbolAddress((void**)&xn,  g_xn);
    cudaGetSymbolAddress((void**)&mlp, g_mlp);
    cudaGetSymbolAddress((void**)&o,   g_o);
    cudaGetSymbolAddress((void**)&qkv16, g_qkv16);
    cudaGetSymbolAddress((void**)&qh,  g_qh2);
    cudaGetSymbolAddress((void**)&kh,  g_kh2);
    cudaGetSymbolAddress((void**)&vh,  g_vh2);

    float* kf = qkv + (size_t)NTOK*DIM;
    float* vf = qkv + (size_t)2*NTOK*DIM;

    // ---- weight convert: single fused launch ----
    {
        WSrcs ws;
        ws.p[0] = wq;  ws.p[1] = wk;  ws.p[2] = wv;  ws.p[3] = wo;
        ws.p[4] = ff_w1; ws.p[5] = ff_w2; ws.p[6] = pe_w;
        ws.p[7] = pool_wk; ws.p[8] = pool_wv;
        int n4 = (int)(WTOT >> 2);
        wcvt_all_kernel<<<(n4 + 255)/256, 256>>>(ws, wh, n4);
    }

    // ---- patch embed ----
    pack_kernel<<<((size_t)NTOK*PDIM + 255)/256, 256>>>(images, tok);
    lnw_kernel<6><<<(NTOK*32 + 255)/256, 256>>>(tok, pe_ln1_w, pe_ln1_b, nullptr, lt, NTOK, 1);
    launch_bg(lt, PDIM, wh + OFF_PE, PDIM, 0, pe_b,
              nullptr, 0, t, nullptr, DIM, 0, DIM, PDIM, 0, 1, 1);
    ln_pos_kernel<<<(NTOK*32 + 255)/256, 256>>>(t, pe_ln2_w, pe_ln2_b, pos_h, pos_w);

    // ---- transformer layers ----
    for (int l = 0; l < NDEPTH; l++){
        launch_ln4(t, attn_ln + l*DIM, nullptr, nullptr, xn, NTOK, 1);
        launch_bg(xn, DIM, wh + OFF_QKV + (size_t)l*DIM*DIM, DIM, 1572864L,
                  nullptr, nullptr, 0,
                  nullptr, qkv16, DIM, (long)NTOK*DIM, DIM, DIM, 0, 3, 1);
        kvprep_kernel<<<NTOK*HEADS*8/256, 256>>>(qkv16, qn + l*DH, kn + l*DH, qh, kh, vh);
        flash_kernel<<<dim3(8, BB*HEADS), 256, FSMEM>>>(qh, kh, vh, o);
        launch_bg(o, DIM, wh + OFF_WO + (size_t)l*DIM*DIM, DIM, 0,
                  nullptr, t, DIM, t, nullptr, DIM, 0, DIM, DIM, 0, 1, 1);
        launch_ln4(t, ff_ln + l*DIM, nullptr, nullptr, xn, NTOK, 1);
        launch_bg(xn, DIM, wh + OFF_FF1 + (size_t)l*MLPD*DIM, DIM, 0,
                  ff_b1 + l*MLPD, nullptr, 0,
                  nullptr, mlp, MLPD, 0, MLPD, DIM, 1, 1, 1);
        launch_bg(mlp, MLPD, wh + OFF_FF2 + (size_t)l*DIM*MLPD, MLPD, 0,
                  ff_b2 + l*DIM, t, DIM, t, nullptr, DIM, 0, DIM, MLPD, 0, 1, 1);
    }

    // ---- final LN + pooling ----
    launch_ln4(t, final_ln, nullptr, nullptr, xn, NTOK, 1);
    launch_ln4(pool_q, pool_ln, nullptr, u, nullptr, 1, 0);
    launch_tiny(u, DIM, pool_wq, DIM, nullptr, qp, DIM, 1, DIM, DIM);
    head_ln_kernel<<<1, 256>>>(qp, pool_qn, HEADS);
    // pool K and V in one batched GEMM (weights adjacent: OFF_PK then OFF_PV)
    launch_bg(xn, DIM, wh + OFF_PK, DIM, (long)(OFF_PV - OFF_PK), nullptr, nullptr, 0,
              kf, nullptr, DIM, (long)NTOK*DIM, DIM, DIM, 0, 2, 1);
    head_ln_kernel<<<(NTOK*HEADS*32 + 255)/256, 256>>>(kf, pool_kn, NTOK*HEADS);
    pool_attn_kernel<<<dim3(HEADS, BB), 256>>>(qp, kf, vf, po);
    launch_tiny(po, DIM, pool_wo, DIM, nullptr, pooled, DIM, BB, DIM, DIM);
    launch_ln4(pooled, head_ln, nullptr, hn, nullptr, BB, 0);
    launch_tiny(hn, DIM, head_w, DIM, nullptr, out, NC, BB, NC, DIM);
}

// round 16
// speedup vs baseline: 1.1827x; 1.0574x over previous
#include <cuda_runtime.h>
#include <cuda_fp16.h>
#include <math.h>
#include <stdint.h>

#define BB 8
#define LMAX 1024
#define DIM 512
#define HEADS 8
#define DH 64
#define NDEPTH 6
#define MLPD 2048
#define NC 1000
#define PDIM 768
#define NTOK (BB*LMAX)   // 8192

__constant__ int c_L[8]  = {1024, 768, 896, 576, 560, 512, 384, 640};
__constant__ int c_Wp[8] = {  32,  24,  32,  24,  28,  32,  16,  20};

// weight buffer offsets (elements)
#define OFF_QKV 0L
#define OFF_WO  4718592L
#define OFF_FF1 6291456L
#define OFF_FF2 12582912L
#define OFF_PE  18874368L
#define OFF_PK  19267584L
#define OFF_PV  19529728L
#define WTOT    19791872L

// ---------------- scratch ----------------
__device__ __align__(128) float g_tok[(size_t)NTOK*PDIM];
__device__ __align__(128) float g_t  [(size_t)NTOK*DIM];
__device__ __align__(128) float g_qkv[(size_t)3*NTOK*DIM];
__device__ __align__(128) float g_u  [DIM];
__device__ __align__(128) float g_qp [DIM];
__device__ __align__(128) float g_po [BB*DIM];
__device__ __align__(128) float g_pooled[BB*DIM];
__device__ __align__(128) float g_hn [BB*DIM];
__device__ __align__(128) __half g_wh[WTOT];
__device__ __align__(128) __half g_lt [(size_t)NTOK*PDIM];
__device__ __align__(128) __half g_xn [(size_t)NTOK*DIM];
__device__ __align__(128) __half g_mlp[(size_t)NTOK*MLPD];
__device__ __align__(128) __half g_o  [(size_t)NTOK*DIM];
__device__ __align__(128) __half g_qkv16[(size_t)3*NTOK*DIM];
__device__ __align__(128) __half g_qh2[(size_t)NTOK*DIM];
__device__ __align__(128) __half g_kh2[(size_t)NTOK*DIM];
__device__ __align__(128) __half g_vh2[(size_t)NTOK*DIM];

// ================= helpers =================
__device__ __forceinline__ uint32_t smem_u32(const void* p){
    uint32_t a; asm("{ .reg .u64 t; cvta.to.shared.u64 t, %1; cvt.u32.u64 %0, t; }" : "=r"(a) : "l"(p));
    return a;
}
__device__ __forceinline__ void ldsm_x4(uint32_t* r, uint32_t addr){
    asm volatile("ldmatrix.sync.aligned.m8n8.x4.shared.b16 {%0,%1,%2,%3}, [%4];"
        : "=r"(r[0]),"=r"(r[1]),"=r"(r[2]),"=r"(r[3]) : "r"(addr));
}
__device__ __forceinline__ void ldsm_x2(uint32_t* r, uint32_t addr){
    asm volatile("ldmatrix.sync.aligned.m8n8.x2.shared.b16 {%0,%1}, [%2];"
        : "=r"(r[0]),"=r"(r[1]) : "r"(addr));
}
__device__ __forceinline__ void ldsm_x2t(uint32_t* r, uint32_t addr){
    asm volatile("ldmatrix.sync.aligned.m8n8.x2.trans.shared.b16 {%0,%1}, [%2];"
        : "=r"(r[0]),"=r"(r[1]) : "r"(addr));
}
__device__ __forceinline__ void mma16816(float* c, const uint32_t* a, const uint32_t* b){
    asm volatile("mma.sync.aligned.m16n8k16.row.col.f32.f16.f16.f32 "
        "{%0,%1,%2,%3}, {%4,%5,%6,%7}, {%8,%9}, {%0,%1,%2,%3};"
        : "+f"(c[0]),"+f"(c[1]),"+f"(c[2]),"+f"(c[3])
        : "r"(a[0]),"r"(a[1]),"r"(a[2]),"r"(a[3]), "r"(b[0]),"r"(b[1]));
}
__device__ __forceinline__ void cp_async16(uint32_t dst, const void* src){
    asm volatile("cp.async.cg.shared.global [%0], [%1], 16;" :: "r"(dst), "l"(src) : "memory");
}
__device__ __forceinline__ void cp_commit(){ asm volatile("cp.async.commit_group;" ::: "memory"); }
template<int N> __device__ __forceinline__ void cp_wait(){
    asm volatile("cp.async.wait_group %0;" :: "n"(N) : "memory");
}
__device__ __forceinline__ uint32_t h2u(__half2 v){ return *reinterpret_cast<uint32_t*>(&v); }
__device__ __forceinline__ uint32_t packh(float a, float b){
    return h2u(__float22half2_rn(make_float2(a, b)));
}
__device__ __forceinline__ uint4 cvt8s(float4 a, float4 b){
    return make_uint4(packh(a.x, a.y), packh(a.z, a.w), packh(b.x, b.y), packh(b.z, b.w));
}

// ---------------- fused weight convert: all 9 regions in one kernel ----------------
struct WSrcs { const float* p[9]; };
__constant__ long c_wbase4[10] = {0L, 393216L, 786432L, 1179648L, 1572864L,
                                  3145728L, 4718592L, 4816896L, 4882432L, 4947968L};
__global__ void wcvt_all_kernel(WSrcs srcs, __half* __restrict__ h, int n4){
    int i = blockIdx.x*blockDim.x + threadIdx.x;
    if (i >= n4) return;
    int r = 0;
    #pragma unroll
    for (int j = 1; j < 9; j++) if (i >= (int)c_wbase4[j]) r = j;
    float4 v = ((const float4*)srcs.p[r])[i - (int)c_wbase4[r]];
    ((uint2*)h)[i] = make_uint2(packh(v.x, v.y), packh(v.z, v.w));
}

// ============== cp.async HMMA GEMM NT (64x64 tile, 128 threads, high occupancy) ==============
#define BTILE (64*144)           // 9216
#define B_A  0
#define B_W  BTILE
#define B_BUF (2*BTILE)          // 18432
#define B_SMEM (2*B_BUF)         // 36864

__global__ __launch_bounds__(128, 6) void bgemm_nt(
    const __half* __restrict__ A, int lda,
    const __half* __restrict__ W, int ldw, long wz,
    const float* __restrict__ bias,
    const float* __restrict__ R, int ldr,
    float* __restrict__ C, __half* __restrict__ Ch,
    int ldc, long cz,
    int K, int act, int tokrows)
{
    extern __shared__ char smem[];
    uint32_t sb = smem_u32(smem);
    int tid = threadIdx.x, lane = tid & 31, wid = tid >> 5;
    int z = blockIdx.z;
    W += (size_t)z*wz;
    if (C)  C  += (size_t)z*cz;
    if (Ch) Ch += (size_t)z*cz;
    int bm = blockIdx.y*64, bn = blockIdx.x*64;
    if (tokrows && (bm & 1023) >= c_L[bm >> 10]) return;
    int wr = (wid & 1)*32;
    int wn = (wid >> 1)*32;

    float acc[2][4][4];
    #pragma unroll
    for (int i = 0; i < 2; i++)
        #pragma unroll
        for (int j = 0; j < 4; j++)
            #pragma unroll
            for (int p = 0; p < 4; p++) acc[i][j][p] = 0.f;

#define BSTAGE(KC, BUFB) do { \
    _Pragma("unroll") \
    for (int it = 0; it < 4; it++){ \
        int slot = it*128 + tid; int row = slot >> 3, seg = slot & 7; \
        uint32_t so = (uint32_t)(BUFB) + (uint32_t)(row*144 + seg*16); \
        cp_async16(sb + B_A + so, A + (size_t)(bm + row)*lda + (KC)*64 + seg*8); \
        cp_async16(sb + B_W + so, W + (size_t)(bn + row)*ldw + (KC)*64 + seg*8); \
    } } while(0)

    int nk = K >> 6;
    BSTAGE(0, 0);
    cp_commit();

    int grp = lane >> 3, wi = lane & 7;
    for (int kc = 0; kc < nk; kc++){
        cp_wait<0>();
        __syncthreads();
        if (kc + 1 < nk){
            BSTAGE(kc + 1, ((kc + 1) & 1)*B_BUF);
            cp_commit();
        }
        uint32_t cur = (uint32_t)((kc & 1)*B_BUF);
        #pragma unroll
        for (int ks = 0; ks < 4; ks++){
            uint32_t a_f[2][4];
            #pragma unroll
            for (int mi = 0; mi < 2; mi++){
                uint32_t off = (uint32_t)((wr + mi*16 + wi + (grp & 1)*8)*144
                                          + (ks*16 + (grp >> 1)*8)*2);
                ldsm_x4(a_f[mi], sb + B_A + cur + off);
            }
            uint32_t b_f[4][2];
            #pragma unroll
            for (int ni = 0; ni < 4; ni++){
                uint32_t off = (uint32_t)((wn + ni*8 + (lane & 7))*144
                                          + (ks*16 + ((lane >> 3) & 1)*8)*2);
                ldsm_x2(b_f[ni], sb + B_W + cur + off);
            }
            #pragma unroll
            for (int mi = 0; mi < 2; mi++)
                #pragma unroll
                for (int ni = 0; ni < 4; ni++)
                    mma16816(acc[mi][ni], a_f[mi], b_f[ni]);
        }
    }
#undef BSTAGE

    // ---- epilogue ----
    #pragma unroll
    for (int mi = 0; mi < 2; mi++){
        #pragma unroll
        for (int ni = 0; ni < 4; ni++){
            int gn = bn + wn + ni*8 + (lane & 3)*2;
            #pragma unroll
            for (int hh = 0; hh < 2; hh++){
                int m = bm + wr + mi*16 + (lane >> 2) + hh*8;
                float v0 = acc[mi][ni][hh*2 + 0];
                float v1 = acc[mi][ni][hh*2 + 1];
                if (bias){ v0 += bias[gn]; v1 += bias[gn + 1]; }
                if (act){
                    v0 = 0.5f*v0*(1.f + erff(v0*0.70710678118654752f));
                    v1 = 0.5f*v1*(1.f + erff(v1*0.70710678118654752f));
                }
                if (Ch){
                    *(uint32_t*)(Ch + (size_t)m*ldc + gn) = packh(v0, v1);
                } else {
                    if (R){
                        const float* rp = R + (size_t)m*ldr + gn;
                        v0 += rp[0]; v1 += rp[1];
                    }
                    *(float2*)(C + (size_t)m*ldc + gn) = make_float2(v0, v1);
                }
            }
        }
    }
}

// ============== kvprep: reads fp16 qkv; head-LN(Q x 1/8, K); writes fp16 ==============
__global__ void kvprep_kernel(const __half* __restrict__ qkv,
    const float* __restrict__ qn, const float* __restrict__ kn,
    __half* __restrict__ qh, __half* __restrict__ kh, __half* __restrict__ vh)
{
    int g = blockIdx.x*blockDim.x + threadIdx.x;   // NTOK*HEADS*8
    int seg = g & 7;
    int r = g >> 3;
    int tokn = r >> 3, h = r & 7;
    int b = tokn >> 10, l = tokn & 1023;
    if (l >= c_L[b]) return;
    size_t base = (size_t)tokn*DIM + h*64 + seg*8;

#define LD8H(P, X, Y) do { \
    uint4 raw = *(const uint4*)(P); \
    float2 f0 = __half22float2(*reinterpret_cast<__half2*>(&raw.x)); \
    float2 f1 = __half22float2(*reinterpret_cast<__half2*>(&raw.y)); \
    float2 f2 = __half22float2(*reinterpret_cast<__half2*>(&raw.z)); \
    float2 f3 = __half22float2(*reinterpret_cast<__half2*>(&raw.w)); \
    X = make_float4(f0.x, f0.y, f1.x, f1.y); \
    Y = make_float4(f2.x, f2.y, f3.x, f3.y); \
} while(0)

#define LN8(x, y, wvec, scale) do { \
    float sum = x.x + x.y + x.z + x.w + y.x + y.y + y.z + y.w; \
    sum += __shfl_xor_sync(0xffffffffu, sum, 1); \
    sum += __shfl_xor_sync(0xffffffffu, sum, 2); \
    sum += __shfl_xor_sync(0xffffffffu, sum, 4); \
    float mu = sum * (1.f/64.f); \
    x.x -= mu; x.y -= mu; x.z -= mu; x.w -= mu; \
    y.x -= mu; y.y -= mu; y.z -= mu; y.w -= mu; \
    float ss = x.x*x.x + x.y*x.y + x.z*x.z + x.w*x.w \
             + y.x*y.x + y.y*y.y + y.z*y.z + y.w*y.w; \
    ss += __shfl_xor_sync(0xffffffffu, ss, 1); \
    ss += __shfl_xor_sync(0xffffffffu, ss, 2); \
    ss += __shfl_xor_sync(0xffffffffu, ss, 4); \
    float rs = rsqrtf(ss * (1.f/64.f) + 1e-5f) * (scale); \
    float4 w0 = *(const float4*)((wvec) + seg*8); \
    float4 w1 = *(const float4*)((wvec) + seg*8 + 4); \
    x.x *= rs*w0.x; x.y *= rs*w0.y; x.z *= rs*w0.z; x.w *= rs*w0.w; \
    y.x *= rs*w1.x; y.y *= rs*w1.y; y.z *= rs*w1.z; y.w *= rs*w1.w; \
} while(0)

    {   // Q
        float4 x, y; LD8H(qkv + base, x, y);
        LN8(x, y, qn, 0.125f);
        *(uint4*)(qh + base) = cvt8s(x, y);
    }
    {   // K
        float4 x, y; LD8H(qkv + (size_t)NTOK*DIM + base, x, y);
        LN8(x, y, kn, 1.f);
        *(uint4*)(kh + base) = cvt8s(x, y);
    }
    {   // V (straight copy, already fp16)
        *(uint4*)(vh + base) = *(const uint4*)(qkv + (size_t)2*NTOK*DIM + base);
    }
#undef LN8
#undef LD8H
}

// ============== flash attention: pure fp16, cp.async double-buffered, 1 sync/iter ==============
#define FQ 0
#define FKV0 18432
#define FKVS 36864
#define FSMEM (18432 + 2*36864)          // 92160

__global__ __launch_bounds__(256, 2) void flash_kernel(
    const __half* __restrict__ Qh,
    const __half* __restrict__ Kh,
    const __half* __restrict__ Vh,
    __half* __restrict__ O)
{
    extern __shared__ char smem[];
    uint32_t sb = smem_u32(smem);
    int tid = threadIdx.x, lane = tid & 31, wid = tid >> 5;
    int qt = blockIdx.x;
    int bh = blockIdx.y;
    int b = bh >> 3, h = bh & 7;
    int L = c_L[b];
    if (qt*128 >= L) return;
    int ktiles = (L + 127) >> 7;

    // ---- stage Q + KV0 ----
    #pragma unroll
    for (int it = 0; it < 4; it++){
        int slot = it*256 + tid; int row = slot >> 3, seg = slot & 7;
        size_t go = (size_t)(b*1024 + qt*128 + row)*DIM + h*64 + seg*8;
        cp_async16(sb + FQ + (uint32_t)(row*144 + seg*16), Qh + go);
    }
    cp_commit();

#define KVSTAGE(KT, SBASE) do { \
    _Pragma("unroll") \
    for (int it = 0; it < 4; it++){ \
        int slot = it*256 + tid; int row = slot >> 3, seg = slot & 7; \
        size_t go = (size_t)(b*1024 + (KT)*128 + row)*DIM + h*64 + seg*8; \
        uint32_t so = (uint32_t)(SBASE) + (uint32_t)(row*144 + seg*16); \
        cp_async16(sb + so,         Kh + go); \
        cp_async16(sb + so + 18432, Vh + go); \
    } } while(0)

    KVSTAGE(0, FKV0);
    cp_commit();

    cp_wait<1>();
    __syncthreads();

    int wr = wid*16;
    int grp = lane >> 3, wi = lane & 7;
    uint32_t aq[4][4];
    #pragma unroll
    for (int ks = 0; ks < 4; ks++){
        uint32_t off = (uint32_t)((wr + wi + (grp & 1)*8)*144 + (ks*16 + (grp >> 1)*8)*2);
        ldsm_x4(aq[ks], sb + FQ + off);
    }

    float m0 = -1e30f, m1 = -1e30f, l0 = 0.f, l1 = 0.f;
    float ao[8][4];
    #pragma unroll
    for (int i = 0; i < 8; i++)
        #pragma unroll
        for (int p = 0; p < 4; p++) ao[i][p] = 0.f;

    for (int kt = 0; kt < ktiles; kt++){
        cp_wait<0>();
        __syncthreads();
        if (kt + 1 < ktiles){
            KVSTAGE(kt + 1, FKV0 + ((kt + 1) & 1)*FKVS);
            cp_commit();
        }
        uint32_t kb = (uint32_t)(FKV0 + (kt & 1)*FKVS);

        // ---- S = Q K^T ----
        float s[16][4];
        #pragma unroll
        for (int i = 0; i < 16; i++)
            #pragma unroll
            for (int p = 0; p < 4; p++) s[i][p] = 0.f;
        #pragma unroll
        for (int ks = 0; ks < 4; ks++){
            #pragma unroll
            for (int ni = 0; ni < 16; ni++){
                uint32_t off = (uint32_t)((ni*8 + wi)*144 + (ks*16 + (grp & 1)*8)*2);
                uint32_t b_[2];
                ldsm_x2(b_, sb + kb + off);
                mma16816(s[ni], aq[ks], b_);
            }
        }

        // ---- mask (partial tile only) ----
        if (kt == ktiles - 1 && (L & 127)){
            int kbase = kt*128 + 2*(lane & 3);
            #pragma unroll
            for (int ni = 0; ni < 16; ni++){
                int kg = kbase + ni*8;
                if (kg     >= L){ s[ni][0] = -1e9f; s[ni][2] = -1e9f; }
                if (kg + 1 >= L){ s[ni][1] = -1e9f; s[ni][3] = -1e9f; }
            }
        }

        // ---- online softmax ----
        float tm0 = -1e30f, tm1 = -1e30f;
        #pragma unroll
        for (int ni = 0; ni < 16; ni++){
            tm0 = fmaxf(tm0, fmaxf(s[ni][0], s[ni][1]));
            tm1 = fmaxf(tm1, fmaxf(s[ni][2], s[ni][3]));
        }
        tm0 = fmaxf(tm0, __shfl_xor_sync(0xffffffffu, tm0, 1));
        tm0 = fmaxf(tm0, __shfl_xor_sync(0xffffffffu, tm0, 2));
        tm1 = fmaxf(tm1, __shfl_xor_sync(0xffffffffu, tm1, 1));
        tm1 = fmaxf(tm1, __shfl_xor_sync(0xffffffffu, tm1, 2));
        float mn0 = fmaxf(m0, tm0), mn1 = fmaxf(m1, tm1);
        float sc0 = __expf(m0 - mn0), sc1 = __expf(m1 - mn1);
        m0 = mn0; m1 = mn1;
        float ts0 = 0.f, ts1 = 0.f;
        #pragma unroll
        for (int ni = 0; ni < 16; ni++){
            s[ni][0] = __expf(s[ni][0] - m0);
            s[ni][1] = __expf(s[ni][1] - m0);
            s[ni][2] = __expf(s[ni][2] - m1);
            s[ni][3] = __expf(s[ni][3] - m1);
            ts0 += s[ni][0] + s[ni][1];
            ts1 += s[ni][2] + s[ni][3];
        }
        ts0 += __shfl_xor_sync(0xffffffffu, ts0, 1);
        ts0 += __shfl_xor_sync(0xffffffffu, ts0, 2);
        ts1 += __shfl_xor_sync(0xffffffffu, ts1, 1);
        ts1 += __shfl_xor_sync(0xffffffffu, ts1, 2);
        l0 = l0*sc0 + ts0;
        l1 = l1*sc1 + ts1;
        #pragma unroll
        for (int i = 0; i < 8; i++){
            ao[i][0] *= sc0; ao[i][1] *= sc0;
            ao[i][2] *= sc1; ao[i][3] *= sc1;
        }

        // ---- O += P V ----
        #pragma unroll
        for (int kk = 0; kk < 8; kk++){
            uint32_t ap[4];
            ap[0] = packh(s[2*kk][0],   s[2*kk][1]);
            ap[1] = packh(s[2*kk][2],   s[2*kk][3]);
            ap[2] = packh(s[2*kk+1][0], s[2*kk+1][1]);
            ap[3] = packh(s[2*kk+1][2], s[2*kk+1][3]);
            #pragma unroll
            for (int ni = 0; ni < 8; ni++){
                uint32_t off = (uint32_t)((kk*16 + (lane & 15))*144 + ni*16);
                uint32_t v_[2];
                ldsm_x2t(v_, sb + kb + 18432 + off);
                mma16816(ao[ni], ap, v_);
            }
        }
    }
#undef KVSTAGE

    // ---- epilogue: fp16 O ----
    float il0 = 1.f / l0, il1 = 1.f / l1;
    int mrow = qt*128 + wr + (lane >> 2);
    #pragma unroll
    for (int ni = 0; ni < 8; ni++){
        int col = h*64 + ni*8 + 2*(lane & 3);
        *(uint32_t*)(O + (size_t)(b*1024 + mrow)*DIM + col)     = packh(ao[ni][0]*il0, ao[ni][1]*il0);
        *(uint32_t*)(O + (size_t)(b*1024 + mrow + 8)*DIM + col) = packh(ao[ni][2]*il1, ao[ni][3]*il1);
    }
}

// ---------------- patch packing ----------------
__global__ void pack_kernel(const float* __restrict__ img, float* __restrict__ tok){
    size_t i = (size_t)blockIdx.x*blockDim.x + threadIdx.x;
    if (i >= (size_t)NTOK*PDIM) return;
    int pd = (int)(i % PDIM);
    size_t bl = i / PDIM;
    int l = (int)(bl % LMAX);
    int b = (int)(bl / LMAX);
    int L = c_L[b], w = c_Wp[b];
    float v = 0.f;
    if (l < L){
        int c  = pd >> 8;
        int r  = pd & 255;
        int py = r >> 4, px = r & 15;
        int ph = l / w, pw = l % w;
        v = img[((size_t)(b*3 + c)*512 + (size_t)(ph*16 + py))*512 + (size_t)(pw*16 + px)];
    }
    tok[i] = v;
}

// ---------------- warp-per-row LayerNorm (D = NV*128); writes f32 (y) or fp16 (yh) ----------------
template<int NV>
__global__ void lnw_kernel(const float* __restrict__ x, const float* __restrict__ w,
                           const float* __restrict__ bb, float* __restrict__ y,
                           __half* __restrict__ yh, int rows, int tokskip){
    int gw = (int)(((size_t)blockIdx.x*blockDim.x + threadIdx.x) >> 5);
    int lane = threadIdx.x & 31;
    if (gw >= rows) return;
    if (tokskip && (gw & 1023) >= c_L[gw >> 10]) return;
    const int D = NV*128;
    const float* xr = x + (size_t)gw*D;
    float4 v[NV];
    float s = 0.f;
    #pragma unroll
    for (int i = 0; i < NV; i++){
        v[i] = *(const float4*)(xr + i*128 + lane*4);
        s += v[i].x + v[i].y + v[i].z + v[i].w;
    }
    #pragma unroll
    for (int off = 16; off; off >>= 1) s += __shfl_xor_sync(0xffffffffu, s, off);
    float mu = s / (float)D;
    float vs = 0.f;
    #pragma unroll
    for (int i = 0; i < NV; i++){
        float a = v[i].x - mu, b = v[i].y - mu, c = v[i].z - mu, d = v[i].w - mu;
        vs += a*a + b*b + c*c + d*d;
    }
    #pragma unroll
    for (int off = 16; off; off >>= 1) vs += __shfl_xor_sync(0xffffffffu, vs, off);
    float rs = rsqrtf(vs / (float)D + 1e-5f);
    #pragma unroll
    for (int i = 0; i < NV; i++){
        int idx = i*128 + lane*4;
        float4 w4 = *(const float4*)(w + idx);
        float4 o;
        o.x = (v[i].x - mu)*rs*w4.x;
        o.y = (v[i].y - mu)*rs*w4.y;
        o.z = (v[i].z - mu)*rs*w4.z;
        o.w = (v[i].w - mu)*rs*w4.w;
        if (bb){
            float4 b4 = *(const float4*)(bb + idx);
            o.x += b4.x; o.y += b4.y; o.z += b4.z; o.w += b4.w;
        }
        if (y) *(float4*)(y + (size_t)gw*D + idx) = o;
        else   *(uint2*)(yh + (size_t)gw*D + idx) = make_uint2(packh(o.x, o.y), packh(o.z, o.w));
    }
}

// ---------------- fused LN + pos-embed + mask (D=512, in-place on t), warp per row ----------------
__global__ void ln_pos_kernel(float* __restrict__ t, const float* __restrict__ w,
                              const float* __restrict__ bb,
                              const float* __restrict__ ph, const float* __restrict__ pw){
    int gw = (int)(((size_t)blockIdx.x*blockDim.x + threadIdx.x) >> 5);
    int lane = threadIdx.x & 31;
    if (gw >= NTOK) return;
    int b = gw >> 10, l = gw & 1023;
    int L = c_L[b], wgrid = c_Wp[b];
    float* tr = t + (size_t)gw*DIM;
    if (l >= L){
        #pragma unroll
        for (int i = 0; i < 4; i++)
            *(float4*)(tr + i*128 + lane*4) = make_float4(0,0,0,0);
        return;
    }
    float4 v[4];
    float s = 0.f;
    #pragma unroll
    for (int i = 0; i < 4; i++){
        v[i] = *(const float4*)(tr + i*128 + lane*4);
        s += v[i].x + v[i].y + v[i].z + v[i].w;
    }
    #pragma unroll
    for (int off = 16; off; off >>= 1) s += __shfl_xor_sync(0xffffffffu, s, off);
    float mu = s / (float)DIM;
    float vs = 0.f;
    #pragma unroll
    for (int i = 0; i < 4; i++){
        float a = v[i].x - mu, b2 = v[i].y - mu, c = v[i].z - mu, d = v[i].w - mu;
        vs += a*a + b2*b2 + c*c + d*d;
    }
    #pragma unroll
    for (int off = 16; off; off >>= 1) vs += __shfl_xor_sync(0xffffffffu, vs, off);
    float rs = rsqrtf(vs / (float)DIM + 1e-5f);
    const float* p0r = ph + (size_t)(l / wgrid)*DIM;
    const float* p1r = pw + (size_t)(l % wgrid)*DIM;
    #pragma unroll
    for (int i = 0; i < 4; i++){
        int idx = i*128 + lane*4;
        float4 w4 = *(const float4*)(w + idx);
        float4 b4 = *(const float4*)(bb + idx);
        float4 p0 = *(const float4*)(p0r + idx);
        float4 p1 = *(const float4*)(p1r + idx);
        float4 o;
        o.x = (v[i].x - mu)*rs*w4.x + b4.x + p0.x + p1.x;
        o.y = (v[i].y - mu)*rs*w4.y + b4.y + p0.y + p1.y;
        o.z = (v[i].z - mu)*rs*w4.z + b4.z + p0.z + p1.z;
        o.w = (v[i].w - mu)*rs*w4.w + b4.w + p0.w + p1.w;
        *(float4*)(tr + idx) = o;
    }
}

// ---------------- per-head LayerNorm over 64 dims (pool path) ----------------
__global__ void head_ln_kernel(float* __restrict__ x, const float* __restrict__ w, int rows){
    int gw = (int)(((size_t)blockIdx.x*blockDim.x + threadIdx.x) >> 5);
    int lane = threadIdx.x & 31;
    if (gw >= rows) return;
    float* p = x + (size_t)gw*64;
    float a = p[lane], b = p[lane + 32];
    float s = a + b;
    #pragma unroll
    for (int off = 16; off; off >>= 1) s += __shfl_xor_sync(0xffffffffu, s, off);
    float mu = s * (1.f/64.f);
    float da = a - mu, db = b - mu;
    float vs = da*da + db*db;
    #pragma unroll
    for (int off = 16; off; off >>= 1) vs += __shfl_xor_sync(0xffffffffu, vs, off);
    float rs = rsqrtf(vs * (1.f/64.f) + 1e-5f);
    p[lane]      = da * rs * w[lane];
    p[lane + 32] = db * rs * w[lane + 32];
}

// ---------------- tiny GEMM NT: warp per output element (small M) ----------------
__global__ void tiny_nt_kernel(const float* __restrict__ A, int lda,
                               const float* __restrict__ W, int ldw,
                               const float* __restrict__ bias,
                               float* __restrict__ C, int ldc,
                               int M, int N, int K){
    int gw = (int)(((size_t)blockIdx.x*blockDim.x + threadIdx.x) >> 5);
    int lane = threadIdx.x & 31;
    if (gw >= M*N) return;
    int m = gw / N, n = gw % N;
    const float* a = A + (size_t)m*lda;
    const float* wv = W + (size_t)n*ldw;
    float s = 0.f;
    for (int k = lane*4; k < K; k += 128){
        float4 av = *(const float4*)(a + k);
        float4 bv = *(const float4*)(wv + k);
        s += av.x*bv.x + av.y*bv.y + av.z*bv.z + av.w*bv.w;
    }
    #pragma unroll
    for (int off = 16; off; off >>= 1) s += __shfl_xor_sync(0xffffffffu, s, off);
    if (lane == 0){
        if (bias) s += bias[n];
        C[(size_t)m*ldc + n] = s;
    }
}

// ---------------- pooling attention (Lq=1) ----------------
__global__ void pool_attn_kernel(const float* __restrict__ qhat, const float* __restrict__ K,
                                 const float* __restrict__ V, float* __restrict__ O){
    int h = blockIdx.x, b = blockIdx.y;
    __shared__ float sq[64];
    __shared__ float sa[1024];
    __shared__ float red[8], red2[8];
    __shared__ float racc[4][64];
    int tid = threadIdx.x, lane = tid & 31, wp = tid >> 5;
    if (tid < 64) sq[tid] = qhat[h*64 + tid];
    __syncthreads();
    int L = c_L[b];
    for (int kk = tid; kk < 1024; kk += 256){
        float dot = -1e9f;
        if (kk < L){
            const float* kr = K + ((size_t)(b*1024 + kk))*DIM + h*64;
            float ss = 0.f;
            #pragma unroll
            for (int d = 0; d < 64; d++) ss += sq[d]*kr[d];
            dot = ss*0.125f;
        }
        sa[kk] = dot;
    }
    __syncthreads();
    float m = -1e30f;
    for (int kk = tid; kk < 1024; kk += 256) m = fmaxf(m, sa[kk]);
    #pragma unroll
    for (int off = 16; off; off >>= 1) m = fmaxf(m, __shfl_xor_sync(0xffffffffu, m, off));
    if (lane == 0) red[wp] = m;
    __syncthreads();
    float bm = -1e30f;
    #pragma unroll
    for (int i = 0; i < 8; i++) bm = fmaxf(bm, red[i]);
    float sum = 0.f;
    for (int kk = tid; kk < 1024; kk += 256){
        float e = __expf(sa[kk] - bm);
        sa[kk] = e; sum += e;
    }
    #pragma unroll
    for (int off = 16; off; off >>= 1) sum += __shfl_xor_sync(0xffffffffu, sum, off);
    if (lane == 0) red2[wp] = sum;
    __syncthreads();
    float bs = 0.f;
    #pragma unroll
    for (int i = 0; i < 8; i++) bs += red2[i];
    float inv = 1.f / bs;
    int dd = tid & 63, part = tid >> 6;
    float acc = 0.f;
    for (int kk = part; kk < 1024; kk += 4)
        acc += sa[kk] * V[((size_t)(b*1024 + kk))*DIM + h*64 + dd];
    racc[part][dd] = acc;
    __syncthreads();
    if (part == 0)
        O[b*DIM + h*64 + dd] = (racc[0][dd] + racc[1][dd] + racc[2][dd] + racc[3][dd]) * inv;
}

// ---------------- host helpers ----------------
static void launch_bg(const __half* A, int lda,
                      const __half* W, int ldw, long wz,
                      const float* bias, const float* R, int ldr,
                      float* C, __half* Ch, int ldc, long cz,
                      int N, int K, int act, int nz, int tokrows){
    dim3 g(N/64, NTOK/64, nz);
    bgemm_nt<<<g, 128, B_SMEM>>>(A, lda, W, ldw, wz, bias, R, ldr,
                                 C, Ch, ldc, cz, K, act, tokrows);
}
static void launch_tiny(const float* A, int lda, const float* W, int ldw,
                        const float* bias, float* C, int ldc, int M, int N, int K){
    int warps = M*N;
    tiny_nt_kernel<<<(warps*32 + 255)/256, 256>>>(A, lda, W, ldw, bias, C, ldc, M, N, K);
}
static void launch_ln4(const float* x, const float* w, const float* bb,
                       float* y, __half* yh, int rows, int tokskip){
    lnw_kernel<4><<<(rows*32 + 255)/256, 256>>>(x, w, bb, y, yh, rows, tokskip);
}

extern "C" void kernel_launch(void* const* d_in, const int* in_sizes, int n_in,
                              void* d_out, int out_size){
    const float* images   = (const float*)d_in[0];
    const float* pe_ln1_w = (const float*)d_in[1];
    const float* pe_ln1_b = (const float*)d_in[2];
    const float* pe_w     = (const float*)d_in[3];
    const float* pe_b     = (const float*)d_in[4];
    const float* pe_ln2_w = (const float*)d_in[5];
    const float* pe_ln2_b = (const float*)d_in[6];
    const float* pos_h    = (const float*)d_in[7];
    const float* pos_w    = (const float*)d_in[8];
    const float* attn_ln  = (const float*)d_in[9];
    const float* wq       = (const float*)d_in[10];
    const float* wk       = (const float*)d_in[11];
    const float* wv       = (const float*)d_in[12];
    const float* qn       = (const float*)d_in[13];
    const float* kn       = (const float*)d_in[14];
    const float* wo       = (const float*)d_in[15];
    const float* ff_ln    = (const float*)d_in[16];
    const float* ff_w1    = (const float*)d_in[17];
    const float* ff_b1    = (const float*)d_in[18];
    const float* ff_w2    = (const float*)d_in[19];
    const float* ff_b2    = (const float*)d_in[20];
    const float* final_ln = (const float*)d_in[21];
    const float* pool_q   = (const float*)d_in[22];
    const float* pool_ln  = (const float*)d_in[23];
    const float* pool_wq  = (const float*)d_in[24];
    const float* pool_wk  = (const float*)d_in[25];
    const float* pool_wv  = (const float*)d_in[26];
    const float* pool_qn  = (const float*)d_in[27];
    const float* pool_kn  = (const float*)d_in[28];
    const float* pool_wo  = (const float*)d_in[29];
    const float* head_ln  = (const float*)d_in[30];
    const float* head_w   = (const float*)d_in[31];
    float* out = (float*)d_out;

    cudaFuncSetAttribute(bgemm_nt, cudaFuncAttributeMaxDynamicSharedMemorySize, B_SMEM);
    cudaFuncSetAttribute(flash_kernel, cudaFuncAttributeMaxDynamicSharedMemorySize, FSMEM);

    float *tok,*t,*qkv,*u,*qp,*po,*pooled,*hn;
    __half *wh,*lt,*xn,*mlp,*o,*qkv16,*qh,*kh,*vh;
    cudaGetSymbolAddress((void**)&tok, g_tok);
    cudaGetSymbolAddress((void**)&t,   g_t);
    cudaGetSymbolAddress((void**)&qkv, g_qkv);
    cudaGetSymbolAddress((void**)&u,   g_u);
    cudaGetSymbolAddress((void**)&qp,  g_qp);
    cudaGetSymbolAddress((void**)&po,  g_po);
    cudaGetSymbolAddress((void**)&pooled, g_pooled);
    cudaGetSymbolAddress((void**)&hn,  g_hn);
    cudaGetSymbolAddress((void**)&wh,  g_wh);
    cudaGetSymbolAddress((void**)&lt,  g_lt);
    cudaGetSymbolAddress((void**)&xn,  g_xn);
    cudaGetSymbolAddress((void**)&mlp, g_mlp);
    cudaGetSymbolAddress((void**)&o,   g_o);
    cudaGetSymbolAddress((void**)&qkv16, g_qkv16);
    cudaGetSymbolAddress((void**)&qh,  g_qh2);
    cudaGetSymbolAddress((void**)&kh,  g_kh2);
    cudaGetSymbolAddress((void**)&vh,  g_vh2);

    float* kf = qkv + (size_t)NTOK*DIM;
    float* vf = qkv + (size_t)2*NTOK*DIM;

    // ---- weight convert: single fused launch ----
    {
        WSrcs ws;
        ws.p[0] = wq;  ws.p[1] = wk;  ws.p[2] = wv;  ws.p[3] = wo;
        ws.p[4] = ff_w1; ws.p[5] = ff_w2; ws.p[6] = pe_w;
        ws.p[7] = pool_wk; ws.p[8] = pool_wv;
        int n4 = (int)(WTOT >> 2);
        wcvt_all_kernel<<<(n4 + 255)/256, 256>>>(ws, wh, n4);
    }

    // ---- patch embed ----
    pack_kernel<<<((size_t)NTOK*PDIM + 255)/256, 256>>>(images, tok);
    lnw_kernel<6><<<(NTOK*32 + 255)/256, 256>>>(tok, pe_ln1_w, pe_ln1_b, nullptr, lt, NTOK, 1);
    launch_bg(lt, PDIM, wh + OFF_PE, PDIM, 0, pe_b,
              nullptr, 0, t, nullptr, DIM, 0, DIM, PDIM, 0, 1, 1);
    ln_pos_kernel<<<(NTOK*32 + 255)/256, 256>>>(t, pe_ln2_w, pe_ln2_b, pos_h, pos_w);

    // ---- transformer layers ----
    for (int l = 0; l < NDEPTH; l++){
        launch_ln4(t, attn_ln + l*DIM, nullptr, nullptr, xn, NTOK, 1);
        launch_bg(xn, DIM, wh + OFF_QKV + (size_t)l*DIM*DIM, DIM, 1572864L,
                  nullptr, nullptr, 0,
                  nullptr, qkv16, DIM, (long)NTOK*DIM, DIM, DIM, 0, 3, 1);
        kvprep_kernel<<<NTOK*HEADS*8/256, 256>>>(qkv16, qn + l*DH, kn + l*DH, qh, kh, vh);
        flash_kernel<<<dim3(8, BB*HEADS), 256, FSMEM>>>(qh, kh, vh, o);
        launch_bg(o, DIM, wh + OFF_WO + (size_t)l*DIM*DIM, DIM, 0,
                  nullptr, t, DIM, t, nullptr, DIM, 0, DIM, DIM, 0, 1, 1);
        launch_ln4(t, ff_ln + l*DIM, nullptr, nullptr, xn, NTOK, 1);
        launch_bg(xn, DIM, wh + OFF_FF1 + (size_t)l*MLPD*DIM, DIM, 0,
                  ff_b1 + l*MLPD, nullptr, 0,
                  nullptr, mlp, MLPD, 0, MLPD, DIM, 1, 1, 1);
        launch_bg(mlp, MLPD, wh + OFF_FF2 + (size_t)l*DIM*MLPD, MLPD, 0,
                  ff_b2 + l*DIM, t, DIM, t, nullptr, DIM, 0, DIM, MLPD, 0, 1, 1);
    }

    // ---- final LN + pooling ----
    launch_ln4(t, final_ln, nullptr, nullptr, xn, NTOK, 1);
    launch_ln4(pool_q, pool_ln, nullptr, u, nullptr, 1, 0);
    launch_tiny(u, DIM, pool_wq, DIM, nullptr, qp, DIM, 1, DIM, DIM);
    head_ln_kernel<<<1, 256>>>(qp, pool_qn, HEADS);
    // pool K and V in one batched GEMM (weights adjacent: OFF_PK then OFF_PV)
    launch_bg(xn, DIM, wh + OFF_PK, DIM, (long)(OFF_PV - OFF_PK), nullptr, nullptr, 0,
              kf, nullptr, DIM, (long)NTOK*DIM, DIM, DIM, 0, 2, 1);
    head_ln_kernel<<<(NTOK*HEADS*32 + 255)/256, 256>>>(kf, pool_kn, NTOK*HEADS);
    pool_attn_kernel<<<dim3(HEADS, BB), 256>>>(qp, kf, vf, po);
    launch_tiny(po, DIM, pool_wo, DIM, nullptr, pooled, DIM, BB, DIM, DIM);
    launch_ln4(pooled, head_ln, nullptr, hn, nullptr, BB, 0);
    launch_tiny(hn, DIM, head_w, DIM, nullptr, out, NC, BB, NC, DIM);
}

// round 17
// speedup vs baseline: 1.1877x; 1.0042x over previous
#include <cuda_runtime.h>
#include <cuda_fp16.h>
#include <math.h>
#include <stdint.h>

#define BB 8
#define LMAX 1024
#define DIM 512
#define HEADS 8
#define DH 64
#define NDEPTH 6
#define MLPD 2048
#define NC 1000
#define PDIM 768
#define NTOK (BB*LMAX)   // 8192

__constant__ int c_L[8]  = {1024, 768, 896, 576, 560, 512, 384, 640};
__constant__ int c_Wp[8] = {  32,  24,  32,  24,  28,  32,  16,  20};

// weight buffer offsets (elements)
#define OFF_QKV 0L
#define OFF_WO  4718592L
#define OFF_FF1 6291456L
#define OFF_FF2 12582912L
#define OFF_PE  18874368L
#define OFF_PK  19267584L
#define OFF_PV  19529728L
#define WTOT    19791872L

// ---------------- scratch ----------------
__device__ __align__(128) float g_tok[(size_t)NTOK*PDIM];
__device__ __align__(128) float g_t  [(size_t)NTOK*DIM];
__device__ __align__(128) float g_qkv[(size_t)3*NTOK*DIM];
__device__ __align__(128) float g_u  [DIM];
__device__ __align__(128) float g_qp [DIM];
__device__ __align__(128) float g_po [BB*DIM];
__device__ __align__(128) float g_pooled[BB*DIM];
__device__ __align__(128) float g_hn [BB*DIM];
__device__ __align__(128) __half g_wh[WTOT];
__device__ __align__(128) __half g_lt [(size_t)NTOK*PDIM];
__device__ __align__(128) __half g_xn [(size_t)NTOK*DIM];
__device__ __align__(128) __half g_mlp[(size_t)NTOK*MLPD];
__device__ __align__(128) __half g_o  [(size_t)NTOK*DIM];
__device__ __align__(128) __half g_qkv16[(size_t)3*NTOK*DIM];
__device__ __align__(128) __half g_qh2[(size_t)NTOK*DIM];
__device__ __align__(128) __half g_kh2[(size_t)NTOK*DIM];

// ================= helpers =================
__device__ __forceinline__ uint32_t smem_u32(const void* p){
    uint32_t a; asm("{ .reg .u64 t; cvta.to.shared.u64 t, %1; cvt.u32.u64 %0, t; }" : "=r"(a) : "l"(p));
    return a;
}
__device__ __forceinline__ void ldsm_x4(uint32_t* r, uint32_t addr){
    asm volatile("ldmatrix.sync.aligned.m8n8.x4.shared.b16 {%0,%1,%2,%3}, [%4];"
        : "=r"(r[0]),"=r"(r[1]),"=r"(r[2]),"=r"(r[3]) : "r"(addr));
}
__device__ __forceinline__ void ldsm_x2(uint32_t* r, uint32_t addr){
    asm volatile("ldmatrix.sync.aligned.m8n8.x2.shared.b16 {%0,%1}, [%2];"
        : "=r"(r[0]),"=r"(r[1]) : "r"(addr));
}
__device__ __forceinline__ void ldsm_x2t(uint32_t* r, uint32_t addr){
    asm volatile("ldmatrix.sync.aligned.m8n8.x2.trans.shared.b16 {%0,%1}, [%2];"
        : "=r"(r[0]),"=r"(r[1]) : "r"(addr));
}
__device__ __forceinline__ void mma16816(float* c, const uint32_t* a, const uint32_t* b){
    asm volatile("mma.sync.aligned.m16n8k16.row.col.f32.f16.f16.f32 "
        "{%0,%1,%2,%3}, {%4,%5,%6,%7}, {%8,%9}, {%0,%1,%2,%3};"
        : "+f"(c[0]),"+f"(c[1]),"+f"(c[2]),"+f"(c[3])
        : "r"(a[0]),"r"(a[1]),"r"(a[2]),"r"(a[3]), "r"(b[0]),"r"(b[1]));
}
__device__ __forceinline__ void cp_async16(uint32_t dst, const void* src){
    asm volatile("cp.async.cg.shared.global [%0], [%1], 16;" :: "r"(dst), "l"(src) : "memory");
}
__device__ __forceinline__ void cp_commit(){ asm volatile("cp.async.commit_group;" ::: "memory"); }
template<int N> __device__ __forceinline__ void cp_wait(){
    asm volatile("cp.async.wait_group %0;" :: "n"(N) : "memory");
}
__device__ __forceinline__ uint32_t h2u(__half2 v){ return *reinterpret_cast<uint32_t*>(&v); }
__device__ __forceinline__ uint32_t packh(float a, float b){
    return h2u(__float22half2_rn(make_float2(a, b)));
}
__device__ __forceinline__ uint4 cvt8s(float4 a, float4 b){
    return make_uint4(packh(a.x, a.y), packh(a.z, a.w), packh(b.x, b.y), packh(b.z, b.w));
}

// ---------------- fused weight convert: all 9 regions in one kernel ----------------
struct WSrcs { const float* p[9]; };
__constant__ long c_wbase4[10] = {0L, 393216L, 786432L, 1179648L, 1572864L,
                                  3145728L, 4718592L, 4816896L, 4882432L, 4947968L};
__global__ void wcvt_all_kernel(WSrcs srcs, __half* __restrict__ h, int n4){
    int i = blockIdx.x*blockDim.x + threadIdx.x;
    if (i >= n4) return;
    int r = 0;
    #pragma unroll
    for (int j = 1; j < 9; j++) if (i >= (int)c_wbase4[j]) r = j;
    float4 v = ((const float4*)srcs.p[r])[i - (int)c_wbase4[r]];
    ((uint2*)h)[i] = make_uint2(packh(v.x, v.y), packh(v.z, v.w));
}

// ============== cp.async HMMA GEMM NT (64x64 tile, 128 threads, high occupancy) ==============
#define BTILE (64*144)           // 9216
#define B_A  0
#define B_W  BTILE
#define B_BUF (2*BTILE)          // 18432
#define B_SMEM (2*B_BUF)         // 36864

__global__ __launch_bounds__(128, 6) void bgemm_nt(
    const __half* __restrict__ A, int lda,
    const __half* __restrict__ W, int ldw, long wz,
    const float* __restrict__ bias,
    const float* __restrict__ R, int ldr,
    float* __restrict__ C, __half* __restrict__ Ch,
    int ldc, long cz,
    int K, int act, int tokrows)
{
    extern __shared__ char smem[];
    uint32_t sb = smem_u32(smem);
    int tid = threadIdx.x, lane = tid & 31, wid = tid >> 5;
    int z = blockIdx.z;
    W += (size_t)z*wz;
    if (C)  C  += (size_t)z*cz;
    if (Ch) Ch += (size_t)z*cz;
    int bm = blockIdx.y*64, bn = blockIdx.x*64;
    if (tokrows && (bm & 1023) >= c_L[bm >> 10]) return;
    int wr = (wid & 1)*32;
    int wn = (wid >> 1)*32;

    float acc[2][4][4];
    #pragma unroll
    for (int i = 0; i < 2; i++)
        #pragma unroll
        for (int j = 0; j < 4; j++)
            #pragma unroll
            for (int p = 0; p < 4; p++) acc[i][j][p] = 0.f;

#define BSTAGE(KC, BUFB) do { \
    _Pragma("unroll") \
    for (int it = 0; it < 4; it++){ \
        int slot = it*128 + tid; int row = slot >> 3, seg = slot & 7; \
        uint32_t so = (uint32_t)(BUFB) + (uint32_t)(row*144 + seg*16); \
        cp_async16(sb + B_A + so, A + (size_t)(bm + row)*lda + (KC)*64 + seg*8); \
        cp_async16(sb + B_W + so, W + (size_t)(bn + row)*ldw + (KC)*64 + seg*8); \
    } } while(0)

    int nk = K >> 6;
    BSTAGE(0, 0);
    cp_commit();

    int grp = lane >> 3, wi = lane & 7;
    for (int kc = 0; kc < nk; kc++){
        cp_wait<0>();
        __syncthreads();
        if (kc + 1 < nk){
            BSTAGE(kc + 1, ((kc + 1) & 1)*B_BUF);
            cp_commit();
        }
        uint32_t cur = (uint32_t)((kc & 1)*B_BUF);
        #pragma unroll
        for (int ks = 0; ks < 4; ks++){
            uint32_t a_f[2][4];
            #pragma unroll
            for (int mi = 0; mi < 2; mi++){
                uint32_t off = (uint32_t)((wr + mi*16 + wi + (grp & 1)*8)*144
                                          + (ks*16 + (grp >> 1)*8)*2);
                ldsm_x4(a_f[mi], sb + B_A + cur + off);
            }
            uint32_t b_f[4][2];
            #pragma unroll
            for (int ni = 0; ni < 4; ni++){
                uint32_t off = (uint32_t)((wn + ni*8 + (lane & 7))*144
                                          + (ks*16 + ((lane >> 3) & 1)*8)*2);
                ldsm_x2(b_f[ni], sb + B_W + cur + off);
            }
            #pragma unroll
            for (int mi = 0; mi < 2; mi++)
                #pragma unroll
                for (int ni = 0; ni < 4; ni++)
                    mma16816(acc[mi][ni], a_f[mi], b_f[ni]);
        }
    }
#undef BSTAGE

    // ---- epilogue ----
    #pragma unroll
    for (int mi = 0; mi < 2; mi++){
        #pragma unroll
        for (int ni = 0; ni < 4; ni++){
            int gn = bn + wn + ni*8 + (lane & 3)*2;
            #pragma unroll
            for (int hh = 0; hh < 2; hh++){
                int m = bm + wr + mi*16 + (lane >> 2) + hh*8;
                float v0 = acc[mi][ni][hh*2 + 0];
                float v1 = acc[mi][ni][hh*2 + 1];
                if (bias){ v0 += bias[gn]; v1 += bias[gn + 1]; }
                if (act){
                    v0 = 0.5f*v0*(1.f + erff(v0*0.70710678118654752f));
                    v1 = 0.5f*v1*(1.f + erff(v1*0.70710678118654752f));
                }
                if (Ch){
                    *(uint32_t*)(Ch + (size_t)m*ldc + gn) = packh(v0, v1);
                } else {
                    if (R){
                        const float* rp = R + (size_t)m*ldr + gn;
                        v0 += rp[0]; v1 += rp[1];
                    }
                    *(float2*)(C + (size_t)m*ldc + gn) = make_float2(v0, v1);
                }
            }
        }
    }
}

// ============== kvprep: reads fp16 qkv; head-LN(Q x 1/8, K); writes fp16 (V untouched) ==============
__global__ void kvprep_kernel(const __half* __restrict__ qkv,
    const float* __restrict__ qn, const float* __restrict__ kn,
    __half* __restrict__ qh, __half* __restrict__ kh)
{
    int g = blockIdx.x*blockDim.x + threadIdx.x;   // NTOK*HEADS*8
    int seg = g & 7;
    int r = g >> 3;
    int tokn = r >> 3, h = r & 7;
    int b = tokn >> 10, l = tokn & 1023;
    if (l >= c_L[b]) return;
    size_t base = (size_t)tokn*DIM + h*64 + seg*8;

#define LD8H(P, X, Y) do { \
    uint4 raw = *(const uint4*)(P); \
    float2 f0 = __half22float2(*reinterpret_cast<__half2*>(&raw.x)); \
    float2 f1 = __half22float2(*reinterpret_cast<__half2*>(&raw.y)); \
    float2 f2 = __half22float2(*reinterpret_cast<__half2*>(&raw.z)); \
    float2 f3 = __half22float2(*reinterpret_cast<__half2*>(&raw.w)); \
    X = make_float4(f0.x, f0.y, f1.x, f1.y); \
    Y = make_float4(f2.x, f2.y, f3.x, f3.y); \
} while(0)

#define LN8(x, y, wvec, scale) do { \
    float sum = x.x + x.y + x.z + x.w + y.x + y.y + y.z + y.w; \
    sum += __shfl_xor_sync(0xffffffffu, sum, 1); \
    sum += __shfl_xor_sync(0xffffffffu, sum, 2); \
    sum += __shfl_xor_sync(0xffffffffu, sum, 4); \
    float mu = sum * (1.f/64.f); \
    x.x -= mu; x.y -= mu; x.z -= mu; x.w -= mu; \
    y.x -= mu; y.y -= mu; y.z -= mu; y.w -= mu; \
    float ss = x.x*x.x + x.y*x.y + x.z*x.z + x.w*x.w \
             + y.x*y.x + y.y*y.y + y.z*y.z + y.w*y.w; \
    ss += __shfl_xor_sync(0xffffffffu, ss, 1); \
    ss += __shfl_xor_sync(0xffffffffu, ss, 2); \
    ss += __shfl_xor_sync(0xffffffffu, ss, 4); \
    float rs = rsqrtf(ss * (1.f/64.f) + 1e-5f) * (scale); \
    float4 w0 = *(const float4*)((wvec) + seg*8); \
    float4 w1 = *(const float4*)((wvec) + seg*8 + 4); \
    x.x *= rs*w0.x; x.y *= rs*w0.y; x.z *= rs*w0.z; x.w *= rs*w0.w; \
    y.x *= rs*w1.x; y.y *= rs*w1.y; y.z *= rs*w1.z; y.w *= rs*w1.w; \
} while(0)

    {   // Q
        float4 x, y; LD8H(qkv + base, x, y);
        LN8(x, y, qn, 0.125f);
        *(uint4*)(qh + base) = cvt8s(x, y);
    }
    {   // K
        float4 x, y; LD8H(qkv + (size_t)NTOK*DIM + base, x, y);
        LN8(x, y, kn, 1.f);
        *(uint4*)(kh + base) = cvt8s(x, y);
    }
#undef LN8
#undef LD8H
}

// ============== flash attention: pure fp16, cp.async double-buffered, 1 sync/iter ==============
#define FQ 0
#define FKV0 18432
#define FKVS 36864
#define FSMEM (18432 + 2*36864)          // 92160

__global__ __launch_bounds__(256, 2) void flash_kernel(
    const __half* __restrict__ Qh,
    const __half* __restrict__ Kh,
    const __half* __restrict__ Vh,
    __half* __restrict__ O)
{
    extern __shared__ char smem[];
    uint32_t sb = smem_u32(smem);
    int tid = threadIdx.x, lane = tid & 31, wid = tid >> 5;
    int qt = blockIdx.x;
    int bh = blockIdx.y;
    int b = bh >> 3, h = bh & 7;
    int L = c_L[b];
    if (qt*128 >= L) return;
    int ktiles = (L + 127) >> 7;

    // ---- stage Q + KV0 ----
    #pragma unroll
    for (int it = 0; it < 4; it++){
        int slot = it*256 + tid; int row = slot >> 3, seg = slot & 7;
        size_t go = (size_t)(b*1024 + qt*128 + row)*DIM + h*64 + seg*8;
        cp_async16(sb + FQ + (uint32_t)(row*144 + seg*16), Qh + go);
    }
    cp_commit();

#define KVSTAGE(KT, SBASE) do { \
    _Pragma("unroll") \
    for (int it = 0; it < 4; it++){ \
        int slot = it*256 + tid; int row = slot >> 3, seg = slot & 7; \
        size_t go = (size_t)(b*1024 + (KT)*128 + row)*DIM + h*64 + seg*8; \
        uint32_t so = (uint32_t)(SBASE) + (uint32_t)(row*144 + seg*16); \
        cp_async16(sb + so,         Kh + go); \
        cp_async16(sb + so + 18432, Vh + go); \
    } } while(0)

    KVSTAGE(0, FKV0);
    cp_commit();

    cp_wait<1>();
    __syncthreads();

    int wr = wid*16;
    int grp = lane >> 3, wi = lane & 7;
    uint32_t aq[4][4];
    #pragma unroll
    for (int ks = 0; ks < 4; ks++){
        uint32_t off = (uint32_t)((wr + wi + (grp & 1)*8)*144 + (ks*16 + (grp >> 1)*8)*2);
        ldsm_x4(aq[ks], sb + FQ + off);
    }

    float m0 = -1e30f, m1 = -1e30f, l0 = 0.f, l1 = 0.f;
    float ao[8][4];
    #pragma unroll
    for (int i = 0; i < 8; i++)
        #pragma unroll
        for (int p = 0; p < 4; p++) ao[i][p] = 0.f;

    for (int kt = 0; kt < ktiles; kt++){
        cp_wait<0>();
        __syncthreads();
        if (kt + 1 < ktiles){
            KVSTAGE(kt + 1, FKV0 + ((kt + 1) & 1)*FKVS);
            cp_commit();
        }
        uint32_t kb = (uint32_t)(FKV0 + (kt & 1)*FKVS);

        // ---- S = Q K^T ----
        float s[16][4];
        #pragma unroll
        for (int i = 0; i < 16; i++)
            #pragma unroll
            for (int p = 0; p < 4; p++) s[i][p] = 0.f;
        #pragma unroll
        for (int ks = 0; ks < 4; ks++){
            #pragma unroll
            for (int ni = 0; ni < 16; ni++){
                uint32_t off = (uint32_t)((ni*8 + wi)*144 + (ks*16 + (grp & 1)*8)*2);
                uint32_t b_[2];
                ldsm_x2(b_, sb + kb + off);
                mma16816(s[ni], aq[ks], b_);
            }
        }

        // ---- mask (partial tile only) ----
        if (kt == ktiles - 1 && (L & 127)){
            int kbase = kt*128 + 2*(lane & 3);
            #pragma unroll
            for (int ni = 0; ni < 16; ni++){
                int kg = kbase + ni*8;
                if (kg     >= L){ s[ni][0] = -1e9f; s[ni][2] = -1e9f; }
                if (kg + 1 >= L){ s[ni][1] = -1e9f; s[ni][3] = -1e9f; }
            }
        }

        // ---- online softmax ----
        float tm0 = -1e30f, tm1 = -1e30f;
        #pragma unroll
        for (int ni = 0; ni < 16; ni++){
            tm0 = fmaxf(tm0, fmaxf(s[ni][0], s[ni][1]));
            tm1 = fmaxf(tm1, fmaxf(s[ni][2], s[ni][3]));
        }
        tm0 = fmaxf(tm0, __shfl_xor_sync(0xffffffffu, tm0, 1));
        tm0 = fmaxf(tm0, __shfl_xor_sync(0xffffffffu, tm0, 2));
        tm1 = fmaxf(tm1, __shfl_xor_sync(0xffffffffu, tm1, 1));
        tm1 = fmaxf(tm1, __shfl_xor_sync(0xffffffffu, tm1, 2));
        float mn0 = fmaxf(m0, tm0), mn1 = fmaxf(m1, tm1);
        float sc0 = __expf(m0 - mn0), sc1 = __expf(m1 - mn1);
        m0 = mn0; m1 = mn1;
        float ts0 = 0.f, ts1 = 0.f;
        #pragma unroll
        for (int ni = 0; ni < 16; ni++){
            s[ni][0] = __expf(s[ni][0] - m0);
            s[ni][1] = __expf(s[ni][1] - m0);
            s[ni][2] = __expf(s[ni][2] - m1);
            s[ni][3] = __expf(s[ni][3] - m1);
            ts0 += s[ni][0] + s[ni][1];
            ts1 += s[ni][2] + s[ni][3];
        }
        ts0 += __shfl_xor_sync(0xffffffffu, ts0, 1);
        ts0 += __shfl_xor_sync(0xffffffffu, ts0, 2);
        ts1 += __shfl_xor_sync(0xffffffffu, ts1, 1);
        ts1 += __shfl_xor_sync(0xffffffffu, ts1, 2);
        l0 = l0*sc0 + ts0;
        l1 = l1*sc1 + ts1;
        #pragma unroll
        for (int i = 0; i < 8; i++){
            ao[i][0] *= sc0; ao[i][1] *= sc0;
            ao[i][2] *= sc1; ao[i][3] *= sc1;
        }

        // ---- O += P V ----
        #pragma unroll
        for (int kk = 0; kk < 8; kk++){
            uint32_t ap[4];
            ap[0] = packh(s[2*kk][0],   s[2*kk][1]);
            ap[1] = packh(s[2*kk][2],   s[2*kk][3]);
            ap[2] = packh(s[2*kk+1][0], s[2*kk+1][1]);
            ap[3] = packh(s[2*kk+1][2], s[2*kk+1][3]);
            #pragma unroll
            for (int ni = 0; ni < 8; ni++){
                uint32_t off = (uint32_t)((kk*16 + (lane & 15))*144 + ni*16);
                uint32_t v_[2];
                ldsm_x2t(v_, sb + kb + 18432 + off);
                mma16816(ao[ni], ap, v_);
            }
        }
    }
#undef KVSTAGE

    // ---- epilogue: fp16 O ----
    float il0 = 1.f / l0, il1 = 1.f / l1;
    int mrow = qt*128 + wr + (lane >> 2);
    #pragma unroll
    for (int ni = 0; ni < 8; ni++){
        int col = h*64 + ni*8 + 2*(lane & 3);
        *(uint32_t*)(O + (size_t)(b*1024 + mrow)*DIM + col)     = packh(ao[ni][0]*il0, ao[ni][1]*il0);
        *(uint32_t*)(O + (size_t)(b*1024 + mrow + 8)*DIM + col) = packh(ao[ni][2]*il1, ao[ni][3]*il1);
    }
}

// ---------------- patch packing ----------------
__global__ void pack_kernel(const float* __restrict__ img, float* __restrict__ tok){
    size_t i = (size_t)blockIdx.x*blockDim.x + threadIdx.x;
    if (i >= (size_t)NTOK*PDIM) return;
    int pd = (int)(i % PDIM);
    size_t bl = i / PDIM;
    int l = (int)(bl % LMAX);
    int b = (int)(bl / LMAX);
    int L = c_L[b], w = c_Wp[b];
    float v = 0.f;
    if (l < L){
        int c  = pd >> 8;
        int r  = pd & 255;
        int py = r >> 4, px = r & 15;
        int ph = l / w, pw = l % w;
        v = img[((size_t)(b*3 + c)*512 + (size_t)(ph*16 + py))*512 + (size_t)(pw*16 + px)];
    }
    tok[i] = v;
}

// ---------------- warp-per-row LayerNorm (D = NV*128); writes f32 (y) or fp16 (yh) ----------------
template<int NV>
__global__ void lnw_kernel(const float* __restrict__ x, const float* __restrict__ w,
                           const float* __restrict__ bb, float* __restrict__ y,
                           __half* __restrict__ yh, int rows, int tokskip){
    int gw = (int)(((size_t)blockIdx.x*blockDim.x + threadIdx.x) >> 5);
    int lane = threadIdx.x & 31;
    if (gw >= rows) return;
    if (tokskip && (gw & 1023) >= c_L[gw >> 10]) return;
    const int D = NV*128;
    const float* xr = x + (size_t)gw*D;
    float4 v[NV];
    float s = 0.f;
    #pragma unroll
    for (int i = 0; i < NV; i++){
        v[i] = *(const float4*)(xr + i*128 + lane*4);
        s += v[i].x + v[i].y + v[i].z + v[i].w;
    }
    #pragma unroll
    for (int off = 16; off; off >>= 1) s += __shfl_xor_sync(0xffffffffu, s, off);
    float mu = s / (float)D;
    float vs = 0.f;
    #pragma unroll
    for (int i = 0; i < NV; i++){
        float a = v[i].x - mu, b = v[i].y - mu, c = v[i].z - mu, d = v[i].w - mu;
        vs += a*a + b*b + c*c + d*d;
    }
    #pragma unroll
    for (int off = 16; off; off >>= 1) vs += __shfl_xor_sync(0xffffffffu, vs, off);
    float rs = rsqrtf(vs / (float)D + 1e-5f);
    #pragma unroll
    for (int i = 0; i < NV; i++){
        int idx = i*128 + lane*4;
        float4 w4 = *(const float4*)(w + idx);
        float4 o;
        o.x = (v[i].x - mu)*rs*w4.x;
        o.y = (v[i].y - mu)*rs*w4.y;
        o.z = (v[i].z - mu)*rs*w4.z;
        o.w = (v[i].w - mu)*rs*w4.w;
        if (bb){
            float4 b4 = *(const float4*)(bb + idx);
            o.x += b4.x; o.y += b4.y; o.z += b4.z; o.w += b4.w;
        }
        if (y) *(float4*)(y + (size_t)gw*D + idx) = o;
        else   *(uint2*)(yh + (size_t)gw*D + idx) = make_uint2(packh(o.x, o.y), packh(o.z, o.w));
    }
}

// ---------------- fused LN + pos-embed + mask (D=512, in-place on t), warp per row ----------------
__global__ void ln_pos_kernel(float* __restrict__ t, const float* __restrict__ w,
                              const float* __restrict__ bb,
                              const float* __restrict__ ph, const float* __restrict__ pw){
    int gw = (int)(((size_t)blockIdx.x*blockDim.x + threadIdx.x) >> 5);
    int lane = threadIdx.x & 31;
    if (gw >= NTOK) return;
    int b = gw >> 10, l = gw & 1023;
    int L = c_L[b], wgrid = c_Wp[b];
    float* tr = t + (size_t)gw*DIM;
    if (l >= L){
        #pragma unroll
        for (int i = 0; i < 4; i++)
            *(float4*)(tr + i*128 + lane*4) = make_float4(0,0,0,0);
        return;
    }
    float4 v[4];
    float s = 0.f;
    #pragma unroll
    for (int i = 0; i < 4; i++){
        v[i] = *(const float4*)(tr + i*128 + lane*4);
        s += v[i].x + v[i].y + v[i].z + v[i].w;
    }
    #pragma unroll
    for (int off = 16; off; off >>= 1) s += __shfl_xor_sync(0xffffffffu, s, off);
    float mu = s / (float)DIM;
    float vs = 0.f;
    #pragma unroll
    for (int i = 0; i < 4; i++){
        float a = v[i].x - mu, b2 = v[i].y - mu, c = v[i].z - mu, d = v[i].w - mu;
        vs += a*a + b2*b2 + c*c + d*d;
    }
    #pragma unroll
    for (int off = 16; off; off >>= 1) vs += __shfl_xor_sync(0xffffffffu, vs, off);
    float rs = rsqrtf(vs / (float)DIM + 1e-5f);
    const float* p0r = ph + (size_t)(l / wgrid)*DIM;
    const float* p1r = pw + (size_t)(l % wgrid)*DIM;
    #pragma unroll
    for (int i = 0; i < 4; i++){
        int idx = i*128 + lane*4;
        float4 w4 = *(const float4*)(w + idx);
        float4 b4 = *(const float4*)(bb + idx);
        float4 p0 = *(const float4*)(p0r + idx);
        float4 p1 = *(const float4*)(p1r + idx);
        float4 o;
        o.x = (v[i].x - mu)*rs*w4.x + b4.x + p0.x + p1.x;
        o.y = (v[i].y - mu)*rs*w4.y + b4.y + p0.y + p1.y;
        o.z = (v[i].z - mu)*rs*w4.z + b4.z + p0.z + p1.z;
        o.w = (v[i].w - mu)*rs*w4.w + b4.w + p0.w + p1.w;
        *(float4*)(tr + idx) = o;
    }
}

// ---------------- per-head LayerNorm over 64 dims (pool path) ----------------
__global__ void head_ln_kernel(float* __restrict__ x, const float* __restrict__ w, int rows){
    int gw = (int)(((size_t)blockIdx.x*blockDim.x + threadIdx.x) >> 5);
    int lane = threadIdx.x & 31;
    if (gw >= rows) return;
    float* p = x + (size_t)gw*64;
    float a = p[lane], b = p[lane + 32];
    float s = a + b;
    #pragma unroll
    for (int off = 16; off; off >>= 1) s += __shfl_xor_sync(0xffffffffu, s, off);
    float mu = s * (1.f/64.f);
    float da = a - mu, db = b - mu;
    float vs = da*da + db*db;
    #pragma unroll
    for (int off = 16; off; off >>= 1) vs += __shfl_xor_sync(0xffffffffu, vs, off);
    float rs = rsqrtf(vs * (1.f/64.f) + 1e-5f);
    p[lane]      = da * rs * w[lane];
    p[lane + 32] = db * rs * w[lane + 32];
}

// ---------------- tiny GEMM NT: warp per output element (small M) ----------------
__global__ void tiny_nt_kernel(const float* __restrict__ A, int lda,
                               const float* __restrict__ W, int ldw,
                               const float* __restrict__ bias,
                               float* __restrict__ C, int ldc,
                               int M, int N, int K){
    int gw = (int)(((size_t)blockIdx.x*blockDim.x + threadIdx.x) >> 5);
    int lane = threadIdx.x & 31;
    if (gw >= M*N) return;
    int m = gw / N, n = gw % N;
    const float* a = A + (size_t)m*lda;
    const float* wv = W + (size_t)n*ldw;
    float s = 0.f;
    for (int k = lane*4; k < K; k += 128){
        float4 av = *(const float4*)(a + k);
        float4 bv = *(const float4*)(wv + k);
        s += av.x*bv.x + av.y*bv.y + av.z*bv.z + av.w*bv.w;
    }
    #pragma unroll
    for (int off = 16; off; off >>= 1) s += __shfl_xor_sync(0xffffffffu, s, off);
    if (lane == 0){
        if (bias) s += bias[n];
        C[(size_t)m*ldc + n] = s;
    }
}

// ---------------- pooling attention (Lq=1) ----------------
__global__ void pool_attn_kernel(const float* __restrict__ qhat, const float* __restrict__ K,
                                 const float* __restrict__ V, float* __restrict__ O){
    int h = blockIdx.x, b = blockIdx.y;
    __shared__ float sq[64];
    __shared__ float sa[1024];
    __shared__ float red[8], red2[8];
    __shared__ float racc[4][64];
    int tid = threadIdx.x, lane = tid & 31, wp = tid >> 5;
    if (tid < 64) sq[tid] = qhat[h*64 + tid];
    __syncthreads();
    int L = c_L[b];
    for (int kk = tid; kk < 1024; kk += 256){
        float dot = -1e9f;
        if (kk < L){
            const float* kr = K + ((size_t)(b*1024 + kk))*DIM + h*64;
            float ss = 0.f;
            #pragma unroll
            for (int d = 0; d < 64; d++) ss += sq[d]*kr[d];
            dot = ss*0.125f;
        }
        sa[kk] = dot;
    }
    __syncthreads();
    float m = -1e30f;
    for (int kk = tid; kk < 1024; kk += 256) m = fmaxf(m, sa[kk]);
    #pragma unroll
    for (int off = 16; off; off >>= 1) m = fmaxf(m, __shfl_xor_sync(0xffffffffu, m, off));
    if (lane == 0) red[wp] = m;
    __syncthreads();
    float bm = -1e30f;
    #pragma unroll
    for (int i = 0; i < 8; i++) bm = fmaxf(bm, red[i]);
    float sum = 0.f;
    for (int kk = tid; kk < 1024; kk += 256){
        float e = __expf(sa[kk] - bm);
        sa[kk] = e; sum += e;
    }
    #pragma unroll
    for (int off = 16; off; off >>= 1) sum += __shfl_xor_sync(0xffffffffu, sum, off);
    if (lane == 0) red2[wp] = sum;
    __syncthreads();
    float bs = 0.f;
    #pragma unroll
    for (int i = 0; i < 8; i++) bs += red2[i];
    float inv = 1.f / bs;
    int dd = tid & 63, part = tid >> 6;
    float acc = 0.f;
    for (int kk = part; kk < 1024; kk += 4)
        acc += sa[kk] * V[((size_t)(b*1024 + kk))*DIM + h*64 + dd];
    racc[part][dd] = acc;
    __syncthreads();
    if (part == 0)
        O[b*DIM + h*64 + dd] = (racc[0][dd] + racc[1][dd] + racc[2][dd] + racc[3][dd]) * inv;
}

// ---------------- host helpers ----------------
static void launch_bg(const __half* A, int lda,
                      const __half* W, int ldw, long wz,
                      const float* bias, const float* R, int ldr,
                      float* C, __half* Ch, int ldc, long cz,
                      int N, int K, int act, int nz, int tokrows){
    dim3 g(N/64, NTOK/64, nz);
    bgemm_nt<<<g, 128, B_SMEM>>>(A, lda, W, ldw, wz, bias, R, ldr,
                                 C, Ch, ldc, cz, K, act, tokrows);
}
static void launch_tiny(const float* A, int lda, const float* W, int ldw,
                        const float* bias, float* C, int ldc, int M, int N, int K){
    int warps = M*N;
    tiny_nt_kernel<<<(warps*32 + 255)/256, 256>>>(A, lda, W, ldw, bias, C, ldc, M, N, K);
}
static void launch_ln4(const float* x, const float* w, const float* bb,
                       float* y, __half* yh, int rows, int tokskip){
    lnw_kernel<4><<<(rows*32 + 255)/256, 256>>>(x, w, bb, y, yh, rows, tokskip);
}

extern "C" void kernel_launch(void* const* d_in, const int* in_sizes, int n_in,
                              void* d_out, int out_size){
    const float* images   = (const float*)d_in[0];
    const float* pe_ln1_w = (const float*)d_in[1];
    const float* pe_ln1_b = (const float*)d_in[2];
    const float* pe_w     = (const float*)d_in[3];
    const float* pe_b     = (const float*)d_in[4];
    const float* pe_ln2_w = (const float*)d_in[5];
    const float* pe_ln2_b = (const float*)d_in[6];
    const float* pos_h    = (const float*)d_in[7];
    const float* pos_w    = (const float*)d_in[8];
    const float* attn_ln  = (const float*)d_in[9];
    const float* wq       = (const float*)d_in[10];
    const float* wk       = (const float*)d_in[11];
    const float* wv       = (const float*)d_in[12];
    const float* qn       = (const float*)d_in[13];
    const float* kn       = (const float*)d_in[14];
    const float* wo       = (const float*)d_in[15];
    const float* ff_ln    = (const float*)d_in[16];
    const float* ff_w1    = (const float*)d_in[17];
    const float* ff_b1    = (const float*)d_in[18];
    const float* ff_w2    = (const float*)d_in[19];
    const float* ff_b2    = (const float*)d_in[20];
    const float* final_ln = (const float*)d_in[21];
    const float* pool_q   = (const float*)d_in[22];
    const float* pool_ln  = (const float*)d_in[23];
    const float* pool_wq  = (const float*)d_in[24];
    const float* pool_wk  = (const float*)d_in[25];
    const float* pool_wv  = (const float*)d_in[26];
    const float* pool_qn  = (const float*)d_in[27];
    const float* pool_kn  = (const float*)d_in[28];
    const float* pool_wo  = (const float*)d_in[29];
    const float* head_ln  = (const float*)d_in[30];
    const float* head_w   = (const float*)d_in[31];
    float* out = (float*)d_out;

    cudaFuncSetAttribute(bgemm_nt, cudaFuncAttributeMaxDynamicSharedMemorySize, B_SMEM);
    cudaFuncSetAttribute(flash_kernel, cudaFuncAttributeMaxDynamicSharedMemorySize, FSMEM);

    float *tok,*t,*qkv,*u,*qp,*po,*pooled,*hn;
    __half *wh,*lt,*xn,*mlp,*o,*qkv16,*qh,*kh;
    cudaGetSymbolAddress((void**)&tok, g_tok);
    cudaGetSymbolAddress((void**)&t,   g_t);
    cudaGetSymbolAddress((void**)&qkv, g_qkv);
    cudaGetSymbolAddress((void**)&u,   g_u);
    cudaGetSymbolAddress((void**)&qp,  g_qp);
    cudaGetSymbolAddress((void**)&po,  g_po);
    cudaGetSymbolAddress((void**)&pooled, g_pooled);
    cudaGetSymbolAddress((void**)&hn,  g_hn);
    cudaGetSymbolAddress((void**)&wh,  g_wh);
    cudaGetSymbolAddress((void**)&lt,  g_lt);
    cudaGetSymbolAddress((void**)&xn,  g_xn);
    cudaGetSymbolAddress((void**)&mlp, g_mlp);
    cudaGetSymbolAddress((void**)&o,   g_o);
    cudaGetSymbolAddress((void**)&qkv16, g_qkv16);
    cudaGetSymbolAddress((void**)&qh,  g_qh2);
    cudaGetSymbolAddress((void**)&kh,  g_kh2);
    __half* vh = qkv16 + (size_t)2*NTOK*DIM;   // V aliased: flash reads QKV GEMM output directly

    float* kf = qkv + (size_t)NTOK*DIM;
    float* vf = qkv + (size_t)2*NTOK*DIM;

    // ---- weight convert: single fused launch ----
    {
        WSrcs ws;
        ws.p[0] = wq;  ws.p[1] = wk;  ws.p[2] = wv;  ws.p[3] = wo;
        ws.p[4] = ff_w1; ws.p[5] = ff_w2; ws.p[6] = pe_w;
        ws.p[7] = pool_wk; ws.p[8] = pool_wv;
        int n4 = (int)(WTOT >> 2);
        wcvt_all_kernel<<<(n4 + 255)/256, 256>>>(ws, wh, n4);
    }

    // ---- patch embed ----
    pack_kernel<<<((size_t)NTOK*PDIM + 255)/256, 256>>>(images, tok);
    lnw_kernel<6><<<(NTOK*32 + 255)/256, 256>>>(tok, pe_ln1_w, pe_ln1_b, nullptr, lt, NTOK, 1);
    launch_bg(lt, PDIM, wh + OFF_PE, PDIM, 0, pe_b,
              nullptr, 0, t, nullptr, DIM, 0, DIM, PDIM, 0, 1, 1);
    ln_pos_kernel<<<(NTOK*32 + 255)/256, 256>>>(t, pe_ln2_w, pe_ln2_b, pos_h, pos_w);

    // ---- transformer layers ----
    for (int l = 0; l < NDEPTH; l++){
        launch_ln4(t, attn_ln + l*DIM, nullptr, nullptr, xn, NTOK, 1);
        launch_bg(xn, DIM, wh + OFF_QKV + (size_t)l*DIM*DIM, DIM, 1572864L,
                  nullptr, nullptr, 0,
                  nullptr, qkv16, DIM, (long)NTOK*DIM, DIM, DIM, 0, 3, 1);
        kvprep_kernel<<<NTOK*HEADS*8/256, 256>>>(qkv16, qn + l*DH, kn + l*DH, qh, kh);
        flash_kernel<<<dim3(8, BB*HEADS), 256, FSMEM>>>(qh, kh, vh, o);
        launch_bg(o, DIM, wh + OFF_WO + (size_t)l*DIM*DIM, DIM, 0,
                  nullptr, t, DIM, t, nullptr, DIM, 0, DIM, DIM, 0, 1, 1);
        launch_ln4(t, ff_ln + l*DIM, nullptr, nullptr, xn, NTOK, 1);
        launch_bg(xn, DIM, wh + OFF_FF1 + (size_t)l*MLPD*DIM, DIM, 0,
                  ff_b1 + l*MLPD, nullptr, 0,
                  nullptr, mlp, MLPD, 0, MLPD, DIM, 1, 1, 1);
        launch_bg(mlp, MLPD, wh + OFF_FF2 + (size_t)l*DIM*MLPD, MLPD, 0,
                  ff_b2 + l*DIM, t, DIM, t, nullptr, DIM, 0, DIM, MLPD, 0, 1, 1);
    }

    // ---- final LN + pooling ----
    launch_ln4(t, final_ln, nullptr, nullptr, xn, NTOK, 1);
    launch_ln4(pool_q, pool_ln, nullptr, u, nullptr, 1, 0);
    launch_tiny(u, DIM, pool_wq, DIM, nullptr, qp, DIM, 1, DIM, DIM);
    head_ln_kernel<<<1, 256>>>(qp, pool_qn, HEADS);
    // pool K and V in one batched GEMM (weights adjacent: OFF_PK then OFF_PV)
    launch_bg(xn, DIM, wh + OFF_PK, DIM, (long)(OFF_PV - OFF_PK), nullptr, nullptr, 0,
              kf, nullptr, DIM, (long)NTOK*DIM, DIM, DIM, 0, 2, 1);
    head_ln_kernel<<<(NTOK*HEADS*32 + 255)/256, 256>>>(kf, pool_kn, NTOK*HEADS);
    pool_attn_kernel<<<dim3(HEADS, BB), 256>>>(qp, kf, vf, po);
    launch_tiny(po, DIM, pool_wo, DIM, nullptr, pooled, DIM, BB, DIM, DIM);
    launch_ln4(pooled, head_ln, nullptr, hn, nullptr, BB, 0);
    launch_tiny(hn, DIM, head_w, DIM, nullptr, out, NC, BB, NC, DIM);
}